// round 1
// baseline (speedup 1.0000x reference)
#include <cuda_runtime.h>
#include <cuda_bf16.h>
#include <math.h>

// ---------------- static scratch (no allocation allowed) ----------------
#define NTOK 4096              // B*S
#define DM   1024
#define DFF  2048
#define NH   16
#define DK   64
#define NB   4
#define SEQ  1024
#define NE   8
#define PAIR_CAP 9216          // 8192 pairs + 8*128 alignment pad
#define NTILE72  72            // PAIR_CAP/128

__device__ float g_xn1[NTOK*DM];
__device__ float g_q  [NTOK*DM];
__device__ float g_k  [NTOK*DM];
__device__ float g_v  [NTOK*DM];
__device__ float g_qd [NTOK*DM];
__device__ float g_kd [NTOK*DM];
__device__ float g_vd [NTOK*DM];
__device__ float g_scores[(long long)NB*NH*SEQ*SEQ];   // 256MB
__device__ float g_attnctx[NTOK*DM];
__device__ float g_delta  [NTOK*DM];
__device__ float g_dense_o[NTOK*DM];
__device__ float g_delta_o[NTOK*DM];
__device__ float g_gate[NTOK*2];
__device__ float g_x1 [NTOK*DM];
__device__ float g_xn2[NTOK*DM];
__device__ float g_ctx [NB*NH*DK*DK];
__device__ float g_ksum[NB*NH*DK];
__device__ int   g_topk_idx[NTOK*2];
__device__ float g_topk_w [NTOK*2];
__device__ int   g_counts[NE];
__device__ int   g_cursor[NE];
__device__ int   g_off[NE+1];
__device__ int   g_tile_e[NTILE72];
__device__ int   g_tok[PAIR_CAP];
__device__ int   g_pair_pos[NTOK*2];
__device__ float g_h1[(long long)PAIR_CAP*DFF];        // 75.5MB
__device__ float g_y2[(long long)PAIR_CAP*DM];

// ---------------- reductions ----------------
__device__ __forceinline__ float warpSum(float v){
    #pragma unroll
    for (int o=16;o;o>>=1) v += __shfl_xor_sync(0xffffffffu, v, o);
    return v;
}
__device__ __forceinline__ float warpMax(float v){
    #pragma unroll
    for (int o=16;o;o>>=1) v = fmaxf(v, __shfl_xor_sync(0xffffffffu, v, o));
    return v;
}
// 256-thread block reductions
__device__ __forceinline__ float blockSum(float v, float* red){
    v = warpSum(v);
    if ((threadIdx.x & 31) == 0) red[threadIdx.x>>5] = v;
    __syncthreads();
    if (threadIdx.x < 32) {
        float t = (threadIdx.x < 8) ? red[threadIdx.x] : 0.f;
        t = warpSum(t);
        if (threadIdx.x == 0) red[0] = t;
    }
    __syncthreads();
    float r = red[0];
    __syncthreads();
    return r;
}
__device__ __forceinline__ float blockMax(float v, float* red){
    v = warpMax(v);
    if ((threadIdx.x & 31) == 0) red[threadIdx.x>>5] = v;
    __syncthreads();
    if (threadIdx.x < 32) {
        float t = (threadIdx.x < 8) ? red[threadIdx.x] : -3.0e38f;
        t = warpMax(t);
        if (threadIdx.x == 0) red[0] = t;
    }
    __syncthreads();
    float r = red[0];
    __syncthreads();
    return r;
}

// ---------------- layernorm ----------------
__global__ __launch_bounds__(256) void ln_kernel(const float* __restrict__ x,
                                                 const float* __restrict__ g,
                                                 const float* __restrict__ b,
                                                 float* __restrict__ y){
    __shared__ float row[DM];
    __shared__ float red[8];
    long long base = (long long)blockIdx.x * DM;
    float s = 0.f;
    for (int i = threadIdx.x; i < DM; i += 256) { float v = x[base+i]; row[i] = v; s += v; }
    s = blockSum(s, red);
    float mu = s * (1.f/DM);
    float vs = 0.f;
    for (int i = threadIdx.x; i < DM; i += 256) { float d = row[i]-mu; vs += d*d; }
    vs = blockSum(vs, red);
    float rstd = rsqrtf(vs * (1.f/DM) + 1e-5f);
    for (int i = threadIdx.x; i < DM; i += 256)
        y[base+i] = (row[i]-mu)*rstd*g[i] + b[i];
}

// ---------------- generic SGEMM 128x128x8, 8x8/thread ----------------
__global__ __launch_bounds__(256) void sgemm_kernel(
    const float* __restrict__ A, const float* __restrict__ B, float* __restrict__ C,
    int M, int N, int K, int lda, int ldb, int ldc,
    int innerN,
    long long sAo, long long sAi, long long sBo, long long sBi,
    long long sCo, long long sCi,
    const int* __restrict__ rowIdx, const int* __restrict__ tileExpert,
    long long expStrideB, float alpha, int actMode, int transB)
{
    int z  = blockIdx.z;
    int zo = z / innerN, zi = z - zo*innerN;
    A += zo*sAo + zi*sAi;
    B += zo*sBo + zi*sBi;
    C += zo*sCo + zi*sCi;
    if (tileExpert) B += (long long)tileExpert[blockIdx.y] * expStrideB;

    const int tm0 = blockIdx.y * 128;
    const int tn0 = blockIdx.x * 128;
    int tid = threadIdx.x;

    __shared__ float As[8][128];
    __shared__ float Bs[8][128];

    // A loading: row = tid/2 (0..127), col4 = (tid&1)*4
    int arow = tid >> 1;
    int acol = (tid & 1) << 2;
    int grow = tm0 + arow;
    bool aval = grow < M;
    int srcRow = aval ? (rowIdx ? rowIdx[grow] : grow) : 0;
    const float* Aptr = A + (long long)srcRow * lda + acol;

    float acc[8][8];
    #pragma unroll
    for (int i=0;i<8;i++)
        #pragma unroll
        for (int j=0;j<8;j++) acc[i][j]=0.f;

    int tr = (tid >> 4) << 3;
    int tc = (tid & 15) << 3;

    for (int k0 = 0; k0 < K; k0 += 8) {
        float4 av = make_float4(0.f,0.f,0.f,0.f);
        if (aval) av = *(const float4*)(Aptr + k0);
        As[acol+0][arow]=av.x; As[acol+1][arow]=av.y;
        As[acol+2][arow]=av.z; As[acol+3][arow]=av.w;

        if (!transB) {
            int bk = tid >> 5, bn = (tid & 31) << 2;
            float4 bv = make_float4(0.f,0.f,0.f,0.f);
            if (tn0 + bn < N) bv = *(const float4*)(B + (long long)(k0+bk)*ldb + tn0 + bn);
            *(float4*)&Bs[bk][bn] = bv;
        } else {
            int bn = tid >> 1, bk = (tid & 1) << 2;
            float4 bv = make_float4(0.f,0.f,0.f,0.f);
            if (tn0 + bn < N) bv = *(const float4*)(B + (long long)(tn0+bn)*ldb + k0 + bk);
            Bs[bk+0][bn]=bv.x; Bs[bk+1][bn]=bv.y;
            Bs[bk+2][bn]=bv.z; Bs[bk+3][bn]=bv.w;
        }
        __syncthreads();
        #pragma unroll
        for (int kk=0;kk<8;kk++){
            float ar[8], br[8];
            #pragma unroll
            for (int i=0;i<8;i++) ar[i] = As[kk][tr+i];
            #pragma unroll
            for (int j=0;j<8;j++) br[j] = Bs[kk][tc+j];
            #pragma unroll
            for (int i=0;i<8;i++)
                #pragma unroll
                for (int j=0;j<8;j++) acc[i][j] += ar[i]*br[j];
        }
        __syncthreads();
    }

    #pragma unroll
    for (int i=0;i<8;i++){
        int row = tm0 + tr + i;
        if (row >= M) continue;
        #pragma unroll
        for (int j=0;j<8;j++){
            int col = tn0 + tc + j;
            if (col >= N) continue;
            float v = acc[i][j] * alpha;
            if (actMode == 1)
                v = 0.5f * v * (1.f + erff(v * 0.70710678118654752f));
            C[(long long)row * ldc + col] = v;
        }
    }
}

// ---------------- masked row softmax ----------------
__global__ __launch_bounds__(256) void softmax_kernel(float* __restrict__ s,
                                                      const int* __restrict__ mask){
    long long r = blockIdx.x;           // 0..65535 : (z,q)
    int z = (int)(r >> 10);
    int q = (int)(r & 1023);
    int b = z >> 4;
    float* sr = s + (r << 10);
    const int* mr = mask + ((long long)b << 20) + ((long long)q << 10);
    __shared__ float buf[SEQ];
    __shared__ float red[8];
    float mx = -3.0e38f;
    for (int i = threadIdx.x; i < SEQ; i += 256){
        float v = sr[i];
        if (mr[i] == 0) v = -1e9f;
        buf[i] = v;
        mx = fmaxf(mx, v);
    }
    mx = blockMax(mx, red);
    float sum = 0.f;
    for (int i = threadIdx.x; i < SEQ; i += 256){
        float e = expf(buf[i]-mx);
        buf[i] = e; sum += e;
    }
    sum = blockSum(sum, red);
    float inv = 1.f / sum;
    for (int i = threadIdx.x; i < SEQ; i += 256)
        sr[i] = buf[i] * inv;
}

// ---------------- delta branch: context = kd^T @ vd per (b,h) ----------------
__global__ __launch_bounds__(256) void ctx_kernel(const float* __restrict__ kd,
                                                  const float* __restrict__ vd,
                                                  float* __restrict__ ctx){
    int z = blockIdx.x; int b = z >> 4, h = z & 15;
    const float* kbase = kd + ((long long)b*SEQ)*DM + h*DK;
    const float* vbase = vd + ((long long)b*SEQ)*DM + h*DK;
    __shared__ float ks[64][65];
    __shared__ float vs[64][65];
    int tid = threadIdx.x;
    int d0 = (tid >> 4) << 2;   // 0..60
    int e0 = (tid & 15) << 2;   // 0..60
    float acc[4][4];
    #pragma unroll
    for (int i=0;i<4;i++)
        #pragma unroll
        for (int j=0;j<4;j++) acc[i][j]=0.f;

    for (int s0 = 0; s0 < SEQ; s0 += 64) {
        for (int t = tid; t < 64*16; t += 256) {
            int rr = t >> 4; int cc = (t & 15) << 2;
            float4 kv = *(const float4*)(kbase + (long long)(s0+rr)*DM + cc);
            float4 vv = *(const float4*)(vbase + (long long)(s0+rr)*DM + cc);
            ks[rr][cc+0]=kv.x; ks[rr][cc+1]=kv.y; ks[rr][cc+2]=kv.z; ks[rr][cc+3]=kv.w;
            vs[rr][cc+0]=vv.x; vs[rr][cc+1]=vv.y; vs[rr][cc+2]=vv.z; vs[rr][cc+3]=vv.w;
        }
        __syncthreads();
        #pragma unroll 4
        for (int ss=0; ss<64; ss++){
            float kr[4], vr[4];
            #pragma unroll
            for (int i=0;i<4;i++) kr[i]=ks[ss][d0+i];
            #pragma unroll
            for (int j=0;j<4;j++) vr[j]=vs[ss][e0+j];
            #pragma unroll
            for (int i=0;i<4;i++)
                #pragma unroll
                for (int j=0;j<4;j++) acc[i][j] += kr[i]*vr[j];
        }
        __syncthreads();
    }
    float* cbase = ctx + (long long)z*DK*DK;
    #pragma unroll
    for (int i=0;i<4;i++)
        #pragma unroll
        for (int j=0;j<4;j++)
            cbase[(d0+i)*DK + e0+j] = acc[i][j];
}

// ---------------- ksum = sum_s relu(kd) per (b,h,d) ----------------
__global__ void ksum_kernel(const float* __restrict__ kd, float* __restrict__ ksum){
    int z = blockIdx.x; int b = z >> 4, h = z & 15;
    int d = threadIdx.x;  // 64 threads
    const float* base = kd + ((long long)b*SEQ)*DM + h*DK + d;
    float s = 0.f;
    #pragma unroll 4
    for (int ss=0; ss<SEQ; ss++) s += fmaxf(base[(long long)ss*DM], 0.f);
    ksum[z*DK + d] = s;
}

// ---------------- delta output: (relu(qd)@ctx)/z ----------------
__global__ __launch_bounds__(256) void delta_kernel(const float* __restrict__ qd,
                                                    const float* __restrict__ ctx,
                                                    const float* __restrict__ ksum,
                                                    float* __restrict__ delta){
    int z = blockIdx.x >> 2;
    int sc = blockIdx.x & 3;
    int b = z >> 4, h = z & 15;
    __shared__ float cs[DK*DK];
    __shared__ float kss[DK];
    for (int i = threadIdx.x; i < DK*DK; i += 256) cs[i] = ctx[(long long)z*DK*DK + i];
    if (threadIdx.x < DK) kss[threadIdx.x] = ksum[z*DK + threadIdx.x];
    __syncthreads();
    int s = sc*256 + threadIdx.x;
    const float* qrow = qd + ((long long)(b*SEQ + s))*DM + h*DK;
    float q[DK];
    #pragma unroll
    for (int d=0; d<DK; d+=4){
        float4 v = *(const float4*)(qrow + d);
        q[d+0]=fmaxf(v.x,0.f); q[d+1]=fmaxf(v.y,0.f);
        q[d+2]=fmaxf(v.z,0.f); q[d+3]=fmaxf(v.w,0.f);
    }
    float zv = 1e-6f;
    #pragma unroll
    for (int d=0; d<DK; d++) zv += q[d]*kss[d];
    float invz = 1.f / zv;
    float* orow = delta + ((long long)(b*SEQ + s))*DM + h*DK;
    for (int e=0; e<DK; e++){
        float a = 0.f;
        #pragma unroll
        for (int d=0; d<DK; d++) a += q[d]*cs[d*DK + e];
        orow[e] = a * invz;
    }
}

// ---------------- gate = softmax(xn1 @ w_gate) ----------------
__global__ __launch_bounds__(256) void gate_kernel(const float* __restrict__ xn,
                                                   const float* __restrict__ wg,
                                                   float* __restrict__ gate){
    int t = blockIdx.x;
    float p0=0.f, p1=0.f;
    for (int k = threadIdx.x; k < DM; k += 256){
        float xv = xn[(long long)t*DM + k];
        p0 += xv*wg[k*2+0];
        p1 += xv*wg[k*2+1];
    }
    __shared__ float red[8];
    p0 = blockSum(p0, red);
    p1 = blockSum(p1, red);
    if (threadIdx.x == 0){
        float m = fmaxf(p0,p1);
        float e0 = expf(p0-m), e1 = expf(p1-m);
        float inv = 1.f/(e0+e1);
        gate[t*2+0] = e0*inv;
        gate[t*2+1] = e1*inv;
    }
}

// ---------------- x1 = x + g0*dense + g1*delta ----------------
__global__ void combine1_kernel(const float* __restrict__ x,
                                const float* __restrict__ dense,
                                const float* __restrict__ delta,
                                const float* __restrict__ gate,
                                float* __restrict__ x1){
    long long i = (long long)blockIdx.x*256 + threadIdx.x;
    int t = (int)(i >> 10);
    x1[i] = x[i] + gate[t*2]*dense[i] + gate[t*2+1]*delta[i];
}

// ---------------- router: logits, top-2, softmax weights, counts ----------------
__global__ __launch_bounds__(256) void router_kernel(const float* __restrict__ xn2,
                                                     const float* __restrict__ wr,
                                                     int* __restrict__ topk_idx,
                                                     float* __restrict__ topk_w,
                                                     int* __restrict__ counts){
    int t = blockIdx.x;
    float p[NE];
    #pragma unroll
    for (int e=0;e<NE;e++) p[e]=0.f;
    for (int k = threadIdx.x; k < DM; k += 256){
        float xv = xn2[(long long)t*DM + k];
        #pragma unroll
        for (int e=0;e<NE;e++) p[e] += xv*wr[k*NE + e];
    }
    __shared__ float part[NE][8];
    int w = threadIdx.x >> 5;
    #pragma unroll
    for (int e=0;e<NE;e++){
        float v = warpSum(p[e]);
        if ((threadIdx.x & 31)==0) part[e][w] = v;
    }
    __syncthreads();
    if (threadIdx.x == 0){
        float lg[NE];
        for (int e=0;e<NE;e++){
            float s=0.f;
            for (int ww=0; ww<8; ww++) s += part[e][ww];  // fixed order: deterministic
            lg[e]=s;
        }
        int i0=0; float v0=lg[0];
        for (int e=1;e<NE;e++) if (lg[e]>v0){v0=lg[e];i0=e;}
        int i1=-1; float v1=-3.0e38f;
        for (int e=0;e<NE;e++) if (e!=i0 && lg[e]>v1){v1=lg[e];i1=e;}
        float e1 = expf(v1-v0);
        float inv = 1.f/(1.f+e1);
        topk_idx[t*2+0]=i0; topk_idx[t*2+1]=i1;
        topk_w[t*2+0]=inv;  topk_w[t*2+1]=e1*inv;
        atomicAdd(&counts[i0],1); atomicAdd(&counts[i1],1);
    }
}

__global__ void prep_kernel(int* counts, int* cursor, int* tok){
    int i = blockIdx.x*256 + threadIdx.x;
    if (i < NE){ counts[i]=0; cursor[i]=0; }
    if (i < PAIR_CAP) tok[i]=0;
}

__global__ void scan_kernel(const int* counts, int* off, int* tile_e){
    if (threadIdx.x==0 && blockIdx.x==0){
        int o = 0;
        off[0]=0;
        for (int e=0;e<NE;e++){ o += (counts[e]+127)&~127; off[e+1]=o; }
        for (int t=0;t<NTILE72;t++){
            int row = t*128;
            int ee = NE-1;
            for (int i=0;i<NE;i++){ if (row < off[i+1]) { ee=i; break; } }
            tile_e[t]=ee;
        }
    }
}

__global__ void place_kernel(const int* __restrict__ topk_idx,
                             const int* __restrict__ off,
                             int* cursor, int* tok, int* pair_pos){
    int t = blockIdx.x*256 + threadIdx.x;
    if (t >= NTOK) return;
    for (int k=0;k<2;k++){
        int e = topk_idx[t*2+k];
        int pos = atomicAdd(&cursor[e],1);
        int r = off[e] + pos;
        tok[r] = t;
        pair_pos[t*2+k] = r;
    }
}

// ---------------- out = x1 + w0*y2[p0] + w1*y2[p1] ----------------
__global__ void final_kernel(const float* __restrict__ x1,
                             const float* __restrict__ y2,
                             const float* __restrict__ topk_w,
                             const int* __restrict__ pair_pos,
                             float* __restrict__ out){
    long long i = (long long)blockIdx.x*256 + threadIdx.x;
    int t = (int)(i >> 10);
    int c = (int)(i & 1023);
    int p0 = pair_pos[t*2+0], p1 = pair_pos[t*2+1];
    out[i] = x1[i] + topk_w[t*2+0]*y2[(long long)p0*DM + c]
                   + topk_w[t*2+1]*y2[(long long)p1*DM + c];
}

// ---------------- host side ----------------
static void gemm(const float* A, const float* B, float* C,
                 int M, int N, int K, int lda, int ldb, int ldc,
                 int batch, int innerN,
                 long long sAo, long long sAi, long long sBo, long long sBi,
                 long long sCo, long long sCi,
                 const int* rowIdx, const int* tileE, long long expSB,
                 float alpha, int act, int tb){
    dim3 grid((N+127)/128, (M+127)/128, batch);
    sgemm_kernel<<<grid, 256>>>(A,B,C,M,N,K,lda,ldb,ldc,innerN,
                                sAo,sAi,sBo,sBi,sCo,sCi,
                                rowIdx,tileE,expSB,alpha,act,tb);
}

extern "C" void kernel_launch(void* const* d_in, const int* in_sizes, int n_in,
                              void* d_out, int out_size){
    const float* x        = (const float*)d_in[0];
    const int*   mask     = (const int*)  d_in[1];
    const float* ln1_g    = (const float*)d_in[2];
    const float* ln1_b    = (const float*)d_in[3];
    const float* wq       = (const float*)d_in[4];
    const float* wk       = (const float*)d_in[5];
    const float* wv       = (const float*)d_in[6];
    const float* wo       = (const float*)d_in[7];
    const float* wqd      = (const float*)d_in[8];
    const float* wkd      = (const float*)d_in[9];
    const float* wvd      = (const float*)d_in[10];
    const float* wod      = (const float*)d_in[11];
    const float* w_gate   = (const float*)d_in[12];
    const float* ln2_g    = (const float*)d_in[13];
    const float* ln2_b    = (const float*)d_in[14];
    const float* w_router = (const float*)d_in[15];
    const float* e_w1     = (const float*)d_in[16];
    const float* e_w2     = (const float*)d_in[17];
    float* out = (float*)d_out;

    float *xn1,*q,*k,*v,*qd,*kd,*vd,*scores,*attnctx,*delta,*dense_o,*delta_o;
    float *gate,*x1,*xn2,*ctx,*ksum,*h1,*y2,*topk_w;
    int *topk_idx,*counts,*cursor,*off,*tile_e,*tok,*pair_pos;

    cudaGetSymbolAddress((void**)&xn1,     g_xn1);
    cudaGetSymbolAddress((void**)&q,       g_q);
    cudaGetSymbolAddress((void**)&k,       g_k);
    cudaGetSymbolAddress((void**)&v,       g_v);
    cudaGetSymbolAddress((void**)&qd,      g_qd);
    cudaGetSymbolAddress((void**)&kd,      g_kd);
    cudaGetSymbolAddress((void**)&vd,      g_vd);
    cudaGetSymbolAddress((void**)&scores,  g_scores);
    cudaGetSymbolAddress((void**)&attnctx, g_attnctx);
    cudaGetSymbolAddress((void**)&delta,   g_delta);
    cudaGetSymbolAddress((void**)&dense_o, g_dense_o);
    cudaGetSymbolAddress((void**)&delta_o, g_delta_o);
    cudaGetSymbolAddress((void**)&gate,    g_gate);
    cudaGetSymbolAddress((void**)&x1,      g_x1);
    cudaGetSymbolAddress((void**)&xn2,     g_xn2);
    cudaGetSymbolAddress((void**)&ctx,     g_ctx);
    cudaGetSymbolAddress((void**)&ksum,    g_ksum);
    cudaGetSymbolAddress((void**)&h1,      g_h1);
    cudaGetSymbolAddress((void**)&y2,      g_y2);
    cudaGetSymbolAddress((void**)&topk_w,  g_topk_w);
    cudaGetSymbolAddress((void**)&topk_idx,g_topk_idx);
    cudaGetSymbolAddress((void**)&counts,  g_counts);
    cudaGetSymbolAddress((void**)&cursor,  g_cursor);
    cudaGetSymbolAddress((void**)&off,     g_off);
    cudaGetSymbolAddress((void**)&tile_e,  g_tile_e);
    cudaGetSymbolAddress((void**)&tok,     g_tok);
    cudaGetSymbolAddress((void**)&pair_pos,g_pair_pos);

    const long long TOKD = (long long)SEQ*DM;     // 1048576

    // 1. LN1
    ln_kernel<<<NTOK,256>>>(x, ln1_g, ln1_b, xn1);

    // 2-7. projections
    gemm(xn1, wq,  q,  NTOK,DM,DM, DM,DM,DM, 1,1, 0,0,0,0,0,0, 0,0,0, 1.f,0,0);
    gemm(xn1, wk,  k,  NTOK,DM,DM, DM,DM,DM, 1,1, 0,0,0,0,0,0, 0,0,0, 1.f,0,0);
    gemm(xn1, wv,  v,  NTOK,DM,DM, DM,DM,DM, 1,1, 0,0,0,0,0,0, 0,0,0, 1.f,0,0);
    gemm(xn1, wqd, qd, NTOK,DM,DM, DM,DM,DM, 1,1, 0,0,0,0,0,0, 0,0,0, 1.f,0,0);
    gemm(xn1, wkd, kd, NTOK,DM,DM, DM,DM,DM, 1,1, 0,0,0,0,0,0, 0,0,0, 1.f,0,0);
    gemm(xn1, wvd, vd, NTOK,DM,DM, DM,DM,DM, 1,1, 0,0,0,0,0,0, 0,0,0, 1.f,0,0);

    // 8. scores = Q @ K^T / 8  (batched over b,h)
    gemm(q, k, scores, SEQ, SEQ, DK, DM, DM, SEQ,
         NB*NH, NH,
         TOKD, DK,  TOKD, DK,  (long long)NH*SEQ*SEQ, (long long)SEQ*SEQ,
         0, 0, 0, 0.125f, 0, 1);

    // 9. masked softmax
    softmax_kernel<<<NB*NH*SEQ, 256>>>(scores, mask);

    // 10. attnctx = P @ V (batched)
    gemm(scores, v, attnctx, SEQ, DK, SEQ, SEQ, DM, DM,
         NB*NH, NH,
         (long long)NH*SEQ*SEQ, (long long)SEQ*SEQ,  TOKD, DK,  TOKD, DK,
         0, 0, 0, 1.f, 0, 0);

    // 11-13. delta branch
    ctx_kernel<<<NB*NH, 256>>>(kd, vd, ctx);
    ksum_kernel<<<NB*NH, 64>>>(kd, ksum);
    delta_kernel<<<NB*NH*4, 256>>>(qd, ctx, ksum, delta);

    // 14-15. output projections
    gemm(attnctx, wo,  dense_o, NTOK,DM,DM, DM,DM,DM, 1,1, 0,0,0,0,0,0, 0,0,0, 1.f,0,0);
    gemm(delta,   wod, delta_o, NTOK,DM,DM, DM,DM,DM, 1,1, 0,0,0,0,0,0, 0,0,0, 1.f,0,0);

    // 16-17. gate + residual combine
    gate_kernel<<<NTOK,256>>>(xn1, w_gate, gate);
    combine1_kernel<<<NTOK*DM/256, 256>>>(x, dense_o, delta_o, gate, x1);

    // 18. LN2
    ln_kernel<<<NTOK,256>>>(x1, ln2_g, ln2_b, xn2);

    // 19-22. routing
    prep_kernel<<<(PAIR_CAP+255)/256, 256>>>(counts, cursor, tok);
    router_kernel<<<NTOK, 256>>>(xn2, w_router, topk_idx, topk_w, counts);
    scan_kernel<<<1,32>>>(counts, off, tile_e);
    place_kernel<<<(NTOK+255)/256, 256>>>(topk_idx, off, cursor, tok, pair_pos);

    // 23. expert GEMM1 (gathered, gelu)
    gemm(xn2, e_w1, h1, PAIR_CAP, DFF, DM, DM, DFF, DFF,
         1,1, 0,0,0,0,0,0,
         tok, tile_e, (long long)DM*DFF, 1.f, 1, 0);

    // 24. expert GEMM2
    gemm(h1, e_w2, y2, PAIR_CAP, DM, DFF, DFF, DM, DM,
         1,1, 0,0,0,0,0,0,
         0, tile_e, (long long)DFF*DM, 1.f, 0, 0);

    // 25. final combine -> d_out
    final_kernel<<<NTOK*DM/256, 256>>>(x1, y2, topk_w, pair_pos, out);
}

// round 4
// speedup vs baseline: 1.6811x; 1.6811x over previous
#include <cuda_runtime.h>
#include <cuda_fp16.h>
#include <math.h>

// ---------------- problem constants ----------------
#define NTOK 4096              // B*S
#define DM   1024
#define DFF  2048
#define NH   16
#define DK   64
#define NB   4
#define SEQ  1024
#define NE   8
#define PAIR_CAP 9216
#define NTILE72  72
#define WSZ  (1024*1024)

// ---------------- static scratch ----------------
__device__ float g_xn1[NTOK*DM];
__device__ float g_q  [NTOK*DM];
__device__ float g_k  [NTOK*DM];
__device__ float g_vT [DM*NTOK];
__device__ float g_qd [NTOK*DM];
__device__ float g_kd [NTOK*DM];
__device__ float g_vd [NTOK*DM];
__device__ float g_scores[(long long)NB*NH*SEQ*SEQ];
__device__ float g_attnctx[NTOK*DM];
__device__ float g_delta  [NTOK*DM];
__device__ float g_dense_o[NTOK*DM];
__device__ float g_delta_o[NTOK*DM];
__device__ float g_gate[NTOK*2];
__device__ float g_x1 [NTOK*DM];
__device__ float g_xn2[NTOK*DM];
__device__ float g_ctx [NB*NH*DK*DK];
__device__ float g_ksum[NB*NH*DK];
__device__ int   g_topk_idx[NTOK*2];
__device__ float g_topk_w [NTOK*2];
__device__ int   g_counts[NE];
__device__ int   g_cursor[NE];
__device__ int   g_off[NE+1];
__device__ int   g_tile_e[NTILE72];
__device__ int   g_tok[PAIR_CAP];
__device__ int   g_pair_pos[NTOK*2];
__device__ float g_h1[(long long)PAIR_CAP*DFF];
__device__ float g_y2[(long long)PAIR_CAP*DM];

__device__ __half g_wT_hi[8LL*WSZ];
__device__ __half g_wT_lo[8LL*WSZ];
__device__ __half g_e1T_hi[8LL*DM*DFF];
__device__ __half g_e1T_lo[8LL*DM*DFF];
__device__ __half g_e2T_hi[8LL*DFF*DM];
__device__ __half g_e2T_lo[8LL*DFF*DM];

// ---------------- helpers ----------------
__device__ __forceinline__ void mma_f16(float* d,
        unsigned a0, unsigned a1, unsigned a2, unsigned a3,
        unsigned b0, unsigned b1){
    asm volatile("mma.sync.aligned.m16n8k16.row.col.f32.f16.f16.f32 "
        "{%0,%1,%2,%3}, {%4,%5,%6,%7}, {%8,%9}, {%0,%1,%2,%3};"
        : "+f"(d[0]),"+f"(d[1]),"+f"(d[2]),"+f"(d[3])
        : "r"(a0),"r"(a1),"r"(a2),"r"(a3),"r"(b0),"r"(b1));
}
__device__ __forceinline__ unsigned packh(__half x, __half y){
    return (unsigned)__half_as_ushort(x) | ((unsigned)__half_as_ushort(y) << 16);
}
__device__ __forceinline__ void split2(float x, float y, unsigned& hi, unsigned& lo){
    __half hx = __float2half_rn(x), hy = __float2half_rn(y);
    __half lx = __float2half_rn(x - __half2float(hx));
    __half ly = __float2half_rn(y - __half2float(hy));
    hi = packh(hx, hy);
    lo = packh(lx, ly);
}

__device__ __forceinline__ float warpSum(float v){
    #pragma unroll
    for (int o=16;o;o>>=1) v += __shfl_xor_sync(0xffffffffu, v, o);
    return v;
}
__device__ __forceinline__ float warpMax(float v){
    #pragma unroll
    for (int o=16;o;o>>=1) v = fmaxf(v, __shfl_xor_sync(0xffffffffu, v, o));
    return v;
}
__device__ __forceinline__ float blockSum(float v, float* red){
    v = warpSum(v);
    if ((threadIdx.x & 31) == 0) red[threadIdx.x>>5] = v;
    __syncthreads();
    if (threadIdx.x < 32) {
        float t = (threadIdx.x < 8) ? red[threadIdx.x] : 0.f;
        t = warpSum(t);
        if (threadIdx.x == 0) red[0] = t;
    }
    __syncthreads();
    float r = red[0];
    __syncthreads();
    return r;
}
__device__ __forceinline__ float blockMax(float v, float* red){
    v = warpMax(v);
    if ((threadIdx.x & 31) == 0) red[threadIdx.x>>5] = v;
    __syncthreads();
    if (threadIdx.x < 32) {
        float t = (threadIdx.x < 8) ? red[threadIdx.x] : -3.0e38f;
        t = warpMax(t);
        if (threadIdx.x == 0) red[0] = t;
    }
    __syncthreads();
    float r = red[0];
    __syncthreads();
    return r;
}

// ---------------- weight transpose + hi/lo split: W[K][N] -> out[N][K] ----------------
__global__ void wsplit_kernel(const float* __restrict__ W,
                              __half* __restrict__ hi, __half* __restrict__ lo,
                              int K, int N){
    __shared__ float ts[32][33];
    long long zoff = (long long)blockIdx.z * K * N;
    W  += zoff; hi += zoff; lo += zoff;
    int k0 = blockIdx.y*32, n0 = blockIdx.x*32;
    int tx = threadIdx.x, ty = threadIdx.y;   // 32 x 8
    #pragma unroll
    for (int i=0;i<4;i++)
        ts[ty+8*i][tx] = W[(long long)(k0+ty+8*i)*N + n0 + tx];
    __syncthreads();
    #pragma unroll
    for (int i=0;i<4;i++){
        int n = n0 + ty + 8*i, k = k0 + tx;
        float v = ts[tx][ty+8*i];
        __half h = __float2half_rn(v);
        hi[(long long)n*K + k] = h;
        lo[(long long)n*K + k] = __float2half_rn(v - __half2float(h));
    }
}

// ---------------- layernorm ----------------
__global__ __launch_bounds__(256) void ln_kernel(const float* __restrict__ x,
                                                 const float* __restrict__ g,
                                                 const float* __restrict__ b,
                                                 float* __restrict__ y){
    __shared__ float row[DM];
    __shared__ float red[8];
    long long base = (long long)blockIdx.x * DM;
    float s = 0.f;
    for (int i = threadIdx.x; i < DM; i += 256) { float v = x[base+i]; row[i] = v; s += v; }
    s = blockSum(s, red);
    float mu = s * (1.f/DM);
    float vs = 0.f;
    for (int i = threadIdx.x; i < DM; i += 256) { float d = row[i]-mu; vs += d*d; }
    vs = blockSum(vs, red);
    float rstd = rsqrtf(vs * (1.f/DM) + 1e-5f);
    for (int i = threadIdx.x; i < DM; i += 256)
        y[base+i] = (row[i]-mu)*rstd*g[i] + b[i];
}

// ---------------- fp16x3 tensor-core GEMM 128x128x16, 8 warps (4x2), dbuf 48KB ----------------
__global__ __launch_bounds__(256) void gemm_f16x3_kernel(
    const float* __restrict__ A,
    const float* __restrict__ Bf,
    const __half* __restrict__ Bhi, const __half* __restrict__ Blo,
    float* __restrict__ C,
    int M, int N, int K, int lda, int ldb, int ldc,
    int innerN,
    long long sAo, long long sAi, long long sBo, long long sBi,
    long long sCo, long long sCi,
    const int* __restrict__ rowIdx, const int* __restrict__ tileExpert,
    long long expStrideB, float alpha, int actMode, int cT)
{
    __shared__ unsigned AsH[2][128][12];
    __shared__ unsigned AsL[2][128][12];
    __shared__ unsigned BsH[2][128][12];
    __shared__ unsigned BsL[2][128][12];

    int z  = blockIdx.z;
    int zo = z / innerN, zi = z - zo*innerN;
    A += zo*sAo + zi*sAi;
    C += zo*sCo + zi*sCi;
    long long boff = zo*sBo + zi*sBi;
    if (tileExpert) boff += (long long)tileExpert[blockIdx.y] * expStrideB;
    if (Bf) Bf += boff; else { Bhi += boff; Blo += boff; }

    const int tm0 = blockIdx.y * 128;
    const int tn0 = blockIdx.x * 128;
    const int tid = threadIdx.x;
    const int lane = tid & 31;
    const int warp = tid >> 5;
    const int wm = (warp & 3) * 32;
    const int wn = (warp >> 2) * 64;
    const int g = lane >> 2;
    const int q = lane & 3;

    // loaders: 2 threads per row; each owns 8 consecutive k elements
    const int lrow = tid >> 1;
    const int lsel = tid & 1;
    const int loff = lsel * 8;

    int grow = tm0 + lrow;
    bool aval = grow < M;
    int srcRow = aval ? (rowIdx ? (rowIdx[grow] & (NTOK-1)) : grow) : 0;
    const float* Aptr = A + (long long)srcRow * lda + loff;
    bool bval = (tn0 + lrow) < N;
    const float*  Bptr = Bf  ? (Bf  + (long long)(tn0 + lrow) * ldb + loff) : (const float*)0;
    const __half* BhiP = Bhi ? (Bhi + (long long)(tn0 + lrow) * ldb + loff) : (const __half*)0;
    const __half* BloP = Blo ? (Blo + (long long)(tn0 + lrow) * ldb + loff) : (const __half*)0;

    float acc[2][8][4];
    #pragma unroll
    for (int mi=0;mi<2;mi++)
        #pragma unroll
        for (int ni=0;ni<8;ni++)
            #pragma unroll
            for (int t=0;t<4;t++) acc[mi][ni][t]=0.f;

    float4 ra0 = make_float4(0.f,0.f,0.f,0.f), ra1 = ra0;
    float4 rb0 = ra0, rb1 = ra0;
    uint4  rbh = make_uint4(0,0,0,0), rbl = rbh;

    // ---- prefetch tile 0 into registers ----
    if (aval){ ra0 = *(const float4*)(Aptr); ra1 = *(const float4*)(Aptr + 4); }
    if (Bf){ if (bval){ rb0 = *(const float4*)(Bptr); rb1 = *(const float4*)(Bptr + 4); } }
    else   { if (bval){ rbh = *(const uint4*)(BhiP);  rbl = *(const uint4*)(BloP); } }

    // ---- store tile 0 ----
    {
        unsigned h0,l0,h1,l1,h2,l2,h3,l3;
        split2(ra0.x,ra0.y,h0,l0); split2(ra0.z,ra0.w,h1,l1);
        split2(ra1.x,ra1.y,h2,l2); split2(ra1.z,ra1.w,h3,l3);
        *(uint4*)&AsH[0][lrow][lsel*4] = make_uint4(h0,h1,h2,h3);
        *(uint4*)&AsL[0][lrow][lsel*4] = make_uint4(l0,l1,l2,l3);
        if (Bf){
            split2(rb0.x,rb0.y,h0,l0); split2(rb0.z,rb0.w,h1,l1);
            split2(rb1.x,rb1.y,h2,l2); split2(rb1.z,rb1.w,h3,l3);
            *(uint4*)&BsH[0][lrow][lsel*4] = make_uint4(h0,h1,h2,h3);
            *(uint4*)&BsL[0][lrow][lsel*4] = make_uint4(l0,l1,l2,l3);
        } else {
            *(uint4*)&BsH[0][lrow][lsel*4] = rbh;
            *(uint4*)&BsL[0][lrow][lsel*4] = rbl;
        }
    }
    __syncthreads();

    int buf = 0;
    for (int k0 = 0; k0 < K; k0 += 16){
        bool has = (k0 + 16) < K;
        if (has){
            int kn = k0 + 16;
            if (aval){ ra0 = *(const float4*)(Aptr + kn); ra1 = *(const float4*)(Aptr + kn + 4); }
            if (Bf){ if (bval){ rb0 = *(const float4*)(Bptr + kn); rb1 = *(const float4*)(Bptr + kn + 4); } }
            else   { if (bval){ rbh = *(const uint4*)(BhiP + kn);  rbl = *(const uint4*)(BloP + kn); } }
        }

        // ---- compute on buf ----
        {
            unsigned ah[2][4], al[2][4];
            #pragma unroll
            for (int mi = 0; mi < 2; mi++){
                int row = wm + mi*16 + g;
                ah[mi][0] = AsH[buf][row  ][q];
                ah[mi][1] = AsH[buf][row+8][q];
                ah[mi][2] = AsH[buf][row  ][q+4];
                ah[mi][3] = AsH[buf][row+8][q+4];
                al[mi][0] = AsL[buf][row  ][q];
                al[mi][1] = AsL[buf][row+8][q];
                al[mi][2] = AsL[buf][row  ][q+4];
                al[mi][3] = AsL[buf][row+8][q+4];
            }
            #pragma unroll
            for (int ni = 0; ni < 8; ni++){
                int col = wn + ni*8 + g;
                unsigned bh0 = BsH[buf][col][q], bh1 = BsH[buf][col][q+4];
                unsigned bl0 = BsL[buf][col][q], bl1 = BsL[buf][col][q+4];
                #pragma unroll
                for (int mi = 0; mi < 2; mi++){
                    mma_f16(acc[mi][ni], ah[mi][0],ah[mi][1],ah[mi][2],ah[mi][3], bh0, bh1);
                    mma_f16(acc[mi][ni], ah[mi][0],ah[mi][1],ah[mi][2],ah[mi][3], bl0, bl1);
                    mma_f16(acc[mi][ni], al[mi][0],al[mi][1],al[mi][2],al[mi][3], bh0, bh1);
                }
            }
        }

        if (has){
            int nb = buf ^ 1;
            unsigned h0,l0,h1,l1,h2,l2,h3,l3;
            split2(ra0.x,ra0.y,h0,l0); split2(ra0.z,ra0.w,h1,l1);
            split2(ra1.x,ra1.y,h2,l2); split2(ra1.z,ra1.w,h3,l3);
            *(uint4*)&AsH[nb][lrow][lsel*4] = make_uint4(h0,h1,h2,h3);
            *(uint4*)&AsL[nb][lrow][lsel*4] = make_uint4(l0,l1,l2,l3);
            if (Bf){
                split2(rb0.x,rb0.y,h0,l0); split2(rb0.z,rb0.w,h1,l1);
                split2(rb1.x,rb1.y,h2,l2); split2(rb1.z,rb1.w,h3,l3);
                *(uint4*)&BsH[nb][lrow][lsel*4] = make_uint4(h0,h1,h2,h3);
                *(uint4*)&BsL[nb][lrow][lsel*4] = make_uint4(l0,l1,l2,l3);
            } else {
                *(uint4*)&BsH[nb][lrow][lsel*4] = rbh;
                *(uint4*)&BsL[nb][lrow][lsel*4] = rbl;
            }
            __syncthreads();
            buf = nb;
        }
    }

    // ---- epilogue ----
    #pragma unroll
    for (int mi = 0; mi < 2; mi++){
        #pragma unroll
        for (int rr = 0; rr < 2; rr++){
            int row = tm0 + wm + mi*16 + g + rr*8;
            if (row >= M) continue;
            #pragma unroll
            for (int ni = 0; ni < 8; ni++){
                int col = tn0 + wn + ni*8 + q*2;
                if (col + 1 >= N + 1) continue;   // col < N (col even, N even)
                float v0 = acc[mi][ni][rr*2+0] * alpha;
                float v1 = acc[mi][ni][rr*2+1] * alpha;
                if (actMode == 1){
                    v0 = 0.5f * v0 * (1.f + erff(v0 * 0.70710678118654752f));
                    v1 = 0.5f * v1 * (1.f + erff(v1 * 0.70710678118654752f));
                }
                if (!cT){
                    *(float2*)&C[(long long)row * ldc + col] = make_float2(v0, v1);
                } else {
                    C[(long long)(col  ) * ldc + row] = v0;
                    if (col + 1 < N) C[(long long)(col+1) * ldc + row] = v1;
                }
            }
        }
    }
}

// ---------------- masked row softmax ----------------
__global__ __launch_bounds__(256) void softmax_kernel(float* __restrict__ s,
                                                      const int* __restrict__ mask){
    long long r = blockIdx.x;
    int qq = (int)(r & 1023);
    int b = (int)(r >> 14);
    float* sr = s + (r << 10);
    const int* mr = mask + ((long long)b << 20) + ((long long)qq << 10);
    __shared__ float buf[SEQ];
    __shared__ float red[8];
    float mx = -3.0e38f;
    for (int i = threadIdx.x; i < SEQ; i += 256){
        float v = sr[i];
        if (mr[i] == 0) v = -1e9f;
        buf[i] = v;
        mx = fmaxf(mx, v);
    }
    mx = blockMax(mx, red);
    float sum = 0.f;
    for (int i = threadIdx.x; i < SEQ; i += 256){
        float e = expf(buf[i]-mx);
        buf[i] = e; sum += e;
    }
    sum = blockSum(sum, red);
    float inv = 1.f / sum;
    for (int i = threadIdx.x; i < SEQ; i += 256)
        sr[i] = buf[i] * inv;
}

// ---------------- delta branch ----------------
__global__ __launch_bounds__(256) void ctx_kernel(const float* __restrict__ kd,
                                                  const float* __restrict__ vd,
                                                  float* __restrict__ ctx){
    int z = blockIdx.x; int b = z >> 4, h = z & 15;
    const float* kbase = kd + ((long long)b*SEQ)*DM + h*DK;
    const float* vbase = vd + ((long long)b*SEQ)*DM + h*DK;
    __shared__ float ks[64][65];
    __shared__ float vs[64][65];
    int tid = threadIdx.x;
    int d0 = (tid >> 4) << 2;
    int e0 = (tid & 15) << 2;
    float acc[4][4];
    #pragma unroll
    for (int i=0;i<4;i++)
        #pragma unroll
        for (int j=0;j<4;j++) acc[i][j]=0.f;

    for (int s0 = 0; s0 < SEQ; s0 += 64) {
        for (int t = tid; t < 64*16; t += 256) {
            int rr = t >> 4; int cc = (t & 15) << 2;
            float4 kv = *(const float4*)(kbase + (long long)(s0+rr)*DM + cc);
            float4 vv = *(const float4*)(vbase + (long long)(s0+rr)*DM + cc);
            ks[rr][cc+0]=kv.x; ks[rr][cc+1]=kv.y; ks[rr][cc+2]=kv.z; ks[rr][cc+3]=kv.w;
            vs[rr][cc+0]=vv.x; vs[rr][cc+1]=vv.y; vs[rr][cc+2]=vv.z; vs[rr][cc+3]=vv.w;
        }
        __syncthreads();
        #pragma unroll 4
        for (int ss=0; ss<64; ss++){
            float kr[4], vr[4];
            #pragma unroll
            for (int i=0;i<4;i++) kr[i]=ks[ss][d0+i];
            #pragma unroll
            for (int j=0;j<4;j++) vr[j]=vs[ss][e0+j];
            #pragma unroll
            for (int i=0;i<4;i++)
                #pragma unroll
                for (int j=0;j<4;j++) acc[i][j] += kr[i]*vr[j];
        }
        __syncthreads();
    }
    float* cbase = ctx + (long long)z*DK*DK;
    #pragma unroll
    for (int i=0;i<4;i++)
        #pragma unroll
        for (int j=0;j<4;j++)
            cbase[(d0+i)*DK + e0+j] = acc[i][j];
}

__global__ void ksum_kernel(const float* __restrict__ kd, float* __restrict__ ksum){
    int z = blockIdx.x; int b = z >> 4, h = z & 15;
    int d = threadIdx.x;
    const float* base = kd + ((long long)b*SEQ)*DM + h*DK + d;
    float s = 0.f;
    #pragma unroll 4
    for (int ss=0; ss<SEQ; ss++) s += fmaxf(base[(long long)ss*DM], 0.f);
    ksum[z*DK + d] = s;
}

__global__ __launch_bounds__(256) void delta_kernel(const float* __restrict__ qd,
                                                    const float* __restrict__ ctx,
                                                    const float* __restrict__ ksum,
                                                    float* __restrict__ delta){
    int z = blockIdx.x >> 2;
    int sc = blockIdx.x & 3;
    int b = z >> 4, h = z & 15;
    __shared__ float cs[DK*DK];
    __shared__ float kss[DK];
    for (int i = threadIdx.x; i < DK*DK; i += 256) cs[i] = ctx[(long long)z*DK*DK + i];
    if (threadIdx.x < DK) kss[threadIdx.x] = ksum[z*DK + threadIdx.x];
    __syncthreads();
    int s = sc*256 + threadIdx.x;
    const float* qrow = qd + ((long long)(b*SEQ + s))*DM + h*DK;
    float q[DK];
    #pragma unroll
    for (int d=0; d<DK; d+=4){
        float4 v = *(const float4*)(qrow + d);
        q[d+0]=fmaxf(v.x,0.f); q[d+1]=fmaxf(v.y,0.f);
        q[d+2]=fmaxf(v.z,0.f); q[d+3]=fmaxf(v.w,0.f);
    }
    float zv = 1e-6f;
    #pragma unroll
    for (int d=0; d<DK; d++) zv += q[d]*kss[d];
    float invz = 1.f / zv;
    float* orow = delta + ((long long)(b*SEQ + s))*DM + h*DK;
    for (int e=0; e<DK; e++){
        float a = 0.f;
        #pragma unroll
        for (int d=0; d<DK; d++) a += q[d]*cs[d*DK + e];
        orow[e] = a * invz;
    }
}

// ---------------- gate ----------------
__global__ __launch_bounds__(256) void gate_kernel(const float* __restrict__ xn,
                                                   const float* __restrict__ wg,
                                                   float* __restrict__ gate){
    int t = blockIdx.x;
    float p0=0.f, p1=0.f;
    for (int k = threadIdx.x; k < DM; k += 256){
        float xv = xn[(long long)t*DM + k];
        p0 += xv*wg[k*2+0];
        p1 += xv*wg[k*2+1];
    }
    __shared__ float red[8];
    p0 = blockSum(p0, red);
    p1 = blockSum(p1, red);
    if (threadIdx.x == 0){
        float m = fmaxf(p0,p1);
        float e0 = expf(p0-m), e1 = expf(p1-m);
        float inv = 1.f/(e0+e1);
        gate[t*2+0] = e0*inv;
        gate[t*2+1] = e1*inv;
    }
}

__global__ void combine1_kernel(const float* __restrict__ x,
                                const float* __restrict__ dense,
                                const float* __restrict__ delta,
                                const float* __restrict__ gate,
                                float* __restrict__ x1){
    long long i = (long long)blockIdx.x*256 + threadIdx.x;
    int t = (int)(i >> 10);
    x1[i] = x[i] + gate[t*2]*dense[i] + gate[t*2+1]*delta[i];
}

// ---------------- router ----------------
__global__ __launch_bounds__(256) void router_kernel(const float* __restrict__ xn2,
                                                     const float* __restrict__ wr,
                                                     int* __restrict__ topk_idx,
                                                     float* __restrict__ topk_w,
                                                     int* __restrict__ counts){
    int t = blockIdx.x;
    float p[NE];
    #pragma unroll
    for (int e=0;e<NE;e++) p[e]=0.f;
    for (int k = threadIdx.x; k < DM; k += 256){
        float xv = xn2[(long long)t*DM + k];
        #pragma unroll
        for (int e=0;e<NE;e++) p[e] += xv*wr[k*NE + e];
    }
    __shared__ float part[NE][8];
    int w = threadIdx.x >> 5;
    #pragma unroll
    for (int e=0;e<NE;e++){
        float v = warpSum(p[e]);
        if ((threadIdx.x & 31)==0) part[e][w] = v;
    }
    __syncthreads();
    if (threadIdx.x == 0){
        float lg[NE];
        for (int e=0;e<NE;e++){
            float s=0.f;
            for (int ww=0; ww<8; ww++) s += part[e][ww];
            lg[e]=s;
        }
        int i0=0; float v0=lg[0];
        for (int e=1;e<NE;e++) if (lg[e]>v0){v0=lg[e];i0=e;}
        int i1=-1; float v1=-3.0e38f;
        for (int e=0;e<NE;e++) if (e!=i0 && lg[e]>v1){v1=lg[e];i1=e;}
        float e1 = expf(v1-v0);
        float inv = 1.f/(1.f+e1);
        topk_idx[t*2+0]=i0; topk_idx[t*2+1]=i1;
        topk_w[t*2+0]=inv;  topk_w[t*2+1]=e1*inv;
        atomicAdd(&counts[i0],1); atomicAdd(&counts[i1],1);
    }
}

__global__ void prep_kernel(int* counts, int* cursor, int* tok){
    int i = blockIdx.x*256 + threadIdx.x;
    if (i < NE){ counts[i]=0; cursor[i]=0; }
    if (i < PAIR_CAP) tok[i]=0;
}

__global__ void scan_kernel(const int* counts, int* off, int* tile_e){
    if (threadIdx.x==0 && blockIdx.x==0){
        int o = 0;
        off[0]=0;
        for (int e=0;e<NE;e++){ o += (counts[e]+127)&~127; off[e+1]=o; }
        for (int t=0;t<NTILE72;t++){
            int row = t*128;
            int ee = NE-1;
            for (int i=0;i<NE;i++){ if (row < off[i+1]) { ee=i; break; } }
            tile_e[t]=ee;
        }
    }
}

__global__ void place_kernel(const int* __restrict__ topk_idx,
                             const int* __restrict__ off,
                             int* cursor, int* tok, int* pair_pos){
    int t = blockIdx.x*256 + threadIdx.x;
    if (t >= NTOK) return;
    for (int k=0;k<2;k++){
        int e = topk_idx[t*2+k];
        int pos = atomicAdd(&cursor[e],1);
        int r = off[e] + pos;
        tok[r] = t;
        pair_pos[t*2+k] = r;
    }
}

__global__ void final_kernel(const float* __restrict__ x1,
                             const float* __restrict__ y2,
                             const float* __restrict__ topk_w,
                             const int* __restrict__ pair_pos,
                             float* __restrict__ out){
    long long i = (long long)blockIdx.x*256 + threadIdx.x;
    int t = (int)(i >> 10);
    int c = (int)(i & 1023);
    int p0 = pair_pos[t*2+0], p1 = pair_pos[t*2+1];
    out[i] = x1[i] + topk_w[t*2+0]*y2[(long long)p0*DM + c]
                   + topk_w[t*2+1]*y2[(long long)p1*DM + c];
}

// ---------------- host side ----------------
static void gemm(const float* A, const float* Bf, const __half* Bhi, const __half* Blo,
                 float* C,
                 int M, int N, int K, int lda, int ldb, int ldc,
                 int batch, int innerN,
                 long long sAo, long long sAi, long long sBo, long long sBi,
                 long long sCo, long long sCi,
                 const int* rowIdx, const int* tileE, long long expSB,
                 float alpha, int act, int cT){
    dim3 grid((N+127)/128, (M+127)/128, batch);
    gemm_f16x3_kernel<<<grid, 256>>>(A,Bf,Bhi,Blo,C,M,N,K,lda,ldb,ldc,innerN,
                                     sAo,sAi,sBo,sBi,sCo,sCi,
                                     rowIdx,tileE,expSB,alpha,act,cT);
}

extern "C" void kernel_launch(void* const* d_in, const int* in_sizes, int n_in,
                              void* d_out, int out_size){
    const float* x        = (const float*)d_in[0];
    const int*   mask     = (const int*)  d_in[1];
    const float* ln1_g    = (const float*)d_in[2];
    const float* ln1_b    = (const float*)d_in[3];
    const float* wq       = (const float*)d_in[4];
    const float* wk       = (const float*)d_in[5];
    const float* wv       = (const float*)d_in[6];
    const float* wo       = (const float*)d_in[7];
    const float* wqd      = (const float*)d_in[8];
    const float* wkd      = (const float*)d_in[9];
    const float* wvd      = (const float*)d_in[10];
    const float* wod      = (const float*)d_in[11];
    const float* w_gate   = (const float*)d_in[12];
    const float* ln2_g    = (const float*)d_in[13];
    const float* ln2_b    = (const float*)d_in[14];
    const float* w_router = (const float*)d_in[15];
    const float* e_w1     = (const float*)d_in[16];
    const float* e_w2     = (const float*)d_in[17];
    float* out = (float*)d_out;

    float *xn1,*q,*k,*vT,*qd,*kd,*vd,*scores,*attnctx,*delta,*dense_o,*delta_o;
    float *gate,*x1,*xn2,*ctx,*ksum,*h1,*y2,*topk_w;
    int *topk_idx,*counts,*cursor,*off,*tile_e,*tok,*pair_pos;
    __half *wT_hi,*wT_lo,*e1T_hi,*e1T_lo,*e2T_hi,*e2T_lo;

    cudaGetSymbolAddress((void**)&xn1,     g_xn1);
    cudaGetSymbolAddress((void**)&q,       g_q);
    cudaGetSymbolAddress((void**)&k,       g_k);
    cudaGetSymbolAddress((void**)&vT,      g_vT);
    cudaGetSymbolAddress((void**)&qd,      g_qd);
    cudaGetSymbolAddress((void**)&kd,      g_kd);
    cudaGetSymbolAddress((void**)&vd,      g_vd);
    cudaGetSymbolAddress((void**)&scores,  g_scores);
    cudaGetSymbolAddress((void**)&attnctx, g_attnctx);
    cudaGetSymbolAddress((void**)&delta,   g_delta);
    cudaGetSymbolAddress((void**)&dense_o, g_dense_o);
    cudaGetSymbolAddress((void**)&delta_o, g_delta_o);
    cudaGetSymbolAddress((void**)&gate,    g_gate);
    cudaGetSymbolAddress((void**)&x1,      g_x1);
    cudaGetSymbolAddress((void**)&xn2,     g_xn2);
    cudaGetSymbolAddress((void**)&ctx,     g_ctx);
    cudaGetSymbolAddress((void**)&ksum,    g_ksum);
    cudaGetSymbolAddress((void**)&h1,      g_h1);
    cudaGetSymbolAddress((void**)&y2,      g_y2);
    cudaGetSymbolAddress((void**)&topk_w,  g_topk_w);
    cudaGetSymbolAddress((void**)&topk_idx,g_topk_idx);
    cudaGetSymbolAddress((void**)&counts,  g_counts);
    cudaGetSymbolAddress((void**)&cursor,  g_cursor);
    cudaGetSymbolAddress((void**)&off,     g_off);
    cudaGetSymbolAddress((void**)&tile_e,  g_tile_e);
    cudaGetSymbolAddress((void**)&tok,     g_tok);
    cudaGetSymbolAddress((void**)&pair_pos,g_pair_pos);
    cudaGetSymbolAddress((void**)&wT_hi,   g_wT_hi);
    cudaGetSymbolAddress((void**)&wT_lo,   g_wT_lo);
    cudaGetSymbolAddress((void**)&e1T_hi,  g_e1T_hi);
    cudaGetSymbolAddress((void**)&e1T_lo,  g_e1T_lo);
    cudaGetSymbolAddress((void**)&e2T_hi,  g_e2T_hi);
    cudaGetSymbolAddress((void**)&e2T_lo,  g_e2T_lo);

    const long long TOKD = (long long)SEQ*DM;

    // 0. pre-split weights
    {
        dim3 blk(32,8);
        const float* ws[8] = {wq, wk, wv, wo, wqd, wkd, wvd, wod};
        for (int i=0;i<8;i++)
            wsplit_kernel<<<dim3(32,32,1), blk>>>(ws[i], wT_hi + (long long)i*WSZ,
                                                  wT_lo + (long long)i*WSZ, DM, DM);
        wsplit_kernel<<<dim3(DFF/32, DM/32, NE), blk>>>(e_w1, e1T_hi, e1T_lo, DM, DFF);
        wsplit_kernel<<<dim3(DM/32, DFF/32, NE), blk>>>(e_w2, e2T_hi, e2T_lo, DFF, DM);
    }

    // 1. LN1
    ln_kernel<<<NTOK,256>>>(x, ln1_g, ln1_b, xn1);

    // 2-7. projections
    gemm(xn1, 0, wT_hi+0LL*WSZ, wT_lo+0LL*WSZ, q,  NTOK,DM,DM, DM,DM,DM, 1,1, 0,0,0,0,0,0, 0,0,0, 1.f,0,0);
    gemm(xn1, 0, wT_hi+1LL*WSZ, wT_lo+1LL*WSZ, k,  NTOK,DM,DM, DM,DM,DM, 1,1, 0,0,0,0,0,0, 0,0,0, 1.f,0,0);
    gemm(xn1, 0, wT_hi+2LL*WSZ, wT_lo+2LL*WSZ, vT, NTOK,DM,DM, DM,DM,NTOK, 1,1, 0,0,0,0,0,0, 0,0,0, 1.f,0,1);
    gemm(xn1, 0, wT_hi+4LL*WSZ, wT_lo+4LL*WSZ, qd, NTOK,DM,DM, DM,DM,DM, 1,1, 0,0,0,0,0,0, 0,0,0, 1.f,0,0);
    gemm(xn1, 0, wT_hi+5LL*WSZ, wT_lo+5LL*WSZ, kd, NTOK,DM,DM, DM,DM,DM, 1,1, 0,0,0,0,0,0, 0,0,0, 1.f,0,0);
    gemm(xn1, 0, wT_hi+6LL*WSZ, wT_lo+6LL*WSZ, vd, NTOK,DM,DM, DM,DM,DM, 1,1, 0,0,0,0,0,0, 0,0,0, 1.f,0,0);

    // 8. scores = Q @ K^T / 8
    gemm(q, k, 0, 0, scores, SEQ, SEQ, DK, DM, DM, SEQ,
         NB*NH, NH,
         TOKD, DK,  TOKD, DK,  (long long)NH*SEQ*SEQ, (long long)SEQ*SEQ,
         0, 0, 0, 0.125f, 0, 0);

    // 9. masked softmax
    softmax_kernel<<<NB*NH*SEQ, 256>>>(scores, mask);

    // 10. attnctx = P @ V
    gemm(scores, vT, 0, 0, attnctx, SEQ, DK, SEQ, SEQ, NTOK, DM,
         NB*NH, NH,
         (long long)NH*SEQ*SEQ, (long long)SEQ*SEQ,  SEQ, (long long)DK*NTOK,
         TOKD, DK,
         0, 0, 0, 1.f, 0, 0);

    // 11-13. delta branch
    ctx_kernel<<<NB*NH, 256>>>(kd, vd, ctx);
    ksum_kernel<<<NB*NH, 64>>>(kd, ksum);
    delta_kernel<<<NB*NH*4, 256>>>(qd, ctx, ksum, delta);

    // 14-15. output projections
    gemm(attnctx, 0, wT_hi+3LL*WSZ, wT_lo+3LL*WSZ, dense_o, NTOK,DM,DM, DM,DM,DM, 1,1, 0,0,0,0,0,0, 0,0,0, 1.f,0,0);
    gemm(delta,   0, wT_hi+7LL*WSZ, wT_lo+7LL*WSZ, delta_o, NTOK,DM,DM, DM,DM,DM, 1,1, 0,0,0,0,0,0, 0,0,0, 1.f,0,0);

    // 16-17. gate + combine
    gate_kernel<<<NTOK,256>>>(xn1, w_gate, gate);
    combine1_kernel<<<NTOK*DM/256, 256>>>(x, dense_o, delta_o, gate, x1);

    // 18. LN2
    ln_kernel<<<NTOK,256>>>(x1, ln2_g, ln2_b, xn2);

    // 19-22. routing
    prep_kernel<<<(PAIR_CAP+255)/256, 256>>>(counts, cursor, tok);
    router_kernel<<<NTOK, 256>>>(xn2, w_router, topk_idx, topk_w, counts);
    scan_kernel<<<1,32>>>(counts, off, tile_e);
    place_kernel<<<(NTOK+255)/256, 256>>>(topk_idx, off, cursor, tok, pair_pos);

    // 23. expert GEMM1 (gathered, gelu)
    gemm(xn2, 0, e1T_hi, e1T_lo, h1, PAIR_CAP, DFF, DM, DM, DM, DFF,
         1,1, 0,0,0,0,0,0,
         tok, tile_e, (long long)DM*DFF, 1.f, 1, 0);

    // 24. expert GEMM2
    gemm(h1, 0, e2T_hi, e2T_lo, y2, PAIR_CAP, DM, DFF, DFF, DFF, DM,
         1,1, 0,0,0,0,0,0,
         0, tile_e, (long long)DFF*DM, 1.f, 0, 0);

    // 25. final combine
    final_kernel<<<NTOK*DM/256, 256>>>(x1, y2, topk_w, pair_pos, out);
}

// round 5
// speedup vs baseline: 2.0845x; 1.2399x over previous
#include <cuda_runtime.h>
#include <cuda_fp16.h>
#include <math.h>

// ---------------- problem constants ----------------
#define NTOK 4096              // B*S
#define DM   1024
#define DFF  2048
#define NH   16
#define DK   64
#define NB   4
#define SEQ  1024
#define NE   8
#define PAIR_CAP 9216
#define NTILE72  72
#define WSZ  (1024*1024)

// ---------------- fp32 scratch ----------------
__device__ float g_xn1[NTOK*DM];
__device__ float g_qd [NTOK*DM];
__device__ float g_kd [NTOK*DM];
__device__ float g_vd [NTOK*DM];
__device__ float g_scores[(long long)NB*NH*SEQ*SEQ];   // 256MB
__device__ float g_dense_o[NTOK*DM];
__device__ float g_delta_o[NTOK*DM];
__device__ float g_gate[NTOK*2];
__device__ float g_x1 [NTOK*DM];
__device__ float g_xn2[NTOK*DM];
__device__ float g_ctx [NB*NH*DK*DK];
__device__ float g_ksum[NB*NH*DK];
__device__ float g_y2[(long long)PAIR_CAP*DM];
__device__ int   g_topk_idx[NTOK*2];
__device__ float g_topk_w [NTOK*2];
__device__ int   g_counts[NE];
__device__ int   g_cursor[NE];
__device__ int   g_off[NE+1];
__device__ int   g_tile_e[NTILE72];
__device__ int   g_tok[PAIR_CAP];
__device__ int   g_pair_pos[NTOK*2];

// ---------------- fp16 hi/lo scratch ----------------
__device__ __half g_xn1h[NTOK*DM],  g_xn1l[NTOK*DM];
__device__ __half g_qh  [NTOK*DM],  g_ql  [NTOK*DM];
__device__ __half g_kh  [NTOK*DM],  g_kl  [NTOK*DM];
__device__ __half g_vTh [DM*NTOK],  g_vTl [DM*NTOK];
__device__ __half g_ph  [(long long)NB*NH*SEQ*SEQ], g_pl[(long long)NB*NH*SEQ*SEQ];
__device__ __half g_acth[NTOK*DM],  g_actl[NTOK*DM];
__device__ __half g_dlh [NTOK*DM],  g_dll [NTOK*DM];
__device__ __half g_xn2h[NTOK*DM],  g_xn2l[NTOK*DM];
__device__ __half g_h1h [(long long)PAIR_CAP*DFF], g_h1l[(long long)PAIR_CAP*DFF];

__device__ __half g_wT_hi[8LL*WSZ];
__device__ __half g_wT_lo[8LL*WSZ];
__device__ __half g_e1T_hi[8LL*DM*DFF];
__device__ __half g_e1T_lo[8LL*DM*DFF];
__device__ __half g_e2T_hi[8LL*DFF*DM];
__device__ __half g_e2T_lo[8LL*DFF*DM];

// ---------------- helpers ----------------
__device__ __forceinline__ void mma_f16(float* d,
        unsigned a0, unsigned a1, unsigned a2, unsigned a3,
        unsigned b0, unsigned b1){
    asm volatile("mma.sync.aligned.m16n8k16.row.col.f32.f16.f16.f32 "
        "{%0,%1,%2,%3}, {%4,%5,%6,%7}, {%8,%9}, {%0,%1,%2,%3};"
        : "+f"(d[0]),"+f"(d[1]),"+f"(d[2]),"+f"(d[3])
        : "r"(a0),"r"(a1),"r"(a2),"r"(a3),"r"(b0),"r"(b1));
}
__device__ __forceinline__ unsigned packh(__half x, __half y){
    return (unsigned)__half_as_ushort(x) | ((unsigned)__half_as_ushort(y) << 16);
}
__device__ __forceinline__ void split2(float x, float y, unsigned& hi, unsigned& lo){
    __half hx = __float2half_rn(x), hy = __float2half_rn(y);
    __half lx = __float2half_rn(x - __half2float(hx));
    __half ly = __float2half_rn(y - __half2float(hy));
    hi = packh(hx, hy);
    lo = packh(lx, ly);
}
__device__ __forceinline__ void cp16(unsigned saddr, const void* g, bool v){
    asm volatile("cp.async.ca.shared.global [%0], [%1], 16, %2;"
        :: "r"(saddr), "l"(g), "r"(v ? 16 : 0));
}

__device__ __forceinline__ float warpSum(float v){
    #pragma unroll
    for (int o=16;o;o>>=1) v += __shfl_xor_sync(0xffffffffu, v, o);
    return v;
}
__device__ __forceinline__ float warpMax(float v){
    #pragma unroll
    for (int o=16;o;o>>=1) v = fmaxf(v, __shfl_xor_sync(0xffffffffu, v, o));
    return v;
}
__device__ __forceinline__ float blockSum(float v, float* red){
    v = warpSum(v);
    if ((threadIdx.x & 31) == 0) red[threadIdx.x>>5] = v;
    __syncthreads();
    if (threadIdx.x < 32) {
        float t = (threadIdx.x < 8) ? red[threadIdx.x] : 0.f;
        t = warpSum(t);
        if (threadIdx.x == 0) red[0] = t;
    }
    __syncthreads();
    float r = red[0];
    __syncthreads();
    return r;
}
__device__ __forceinline__ float blockMax(float v, float* red){
    v = warpMax(v);
    if ((threadIdx.x & 31) == 0) red[threadIdx.x>>5] = v;
    __syncthreads();
    if (threadIdx.x < 32) {
        float t = (threadIdx.x < 8) ? red[threadIdx.x] : -3.0e38f;
        t = warpMax(t);
        if (threadIdx.x == 0) red[0] = t;
    }
    __syncthreads();
    float r = red[0];
    __syncthreads();
    return r;
}

// ---------------- weight transpose + split ----------------
struct WP8 { const float* p[8]; };

__global__ void wsplit8_kernel(WP8 wp, __half* __restrict__ hiB, __half* __restrict__ loB){
    __shared__ float ts[32][33];
    int mat = blockIdx.z;
    const float* W = wp.p[mat];
    __half* hi = hiB + (long long)mat*WSZ;
    __half* lo = loB + (long long)mat*WSZ;
    int k0 = blockIdx.y*32, n0 = blockIdx.x*32;
    int tx = threadIdx.x, ty = threadIdx.y;   // 32 x 8
    #pragma unroll
    for (int i=0;i<4;i++)
        ts[ty+8*i][tx] = W[(long long)(k0+ty+8*i)*DM + n0 + tx];
    __syncthreads();
    #pragma unroll
    for (int i=0;i<4;i++){
        int n = n0 + ty + 8*i, k = k0 + tx;
        float v = ts[tx][ty+8*i];
        __half h = __float2half_rn(v);
        hi[(long long)n*DM + k] = h;
        lo[(long long)n*DM + k] = __float2half_rn(v - __half2float(h));
    }
}

__global__ void wsplit_kernel(const float* __restrict__ W,
                              __half* __restrict__ hi, __half* __restrict__ lo,
                              int K, int N){
    __shared__ float ts[32][33];
    long long zoff = (long long)blockIdx.z * K * N;
    W  += zoff; hi += zoff; lo += zoff;
    int k0 = blockIdx.y*32, n0 = blockIdx.x*32;
    int tx = threadIdx.x, ty = threadIdx.y;
    #pragma unroll
    for (int i=0;i<4;i++)
        ts[ty+8*i][tx] = W[(long long)(k0+ty+8*i)*N + n0 + tx];
    __syncthreads();
    #pragma unroll
    for (int i=0;i<4;i++){
        int n = n0 + ty + 8*i, k = k0 + tx;
        float v = ts[tx][ty+8*i];
        __half h = __float2half_rn(v);
        hi[(long long)n*K + k] = h;
        lo[(long long)n*K + k] = __float2half_rn(v - __half2float(h));
    }
}

// ---------------- layernorm (fp32 out + optional split out) ----------------
__global__ __launch_bounds__(256) void ln_kernel(const float* __restrict__ x,
                                                 const float* __restrict__ g,
                                                 const float* __restrict__ b,
                                                 float* __restrict__ y,
                                                 __half* __restrict__ yh,
                                                 __half* __restrict__ yl){
    __shared__ float row[DM];
    __shared__ float red[8];
    long long base = (long long)blockIdx.x * DM;
    float s = 0.f;
    for (int i = threadIdx.x; i < DM; i += 256) { float v = x[base+i]; row[i] = v; s += v; }
    s = blockSum(s, red);
    float mu = s * (1.f/DM);
    float vs = 0.f;
    for (int i = threadIdx.x; i < DM; i += 256) { float d = row[i]-mu; vs += d*d; }
    vs = blockSum(vs, red);
    float rstd = rsqrtf(vs * (1.f/DM) + 1e-5f);
    unsigned* oh = (unsigned*)(yh + base);
    unsigned* ol = (unsigned*)(yl + base);
    for (int i2 = threadIdx.x; i2 < DM/2; i2 += 256){
        int i = i2*2;
        float v0 = (row[i  ]-mu)*rstd*g[i  ] + b[i  ];
        float v1 = (row[i+1]-mu)*rstd*g[i+1] + b[i+1];
        if (y){ y[base+i] = v0; y[base+i+1] = v1; }
        unsigned h,l; split2(v0,v1,h,l);
        oh[i2] = h; ol[i2] = l;
    }
}

// ---------------- fp16x3 tensor-core GEMM, pre-split operands, cp.async ----------------
__global__ __launch_bounds__(256) void gemm_hh_kernel(
    const __half* __restrict__ Ahi, const __half* __restrict__ Alo,
    const __half* __restrict__ Bhi, const __half* __restrict__ Blo,
    float* __restrict__ Cf, __half* __restrict__ Chi, __half* __restrict__ Clo,
    int M, int N, int K, int lda, int ldb, int ldc,
    int innerN,
    long long sAo, long long sAi, long long sBo, long long sBi,
    long long sCo, long long sCi,
    const int* __restrict__ rowIdx, const int* __restrict__ tileExpert,
    long long expStrideB, float alpha, int actMode, int cT)
{
    __shared__ unsigned AsH[2][128][12];
    __shared__ unsigned AsL[2][128][12];
    __shared__ unsigned BsH[2][128][12];
    __shared__ unsigned BsL[2][128][12];

    int z  = blockIdx.z;
    int zo = z / innerN, zi = z - zo*innerN;
    Ahi += zo*sAo + zi*sAi;
    Alo += zo*sAo + zi*sAi;
    long long boff = zo*sBo + zi*sBi;
    if (tileExpert) boff += (long long)tileExpert[blockIdx.y] * expStrideB;
    Bhi += boff; Blo += boff;
    long long coff = zo*sCo + zi*sCi;

    const int tm0 = blockIdx.y * 128;
    const int tn0 = blockIdx.x * 128;
    const int tid = threadIdx.x;
    const int lane = tid & 31;
    const int warp = tid >> 5;
    const int wm = (warp & 3) * 32;
    const int wn = (warp >> 2) * 64;
    const int g = lane >> 2;
    const int q = lane & 3;

    // loaders: 2 threads/row, each owns 8 consecutive halves along k
    const int lrow = tid >> 1;
    const int lsel = tid & 1;
    const int loff = lsel * 8;

    int grow = tm0 + lrow;
    bool aval = grow < M;
    int srcRow = aval ? (rowIdx ? (rowIdx[grow] & (NTOK-1)) : grow) : 0;
    const __half* AhiP = Ahi + (long long)srcRow * lda + loff;
    const __half* AloP = Alo + (long long)srcRow * lda + loff;
    bool bval = (tn0 + lrow) < N;
    int brow = bval ? (tn0 + lrow) : 0;
    const __half* BhiP = Bhi + (long long)brow * ldb + loff;
    const __half* BloP = Blo + (long long)brow * ldb + loff;

    // smem cp.async targets (buf 0 address; buf stride = 6144 bytes)
    unsigned base_off = (unsigned)((lrow*12 + lsel*4)*4);
    unsigned aH0 = (unsigned)__cvta_generic_to_shared(&AsH[0][0][0]) + base_off;
    unsigned aL0 = (unsigned)__cvta_generic_to_shared(&AsL[0][0][0]) + base_off;
    unsigned bH0 = (unsigned)__cvta_generic_to_shared(&BsH[0][0][0]) + base_off;
    unsigned bL0 = (unsigned)__cvta_generic_to_shared(&BsL[0][0][0]) + base_off;

    float acc[2][8][4];
    #pragma unroll
    for (int mi=0;mi<2;mi++)
        #pragma unroll
        for (int ni=0;ni<8;ni++)
            #pragma unroll
            for (int t=0;t<4;t++) acc[mi][ni][t]=0.f;

    // prologue: tile 0
    {
        cp16(aH0, AhiP, aval);
        cp16(aL0, AloP, aval);
        cp16(bH0, BhiP, bval);
        cp16(bL0, BloP, bval);
        asm volatile("cp.async.commit_group;");
        asm volatile("cp.async.wait_group 0;");
    }
    __syncthreads();

    int buf = 0;
    for (int k0 = 0; k0 < K; k0 += 16){
        bool has = (k0 + 16) < K;
        if (has){
            int kn = k0 + 16;
            unsigned boffm = (buf^1) * 6144u;
            cp16(aH0 + boffm, AhiP + kn, aval);
            cp16(aL0 + boffm, AloP + kn, aval);
            cp16(bH0 + boffm, BhiP + kn, bval);
            cp16(bL0 + boffm, BloP + kn, bval);
            asm volatile("cp.async.commit_group;");
        }

        // compute on buf
        {
            unsigned ah[2][4], al[2][4];
            #pragma unroll
            for (int mi = 0; mi < 2; mi++){
                int row = wm + mi*16 + g;
                ah[mi][0] = AsH[buf][row  ][q];
                ah[mi][1] = AsH[buf][row+8][q];
                ah[mi][2] = AsH[buf][row  ][q+4];
                ah[mi][3] = AsH[buf][row+8][q+4];
                al[mi][0] = AsL[buf][row  ][q];
                al[mi][1] = AsL[buf][row+8][q];
                al[mi][2] = AsL[buf][row  ][q+4];
                al[mi][3] = AsL[buf][row+8][q+4];
            }
            #pragma unroll
            for (int ni = 0; ni < 8; ni++){
                int col = wn + ni*8 + g;
                unsigned bh0 = BsH[buf][col][q], bh1 = BsH[buf][col][q+4];
                unsigned bl0 = BsL[buf][col][q], bl1 = BsL[buf][col][q+4];
                #pragma unroll
                for (int mi = 0; mi < 2; mi++){
                    mma_f16(acc[mi][ni], ah[mi][0],ah[mi][1],ah[mi][2],ah[mi][3], bh0, bh1);
                    mma_f16(acc[mi][ni], ah[mi][0],ah[mi][1],ah[mi][2],ah[mi][3], bl0, bl1);
                    mma_f16(acc[mi][ni], al[mi][0],al[mi][1],al[mi][2],al[mi][3], bh0, bh1);
                }
            }
        }

        if (has){
            asm volatile("cp.async.wait_group 0;");
            __syncthreads();
            buf ^= 1;
        }
    }

    // epilogue
    float* CfP = Cf ? (Cf + coff) : (float*)0;
    __half* ChiP = Chi ? (Chi + coff) : (__half*)0;
    __half* CloP = Clo ? (Clo + coff) : (__half*)0;
    #pragma unroll
    for (int mi = 0; mi < 2; mi++){
        #pragma unroll
        for (int rr = 0; rr < 2; rr++){
            int row = tm0 + wm + mi*16 + g + rr*8;
            if (row >= M) continue;
            #pragma unroll
            for (int ni = 0; ni < 8; ni++){
                int col = tn0 + wn + ni*8 + q*2;
                if (col >= N) continue;
                float v0 = acc[mi][ni][rr*2+0] * alpha;
                float v1 = acc[mi][ni][rr*2+1] * alpha;
                if (actMode == 1){
                    v0 = 0.5f * v0 * (1.f + erff(v0 * 0.70710678118654752f));
                    v1 = 0.5f * v1 * (1.f + erff(v1 * 0.70710678118654752f));
                }
                if (!cT){
                    long long ofs = (long long)row * ldc + col;
                    if (CfP) *(float2*)&CfP[ofs] = make_float2(v0, v1);
                    if (ChiP){
                        unsigned h,l; split2(v0,v1,h,l);
                        *(unsigned*)&ChiP[ofs] = h;
                        *(unsigned*)&CloP[ofs] = l;
                    }
                } else {
                    if (CfP){
                        CfP[(long long)(col  ) * ldc + row] = v0;
                        if (col + 1 < N) CfP[(long long)(col+1) * ldc + row] = v1;
                    }
                    if (ChiP){
                        __half h0 = __float2half_rn(v0);
                        __half h1v = __float2half_rn(v1);
                        ChiP[(long long)(col) * ldc + row] = h0;
                        CloP[(long long)(col) * ldc + row] = __float2half_rn(v0 - __half2float(h0));
                        if (col + 1 < N){
                            ChiP[(long long)(col+1) * ldc + row] = h1v;
                            CloP[(long long)(col+1) * ldc + row] = __float2half_rn(v1 - __half2float(h1v));
                        }
                    }
                }
            }
        }
    }
}

// ---------------- masked row softmax -> split halves ----------------
__global__ __launch_bounds__(256) void softmax_kernel(const float* __restrict__ s,
                                                      const int* __restrict__ mask,
                                                      __half* __restrict__ ph,
                                                      __half* __restrict__ pl){
    long long r = blockIdx.x;
    int qq = (int)(r & 1023);
    int b = (int)(r >> 14);
    const float* sr = s + (r << 10);
    const int* mr = mask + ((long long)b << 20) + ((long long)qq << 10);
    unsigned* dh = (unsigned*)(ph + (r << 10));
    unsigned* dl = (unsigned*)(pl + (r << 10));
    __shared__ float buf[SEQ];
    __shared__ float red[8];
    float mx = -3.0e38f;
    for (int i = threadIdx.x; i < SEQ; i += 256){
        float v = sr[i];
        if (mr[i] == 0) v = -1e9f;
        buf[i] = v;
        mx = fmaxf(mx, v);
    }
    mx = blockMax(mx, red);
    float sum = 0.f;
    for (int i = threadIdx.x; i < SEQ; i += 256){
        float e = expf(buf[i]-mx);
        buf[i] = e; sum += e;
    }
    sum = blockSum(sum, red);
    float inv = 1.f / sum;
    for (int i2 = threadIdx.x; i2 < SEQ/2; i2 += 256){
        float v0 = buf[i2*2  ] * inv;
        float v1 = buf[i2*2+1] * inv;
        unsigned h,l; split2(v0,v1,h,l);
        dh[i2] = h; dl[i2] = l;
    }
}

// ---------------- delta branch ----------------
__global__ __launch_bounds__(256) void ctx_kernel(const float* __restrict__ kd,
                                                  const float* __restrict__ vd,
                                                  float* __restrict__ ctx){
    int z = blockIdx.x; int b = z >> 4, h = z & 15;
    const float* kbase = kd + ((long long)b*SEQ)*DM + h*DK;
    const float* vbase = vd + ((long long)b*SEQ)*DM + h*DK;
    __shared__ float ks[64][65];
    __shared__ float vs[64][65];
    int tid = threadIdx.x;
    int d0 = (tid >> 4) << 2;
    int e0 = (tid & 15) << 2;
    float acc[4][4];
    #pragma unroll
    for (int i=0;i<4;i++)
        #pragma unroll
        for (int j=0;j<4;j++) acc[i][j]=0.f;

    for (int s0 = 0; s0 < SEQ; s0 += 64) {
        for (int t = tid; t < 64*16; t += 256) {
            int rr = t >> 4; int cc = (t & 15) << 2;
            float4 kv = *(const float4*)(kbase + (long long)(s0+rr)*DM + cc);
            float4 vv = *(const float4*)(vbase + (long long)(s0+rr)*DM + cc);
            ks[rr][cc+0]=kv.x; ks[rr][cc+1]=kv.y; ks[rr][cc+2]=kv.z; ks[rr][cc+3]=kv.w;
            vs[rr][cc+0]=vv.x; vs[rr][cc+1]=vv.y; vs[rr][cc+2]=vv.z; vs[rr][cc+3]=vv.w;
        }
        __syncthreads();
        #pragma unroll 4
        for (int ss=0; ss<64; ss++){
            float kr[4], vr[4];
            #pragma unroll
            for (int i=0;i<4;i++) kr[i]=ks[ss][d0+i];
            #pragma unroll
            for (int j=0;j<4;j++) vr[j]=vs[ss][e0+j];
            #pragma unroll
            for (int i=0;i<4;i++)
                #pragma unroll
                for (int j=0;j<4;j++) acc[i][j] += kr[i]*vr[j];
        }
        __syncthreads();
    }
    float* cbase = ctx + (long long)z*DK*DK;
    #pragma unroll
    for (int i=0;i<4;i++)
        #pragma unroll
        for (int j=0;j<4;j++)
            cbase[(d0+i)*DK + e0+j] = acc[i][j];
}

__global__ void ksum_kernel(const float* __restrict__ kd, float* __restrict__ ksum){
    int z = blockIdx.x; int b = z >> 4, h = z & 15;
    int d = threadIdx.x;
    const float* base = kd + ((long long)b*SEQ)*DM + h*DK + d;
    float s = 0.f;
    #pragma unroll 4
    for (int ss=0; ss<SEQ; ss++) s += fmaxf(base[(long long)ss*DM], 0.f);
    ksum[z*DK + d] = s;
}

__global__ __launch_bounds__(256) void delta_kernel(const float* __restrict__ qd,
                                                    const float* __restrict__ ctx,
                                                    const float* __restrict__ ksum,
                                                    __half* __restrict__ dh,
                                                    __half* __restrict__ dl){
    int z = blockIdx.x >> 2;
    int sc = blockIdx.x & 3;
    int b = z >> 4, h = z & 15;
    __shared__ float cs[DK*DK];
    __shared__ float kss[DK];
    for (int i = threadIdx.x; i < DK*DK; i += 256) cs[i] = ctx[(long long)z*DK*DK + i];
    if (threadIdx.x < DK) kss[threadIdx.x] = ksum[z*DK + threadIdx.x];
    __syncthreads();
    int s = sc*256 + threadIdx.x;
    const float* qrow = qd + ((long long)(b*SEQ + s))*DM + h*DK;
    float q[DK];
    #pragma unroll
    for (int d=0; d<DK; d+=4){
        float4 v = *(const float4*)(qrow + d);
        q[d+0]=fmaxf(v.x,0.f); q[d+1]=fmaxf(v.y,0.f);
        q[d+2]=fmaxf(v.z,0.f); q[d+3]=fmaxf(v.w,0.f);
    }
    float zv = 1e-6f;
    #pragma unroll
    for (int d=0; d<DK; d++) zv += q[d]*kss[d];
    float invz = 1.f / zv;
    long long obase = ((long long)(b*SEQ + s))*DM + h*DK;
    unsigned* ohp = (unsigned*)(dh + obase);
    unsigned* olp = (unsigned*)(dl + obase);
    for (int e=0; e<DK; e+=2){
        float a0 = 0.f, a1 = 0.f;
        #pragma unroll
        for (int d=0; d<DK; d++){
            a0 += q[d]*cs[d*DK + e];
            a1 += q[d]*cs[d*DK + e+1];
        }
        unsigned hh,ll; split2(a0*invz, a1*invz, hh, ll);
        ohp[e>>1] = hh; olp[e>>1] = ll;
    }
}

// ---------------- gate ----------------
__global__ __launch_bounds__(256) void gate_kernel(const float* __restrict__ xn,
                                                   const float* __restrict__ wg,
                                                   float* __restrict__ gate){
    int t = blockIdx.x;
    float p0=0.f, p1=0.f;
    for (int k = threadIdx.x; k < DM; k += 256){
        float xv = xn[(long long)t*DM + k];
        p0 += xv*wg[k*2+0];
        p1 += xv*wg[k*2+1];
    }
    __shared__ float red[8];
    p0 = blockSum(p0, red);
    p1 = blockSum(p1, red);
    if (threadIdx.x == 0){
        float m = fmaxf(p0,p1);
        float e0 = expf(p0-m), e1 = expf(p1-m);
        float inv = 1.f/(e0+e1);
        gate[t*2+0] = e0*inv;
        gate[t*2+1] = e1*inv;
    }
}

__global__ void combine1_kernel(const float* __restrict__ x,
                                const float* __restrict__ dense,
                                const float* __restrict__ delta,
                                const float* __restrict__ gate,
                                float* __restrict__ x1){
    long long i = (long long)blockIdx.x*256 + threadIdx.x;
    int t = (int)(i >> 10);
    x1[i] = x[i] + gate[t*2]*dense[i] + gate[t*2+1]*delta[i];
}

// ---------------- router ----------------
__global__ __launch_bounds__(256) void router_kernel(const float* __restrict__ xn2,
                                                     const float* __restrict__ wr,
                                                     int* __restrict__ topk_idx,
                                                     float* __restrict__ topk_w,
                                                     int* __restrict__ counts){
    int t = blockIdx.x;
    float p[NE];
    #pragma unroll
    for (int e=0;e<NE;e++) p[e]=0.f;
    for (int k = threadIdx.x; k < DM; k += 256){
        float xv = xn2[(long long)t*DM + k];
        #pragma unroll
        for (int e=0;e<NE;e++) p[e] += xv*wr[k*NE + e];
    }
    __shared__ float part[NE][8];
    int w = threadIdx.x >> 5;
    #pragma unroll
    for (int e=0;e<NE;e++){
        float v = warpSum(p[e]);
        if ((threadIdx.x & 31)==0) part[e][w] = v;
    }
    __syncthreads();
    if (threadIdx.x == 0){
        float lg[NE];
        for (int e=0;e<NE;e++){
            float s=0.f;
            for (int ww=0; ww<8; ww++) s += part[e][ww];
            lg[e]=s;
        }
        int i0=0; float v0=lg[0];
        for (int e=1;e<NE;e++) if (lg[e]>v0){v0=lg[e];i0=e;}
        int i1=-1; float v1=-3.0e38f;
        for (int e=0;e<NE;e++) if (e!=i0 && lg[e]>v1){v1=lg[e];i1=e;}
        float e1 = expf(v1-v0);
        float inv = 1.f/(1.f+e1);
        topk_idx[t*2+0]=i0; topk_idx[t*2+1]=i1;
        topk_w[t*2+0]=inv;  topk_w[t*2+1]=e1*inv;
        atomicAdd(&counts[i0],1); atomicAdd(&counts[i1],1);
    }
}

__global__ void prep_kernel(int* counts, int* cursor, int* tok){
    int i = blockIdx.x*256 + threadIdx.x;
    if (i < NE){ counts[i]=0; cursor[i]=0; }
    if (i < PAIR_CAP) tok[i]=0;
}

__global__ void scan_kernel(const int* counts, int* off, int* tile_e){
    if (threadIdx.x==0 && blockIdx.x==0){
        int o = 0;
        off[0]=0;
        for (int e=0;e<NE;e++){ o += (counts[e]+127)&~127; off[e+1]=o; }
        for (int t=0;t<NTILE72;t++){
            int row = t*128;
            int ee = NE-1;
            for (int i=0;i<NE;i++){ if (row < off[i+1]) { ee=i; break; } }
            tile_e[t]=ee;
        }
    }
}

__global__ void place_kernel(const int* __restrict__ topk_idx,
                             const int* __restrict__ off,
                             int* cursor, int* tok, int* pair_pos){
    int t = blockIdx.x*256 + threadIdx.x;
    if (t >= NTOK) return;
    for (int k=0;k<2;k++){
        int e = topk_idx[t*2+k];
        int pos = atomicAdd(&cursor[e],1);
        int r = off[e] + pos;
        tok[r] = t;
        pair_pos[t*2+k] = r;
    }
}

__global__ void final_kernel(const float* __restrict__ x1,
                             const float* __restrict__ y2,
                             const float* __restrict__ topk_w,
                             const int* __restrict__ pair_pos,
                             float* __restrict__ out){
    long long i = (long long)blockIdx.x*256 + threadIdx.x;
    int t = (int)(i >> 10);
    int c = (int)(i & 1023);
    int p0 = pair_pos[t*2+0], p1 = pair_pos[t*2+1];
    out[i] = x1[i] + topk_w[t*2+0]*y2[(long long)p0*DM + c]
                   + topk_w[t*2+1]*y2[(long long)p1*DM + c];
}

// ---------------- host side ----------------
static void gemm(const __half* Ahi, const __half* Alo,
                 const __half* Bhi, const __half* Blo,
                 float* Cf, __half* Chi, __half* Clo,
                 int M, int N, int K, int lda, int ldb, int ldc,
                 int batch, int innerN,
                 long long sAo, long long sAi, long long sBo, long long sBi,
                 long long sCo, long long sCi,
                 const int* rowIdx, const int* tileE, long long expSB,
                 float alpha, int act, int cT){
    dim3 grid((N+127)/128, (M+127)/128, batch);
    gemm_hh_kernel<<<grid, 256>>>(Ahi,Alo,Bhi,Blo,Cf,Chi,Clo,
                                  M,N,K,lda,ldb,ldc,innerN,
                                  sAo,sAi,sBo,sBi,sCo,sCi,
                                  rowIdx,tileE,expSB,alpha,act,cT);
}

extern "C" void kernel_launch(void* const* d_in, const int* in_sizes, int n_in,
                              void* d_out, int out_size){
    const float* x        = (const float*)d_in[0];
    const int*   mask     = (const int*)  d_in[1];
    const float* ln1_g    = (const float*)d_in[2];
    const float* ln1_b    = (const float*)d_in[3];
    const float* wq       = (const float*)d_in[4];
    const float* wk       = (const float*)d_in[5];
    const float* wv       = (const float*)d_in[6];
    const float* wo       = (const float*)d_in[7];
    const float* wqd      = (const float*)d_in[8];
    const float* wkd      = (const float*)d_in[9];
    const float* wvd      = (const float*)d_in[10];
    const float* wod      = (const float*)d_in[11];
    const float* w_gate   = (const float*)d_in[12];
    const float* ln2_g    = (const float*)d_in[13];
    const float* ln2_b    = (const float*)d_in[14];
    const float* w_router = (const float*)d_in[15];
    const float* e_w1     = (const float*)d_in[16];
    const float* e_w2     = (const float*)d_in[17];
    float* out = (float*)d_out;

    float *xn1,*qd,*kd,*vd,*scores,*dense_o,*delta_o,*gate,*x1,*xn2,*ctx,*ksum,*y2,*topk_w;
    int *topk_idx,*counts,*cursor,*off,*tile_e,*tok,*pair_pos;
    __half *xn1h,*xn1l,*qh,*ql,*kh,*kl,*vTh,*vTl,*ph,*pl,*acth,*actl,*dlh,*dll;
    __half *xn2h,*xn2l,*h1h,*h1l;
    __half *wT_hi,*wT_lo,*e1T_hi,*e1T_lo,*e2T_hi,*e2T_lo;

    cudaGetSymbolAddress((void**)&xn1,     g_xn1);
    cudaGetSymbolAddress((void**)&qd,      g_qd);
    cudaGetSymbolAddress((void**)&kd,      g_kd);
    cudaGetSymbolAddress((void**)&vd,      g_vd);
    cudaGetSymbolAddress((void**)&scores,  g_scores);
    cudaGetSymbolAddress((void**)&dense_o, g_dense_o);
    cudaGetSymbolAddress((void**)&delta_o, g_delta_o);
    cudaGetSymbolAddress((void**)&gate,    g_gate);
    cudaGetSymbolAddress((void**)&x1,      g_x1);
    cudaGetSymbolAddress((void**)&xn2,     g_xn2);
    cudaGetSymbolAddress((void**)&ctx,     g_ctx);
    cudaGetSymbolAddress((void**)&ksum,    g_ksum);
    cudaGetSymbolAddress((void**)&y2,      g_y2);
    cudaGetSymbolAddress((void**)&topk_w,  g_topk_w);
    cudaGetSymbolAddress((void**)&topk_idx,g_topk_idx);
    cudaGetSymbolAddress((void**)&counts,  g_counts);
    cudaGetSymbolAddress((void**)&cursor,  g_cursor);
    cudaGetSymbolAddress((void**)&off,     g_off);
    cudaGetSymbolAddress((void**)&tile_e,  g_tile_e);
    cudaGetSymbolAddress((void**)&tok,     g_tok);
    cudaGetSymbolAddress((void**)&pair_pos,g_pair_pos);
    cudaGetSymbolAddress((void**)&xn1h,    g_xn1h);
    cudaGetSymbolAddress((void**)&xn1l,    g_xn1l);
    cudaGetSymbolAddress((void**)&qh,      g_qh);
    cudaGetSymbolAddress((void**)&ql,      g_ql);
    cudaGetSymbolAddress((void**)&kh,      g_kh);
    cudaGetSymbolAddress((void**)&kl,      g_kl);
    cudaGetSymbolAddress((void**)&vTh,     g_vTh);
    cudaGetSymbolAddress((void**)&vTl,     g_vTl);
    cudaGetSymbolAddress((void**)&ph,      g_ph);
    cudaGetSymbolAddress((void**)&pl,      g_pl);
    cudaGetSymbolAddress((void**)&acth,    g_acth);
    cudaGetSymbolAddress((void**)&actl,    g_actl);
    cudaGetSymbolAddress((void**)&dlh,     g_dlh);
    cudaGetSymbolAddress((void**)&dll,     g_dll);
    cudaGetSymbolAddress((void**)&xn2h,    g_xn2h);
    cudaGetSymbolAddress((void**)&xn2l,    g_xn2l);
    cudaGetSymbolAddress((void**)&h1h,     g_h1h);
    cudaGetSymbolAddress((void**)&h1l,     g_h1l);
    cudaGetSymbolAddress((void**)&wT_hi,   g_wT_hi);
    cudaGetSymbolAddress((void**)&wT_lo,   g_wT_lo);
    cudaGetSymbolAddress((void**)&e1T_hi,  g_e1T_hi);
    cudaGetSymbolAddress((void**)&e1T_lo,  g_e1T_lo);
    cudaGetSymbolAddress((void**)&e2T_hi,  g_e2T_hi);
    cudaGetSymbolAddress((void**)&e2T_lo,  g_e2T_lo);

    const long long TOKD = (long long)SEQ*DM;

    // launch 0: all 8 dense weight splits in one grid
    WP8 wp;
    wp.p[0]=wq; wp.p[1]=wk; wp.p[2]=wv; wp.p[3]=wo;
    wp.p[4]=wqd; wp.p[5]=wkd; wp.p[6]=wvd; wp.p[7]=wod;
    wsplit8_kernel<<<dim3(32,32,8), dim3(32,8)>>>(wp, wT_hi, wT_lo);
    // launches 1-2: expert weights
    wsplit_kernel<<<dim3(DFF/32, DM/32, NE), dim3(32,8)>>>(e_w1, e1T_hi, e1T_lo, DM, DFF);
    wsplit_kernel<<<dim3(DM/32, DFF/32, NE), dim3(32,8)>>>(e_w2, e2T_hi, e2T_lo, DFF, DM);

    // launch 3: LN1 (fp32 + split)
    ln_kernel<<<NTOK,256>>>(x, ln1_g, ln1_b, xn1, xn1h, xn1l);

    // launches 4-9: projections
    gemm(xn1h,xn1l, wT_hi+0LL*WSZ,wT_lo+0LL*WSZ, 0,qh,ql,   NTOK,DM,DM, DM,DM,DM, 1,1, 0,0,0,0,0,0, 0,0,0, 1.f,0,0);
    gemm(xn1h,xn1l, wT_hi+1LL*WSZ,wT_lo+1LL*WSZ, 0,kh,kl,   NTOK,DM,DM, DM,DM,DM, 1,1, 0,0,0,0,0,0, 0,0,0, 1.f,0,0);
    gemm(xn1h,xn1l, wT_hi+2LL*WSZ,wT_lo+2LL*WSZ, 0,vTh,vTl, NTOK,DM,DM, DM,DM,NTOK, 1,1, 0,0,0,0,0,0, 0,0,0, 1.f,0,1);
    gemm(xn1h,xn1l, wT_hi+4LL*WSZ,wT_lo+4LL*WSZ, qd,0,0,    NTOK,DM,DM, DM,DM,DM, 1,1, 0,0,0,0,0,0, 0,0,0, 1.f,0,0);
    gemm(xn1h,xn1l, wT_hi+5LL*WSZ,wT_lo+5LL*WSZ, kd,0,0,    NTOK,DM,DM, DM,DM,DM, 1,1, 0,0,0,0,0,0, 0,0,0, 1.f,0,0);
    gemm(xn1h,xn1l, wT_hi+6LL*WSZ,wT_lo+6LL*WSZ, vd,0,0,    NTOK,DM,DM, DM,DM,DM, 1,1, 0,0,0,0,0,0, 0,0,0, 1.f,0,0);

    // scores = Q @ K^T / 8
    gemm(qh,ql, kh,kl, scores,0,0, SEQ,SEQ,DK, DM,DM,SEQ,
         NB*NH, NH,
         TOKD, DK,  TOKD, DK,  (long long)NH*SEQ*SEQ, (long long)SEQ*SEQ,
         0, 0, 0, 0.125f, 0, 0);

    // masked softmax -> prob halves
    softmax_kernel<<<NB*NH*SEQ, 256>>>(scores, mask, ph, pl);

    // attnctx = P @ V -> halves
    gemm(ph,pl, vTh,vTl, 0,acth,actl, SEQ,DK,SEQ, SEQ,NTOK,DM,
         NB*NH, NH,
         (long long)NH*SEQ*SEQ, (long long)SEQ*SEQ,  SEQ, (long long)DK*NTOK,
         TOKD, DK,
         0, 0, 0, 1.f, 0, 0);

    // delta branch
    ctx_kernel<<<NB*NH, 256>>>(kd, vd, ctx);
    ksum_kernel<<<NB*NH, 64>>>(kd, ksum);
    delta_kernel<<<NB*NH*4, 256>>>(qd, ctx, ksum, dlh, dll);

    // output projections
    gemm(acth,actl, wT_hi+3LL*WSZ,wT_lo+3LL*WSZ, dense_o,0,0, NTOK,DM,DM, DM,DM,DM, 1,1, 0,0,0,0,0,0, 0,0,0, 1.f,0,0);
    gemm(dlh,dll,   wT_hi+7LL*WSZ,wT_lo+7LL*WSZ, delta_o,0,0, NTOK,DM,DM, DM,DM,DM, 1,1, 0,0,0,0,0,0, 0,0,0, 1.f,0,0);

    // gate + combine
    gate_kernel<<<NTOK,256>>>(xn1, w_gate, gate);
    combine1_kernel<<<NTOK*DM/256, 256>>>(x, dense_o, delta_o, gate, x1);

    // LN2 (fp32 + split)
    ln_kernel<<<NTOK,256>>>(x1, ln2_g, ln2_b, xn2, xn2h, xn2l);

    // routing
    prep_kernel<<<(PAIR_CAP+255)/256, 256>>>(counts, cursor, tok);
    router_kernel<<<NTOK, 256>>>(xn2, w_router, topk_idx, topk_w, counts);
    scan_kernel<<<1,32>>>(counts, off, tile_e);
    place_kernel<<<(NTOK+255)/256, 256>>>(topk_idx, off, cursor, tok, pair_pos);

    // expert GEMM1 (gathered, gelu) -> h1 halves
    gemm(xn2h,xn2l, e1T_hi,e1T_lo, 0,h1h,h1l, PAIR_CAP,DFF,DM, DM,DM,DFF,
         1,1, 0,0,0,0,0,0,
         tok, tile_e, (long long)DM*DFF, 1.f, 1, 0);

    // expert GEMM2 -> y2 fp32
    gemm(h1h,h1l, e2T_hi,e2T_lo, y2,0,0, PAIR_CAP,DM,DFF, DFF,DFF,DM,
         1,1, 0,0,0,0,0,0,
         0, tile_e, (long long)DFF*DM, 1.f, 0, 0);

    // final combine
    final_kernel<<<NTOK*DM/256, 256>>>(x1, y2, topk_w, pair_pos, out);
}

// round 6
// speedup vs baseline: 2.1233x; 1.0186x over previous
#include <cuda_runtime.h>
#include <cuda_fp16.h>
#include <math.h>

// ---------------- problem constants ----------------
#define NTOK 4096              // B*S
#define DM   1024
#define DFF  2048
#define NH   16
#define DK   64
#define NB   4
#define SEQ  1024
#define NE   8
#define PAIR_CAP 9216
#define NTILE72  72
#define WSZ  (1024*1024)

// ---------------- fp32 scratch ----------------
__device__ float g_xn1[NTOK*DM];
__device__ float g_qd [NTOK*DM];
__device__ float g_kd [NTOK*DM];
__device__ float g_vd [NTOK*DM];
__device__ float g_dense_o[NTOK*DM];
__device__ float g_delta_o[NTOK*DM];
__device__ float g_gate[NTOK*2];
__device__ float g_x1 [NTOK*DM];
__device__ float g_xn2[NTOK*DM];
__device__ float g_ctx [NB*NH*DK*DK];
__device__ float g_ctxp[NB*NH*4*DK*DK];
__device__ float g_ksum[NB*NH*DK];
__device__ float g_ksump[NB*NH*8*DK];
__device__ float g_y2[(long long)PAIR_CAP*DM];
__device__ int   g_topk_idx[NTOK*2];
__device__ float g_topk_w [NTOK*2];
__device__ int   g_counts[NE];
__device__ int   g_cursor[NE];
__device__ int   g_off[NE+1];
__device__ int   g_tile_e[NTILE72];
__device__ int   g_tok[PAIR_CAP];
__device__ int   g_pair_pos[NTOK*2];

// ---------------- fp16 hi/lo scratch (k-pair permuted layout) ----------------
__device__ __half g_xn1h[NTOK*DM],  g_xn1l[NTOK*DM];
__device__ __half g_qh  [NTOK*DM],  g_ql  [NTOK*DM];
__device__ __half g_kh  [NTOK*DM],  g_kl  [NTOK*DM];
__device__ __half g_vTh [DM*NTOK],  g_vTl [DM*NTOK];
__device__ __half g_ph  [(long long)NB*NH*SEQ*SEQ], g_pl[(long long)NB*NH*SEQ*SEQ];
__device__ __half g_acth[NTOK*DM],  g_actl[NTOK*DM];
__device__ __half g_dlh [NTOK*DM],  g_dll [NTOK*DM];
__device__ __half g_xn2h[NTOK*DM],  g_xn2l[NTOK*DM];
__device__ __half g_h1h [(long long)PAIR_CAP*DFF], g_h1l[(long long)PAIR_CAP*DFF];

__device__ __half g_wT_hi[8LL*WSZ];
__device__ __half g_wT_lo[8LL*WSZ];
__device__ __half g_e1T_hi[8LL*DM*DFF];
__device__ __half g_e1T_lo[8LL*DM*DFF];
__device__ __half g_e2T_hi[8LL*DFF*DM];
__device__ __half g_e2T_lo[8LL*DFF*DM];

// ---------------- permutation helpers ----------------
// logical k-pair p (0..7 within 16-half group) -> stored word index
__device__ __forceinline__ int pperm(int p){ return ((p&3)<<1) | (p>>2); }
// stored word w -> logical pair
__device__ __forceinline__ int pinv(int w){ return (w>>1) | ((w&1)<<2); }
// remap a half index k within its 16-group
__device__ __forceinline__ int kperm(int k){
    return (k & ~15) | (pperm((k>>1)&7)<<1) | (k&1);
}
// remap a pair (word) index within its 8-group
__device__ __forceinline__ int wperm(int p){
    return (p & ~7) | pperm(p&7);
}

// ---------------- helpers ----------------
__device__ __forceinline__ void mma_f16(float* d,
        unsigned a0, unsigned a1, unsigned a2, unsigned a3,
        unsigned b0, unsigned b1){
    asm volatile("mma.sync.aligned.m16n8k16.row.col.f32.f16.f16.f32 "
        "{%0,%1,%2,%3}, {%4,%5,%6,%7}, {%8,%9}, {%0,%1,%2,%3};"
        : "+f"(d[0]),"+f"(d[1]),"+f"(d[2]),"+f"(d[3])
        : "r"(a0),"r"(a1),"r"(a2),"r"(a3),"r"(b0),"r"(b1));
}
__device__ __forceinline__ unsigned packh(__half x, __half y){
    return (unsigned)__half_as_ushort(x) | ((unsigned)__half_as_ushort(y) << 16);
}
__device__ __forceinline__ void split2(float x, float y, unsigned& hi, unsigned& lo){
    __half hx = __float2half_rn(x), hy = __float2half_rn(y);
    __half lx = __float2half_rn(x - __half2float(hx));
    __half ly = __float2half_rn(y - __half2float(hy));
    hi = packh(hx, hy);
    lo = packh(lx, ly);
}
__device__ __forceinline__ void cp16(unsigned saddr, const void* g, bool v){
    asm volatile("cp.async.ca.shared.global [%0], [%1], 16, %2;"
        :: "r"(saddr), "l"(g), "r"(v ? 16 : 0));
}

__device__ __forceinline__ float warpSum(float v){
    #pragma unroll
    for (int o=16;o;o>>=1) v += __shfl_xor_sync(0xffffffffu, v, o);
    return v;
}
__device__ __forceinline__ float warpMax(float v){
    #pragma unroll
    for (int o=16;o;o>>=1) v = fmaxf(v, __shfl_xor_sync(0xffffffffu, v, o));
    return v;
}
__device__ __forceinline__ float blockSum(float v, float* red){
    v = warpSum(v);
    if ((threadIdx.x & 31) == 0) red[threadIdx.x>>5] = v;
    __syncthreads();
    if (threadIdx.x < 32) {
        float t = (threadIdx.x < 8) ? red[threadIdx.x] : 0.f;
        t = warpSum(t);
        if (threadIdx.x == 0) red[0] = t;
    }
    __syncthreads();
    float r = red[0];
    __syncthreads();
    return r;
}
__device__ __forceinline__ float blockMax(float v, float* red){
    v = warpMax(v);
    if ((threadIdx.x & 31) == 0) red[threadIdx.x>>5] = v;
    __syncthreads();
    if (threadIdx.x < 32) {
        float t = (threadIdx.x < 8) ? red[threadIdx.x] : -3.0e38f;
        t = warpMax(t);
        if (threadIdx.x == 0) red[0] = t;
    }
    __syncthreads();
    float r = red[0];
    __syncthreads();
    return r;
}

// ---------------- weight transpose + split (permuted k) ----------------
struct WP8 { const float* p[8]; };

__global__ void wsplit8_kernel(WP8 wp, __half* __restrict__ hiB, __half* __restrict__ loB){
    __shared__ float ts[32][33];
    int mat = blockIdx.z;
    const float* W = wp.p[mat];
    __half* hi = hiB + (long long)mat*WSZ;
    __half* lo = loB + (long long)mat*WSZ;
    int k0 = blockIdx.y*32, n0 = blockIdx.x*32;
    int tx = threadIdx.x, ty = threadIdx.y;   // 32 x 8
    #pragma unroll
    for (int i=0;i<4;i++)
        ts[ty+8*i][tx] = W[(long long)(k0+ty+8*i)*DM + n0 + tx];
    __syncthreads();
    #pragma unroll
    for (int i=0;i<4;i++){
        int n = n0 + ty + 8*i, k = k0 + tx;
        float v = ts[tx][ty+8*i];
        __half h = __float2half_rn(v);
        int kp = kperm(k);
        hi[(long long)n*DM + kp] = h;
        lo[(long long)n*DM + kp] = __float2half_rn(v - __half2float(h));
    }
}

__global__ void wsplit_kernel(const float* __restrict__ W,
                              __half* __restrict__ hi, __half* __restrict__ lo,
                              int K, int N){
    __shared__ float ts[32][33];
    long long zoff = (long long)blockIdx.z * K * N;
    W  += zoff; hi += zoff; lo += zoff;
    int k0 = blockIdx.y*32, n0 = blockIdx.x*32;
    int tx = threadIdx.x, ty = threadIdx.y;
    #pragma unroll
    for (int i=0;i<4;i++)
        ts[ty+8*i][tx] = W[(long long)(k0+ty+8*i)*N + n0 + tx];
    __syncthreads();
    #pragma unroll
    for (int i=0;i<4;i++){
        int n = n0 + ty + 8*i, k = k0 + tx;
        float v = ts[tx][ty+8*i];
        __half h = __float2half_rn(v);
        int kp = kperm(k);
        hi[(long long)n*K + kp] = h;
        lo[(long long)n*K + kp] = __float2half_rn(v - __half2float(h));
    }
}

// ---------------- layernorm (fp32 out + permuted split out) ----------------
__global__ __launch_bounds__(256) void ln_kernel(const float* __restrict__ x,
                                                 const float* __restrict__ g,
                                                 const float* __restrict__ b,
                                                 float* __restrict__ y,
                                                 __half* __restrict__ yh,
                                                 __half* __restrict__ yl){
    __shared__ float row[DM];
    __shared__ float red[8];
    long long base = (long long)blockIdx.x * DM;
    float s = 0.f;
    for (int i = threadIdx.x; i < DM; i += 256) { float v = x[base+i]; row[i] = v; s += v; }
    s = blockSum(s, red);
    float mu = s * (1.f/DM);
    float vs = 0.f;
    for (int i = threadIdx.x; i < DM; i += 256) { float d = row[i]-mu; vs += d*d; }
    vs = blockSum(vs, red);
    float rstd = rsqrtf(vs * (1.f/DM) + 1e-5f);
    unsigned* oh = (unsigned*)(yh + base);
    unsigned* ol = (unsigned*)(yl + base);
    for (int i2 = threadIdx.x; i2 < DM/2; i2 += 256){
        int i = i2*2;
        float v0 = (row[i  ]-mu)*rstd*g[i  ] + b[i  ];
        float v1 = (row[i+1]-mu)*rstd*g[i+1] + b[i+1];
        if (y){ y[base+i] = v0; y[base+i+1] = v1; }
        unsigned h,l; split2(v0,v1,h,l);
        int w = wperm(i2);
        oh[w] = h; ol[w] = l;
    }
}

// ---------------- fp16x3 GEMM, permuted operands, uint2 fragments ----------------
__global__ __launch_bounds__(256,2) void gemm_hh_kernel(
    const __half* __restrict__ Ahi, const __half* __restrict__ Alo,
    const __half* __restrict__ Bhi, const __half* __restrict__ Blo,
    float* __restrict__ Cf, __half* __restrict__ Chi, __half* __restrict__ Clo,
    int M, int N, int K, int lda, int ldb, int ldc,
    int innerN,
    long long sAo, long long sAi, long long sBo, long long sBi,
    long long sCo, long long sCi,
    const int* __restrict__ rowIdx, const int* __restrict__ tileExpert,
    long long expStrideB, float alpha, int actMode, int cT)
{
    __shared__ unsigned AsH[2][128][8];
    __shared__ unsigned AsL[2][128][8];
    __shared__ unsigned BsH[2][128][8];
    __shared__ unsigned BsL[2][128][8];

    int z  = blockIdx.z;
    int zo = z / innerN, zi = z - zo*innerN;
    Ahi += zo*sAo + zi*sAi;
    Alo += zo*sAo + zi*sAi;
    long long boff = zo*sBo + zi*sBi;
    if (tileExpert) boff += (long long)tileExpert[blockIdx.y] * expStrideB;
    Bhi += boff; Blo += boff;
    long long coff = zo*sCo + zi*sCi;

    const int tm0 = blockIdx.y * 128;
    const int tn0 = blockIdx.x * 128;
    const int tid = threadIdx.x;
    const int lane = tid & 31;
    const int warp = tid >> 5;
    const int wm = (warp & 3) * 32;
    const int wn = (warp >> 2) * 64;
    const int g = lane >> 2;
    const int q = lane & 3;

    // loaders: 2 threads/row, each copies 8 consecutive (permuted) halves
    const int lrow = tid >> 1;
    const int lsel = tid & 1;
    const int loff = lsel * 8;

    int grow = tm0 + lrow;
    bool aval = grow < M;
    int srcRow = aval ? (rowIdx ? (rowIdx[grow] & (NTOK-1)) : grow) : 0;
    const __half* AhiP = Ahi + (long long)srcRow * lda + loff;
    const __half* AloP = Alo + (long long)srcRow * lda + loff;
    bool bval = (tn0 + lrow) < N;
    int brow = bval ? (tn0 + lrow) : 0;
    const __half* BhiP = Bhi + (long long)brow * ldb + loff;
    const __half* BloP = Blo + (long long)brow * ldb + loff;

    unsigned base_off = (unsigned)((lrow*8 + lsel*4)*4);
    unsigned aH0 = (unsigned)__cvta_generic_to_shared(&AsH[0][0][0]) + base_off;
    unsigned aL0 = (unsigned)__cvta_generic_to_shared(&AsL[0][0][0]) + base_off;
    unsigned bH0 = (unsigned)__cvta_generic_to_shared(&BsH[0][0][0]) + base_off;
    unsigned bL0 = (unsigned)__cvta_generic_to_shared(&BsL[0][0][0]) + base_off;

    float acc[2][8][4];
    #pragma unroll
    for (int mi=0;mi<2;mi++)
        #pragma unroll
        for (int ni=0;ni<8;ni++)
            #pragma unroll
            for (int t=0;t<4;t++) acc[mi][ni][t]=0.f;

    // prologue: tile 0
    cp16(aH0, AhiP, aval);
    cp16(aL0, AloP, aval);
    cp16(bH0, BhiP, bval);
    cp16(bL0, BloP, bval);
    asm volatile("cp.async.commit_group;");
    asm volatile("cp.async.wait_group 0;");
    __syncthreads();

    int buf = 0;
    for (int k0 = 0; k0 < K; k0 += 16){
        bool has = (k0 + 16) < K;
        if (has){
            int kn = k0 + 16;
            unsigned bo = (buf^1) * 4096u;
            cp16(aH0 + bo, AhiP + kn, aval);
            cp16(aL0 + bo, AloP + kn, aval);
            cp16(bH0 + bo, BhiP + kn, bval);
            cp16(bL0 + bo, BloP + kn, bval);
            asm volatile("cp.async.commit_group;");
        }

        // compute on buf: fragments via uint2 (permuted pairs are adjacent)
        {
            uint2 ah[2][2], al[2][2];   // [mi][row 0/+8] = {k-pair q, q+4}
            #pragma unroll
            for (int mi = 0; mi < 2; mi++){
                int row = wm + mi*16 + g;
                ah[mi][0] = *(const uint2*)&AsH[buf][row  ][2*q];
                ah[mi][1] = *(const uint2*)&AsH[buf][row+8][2*q];
                al[mi][0] = *(const uint2*)&AsL[buf][row  ][2*q];
                al[mi][1] = *(const uint2*)&AsL[buf][row+8][2*q];
            }
            #pragma unroll
            for (int ni = 0; ni < 8; ni++){
                int col = wn + ni*8 + g;
                uint2 bh = *(const uint2*)&BsH[buf][col][2*q];
                uint2 bl = *(const uint2*)&BsL[buf][col][2*q];
                #pragma unroll
                for (int mi = 0; mi < 2; mi++){
                    mma_f16(acc[mi][ni], ah[mi][0].x, ah[mi][1].x, ah[mi][0].y, ah[mi][1].y, bh.x, bh.y);
                    mma_f16(acc[mi][ni], ah[mi][0].x, ah[mi][1].x, ah[mi][0].y, ah[mi][1].y, bl.x, bl.y);
                    mma_f16(acc[mi][ni], al[mi][0].x, al[mi][1].x, al[mi][0].y, al[mi][1].y, bh.x, bh.y);
                }
            }
        }

        if (has){
            asm volatile("cp.async.wait_group 0;");
            __syncthreads();
            buf ^= 1;
        }
    }

    // epilogue
    float* CfP = Cf ? (Cf + coff) : (float*)0;
    __half* ChiP = Chi ? (Chi + coff) : (__half*)0;
    __half* CloP = Clo ? (Clo + coff) : (__half*)0;
    #pragma unroll
    for (int mi = 0; mi < 2; mi++){
        #pragma unroll
        for (int rr = 0; rr < 2; rr++){
            int row = tm0 + wm + mi*16 + g + rr*8;
            if (row >= M) continue;
            #pragma unroll
            for (int ni = 0; ni < 8; ni++){
                int col = tn0 + wn + ni*8 + q*2;
                if (col >= N) continue;
                float v0 = acc[mi][ni][rr*2+0] * alpha;
                float v1 = acc[mi][ni][rr*2+1] * alpha;
                if (actMode == 1){
                    v0 = 0.5f * v0 * (1.f + erff(v0 * 0.70710678118654752f));
                    v1 = 0.5f * v1 * (1.f + erff(v1 * 0.70710678118654752f));
                }
                if (!cT){
                    long long prow = (long long)row * ldc;
                    if (CfP) *(float2*)&CfP[prow + col] = make_float2(v0, v1);
                    if (ChiP){
                        unsigned h,l; split2(v0,v1,h,l);
                        int pcol = (col & ~15) | (pperm((col>>1)&7)<<1);
                        *(unsigned*)&ChiP[prow + pcol] = h;
                        *(unsigned*)&CloP[prow + pcol] = l;
                    }
                } else {
                    if (CfP){
                        CfP[(long long)(col  ) * ldc + row] = v0;
                        if (col + 1 < N) CfP[(long long)(col+1) * ldc + row] = v1;
                    }
                    if (ChiP){
                        int rowp = kperm(row);
                        __half h0 = __float2half_rn(v0);
                        ChiP[(long long)(col) * ldc + rowp] = h0;
                        CloP[(long long)(col) * ldc + rowp] = __float2half_rn(v0 - __half2float(h0));
                        if (col + 1 < N){
                            __half h1v = __float2half_rn(v1);
                            ChiP[(long long)(col+1) * ldc + rowp] = h1v;
                            CloP[(long long)(col+1) * ldc + rowp] = __float2half_rn(v1 - __half2float(h1v));
                        }
                    }
                }
            }
        }
    }
}

// ---------------- masked row softmax on permuted hi/lo halves (in place) ----------------
__global__ __launch_bounds__(256) void softmax_kernel(const int* __restrict__ mask,
                                                      __half* __restrict__ ph,
                                                      __half* __restrict__ pl){
    long long r = blockIdx.x;
    int qq = (int)(r & 1023);
    int b = (int)(r >> 14);
    const int* mr = mask + ((long long)b << 20) + ((long long)qq << 10);
    unsigned* dh = (unsigned*)(ph + (r << 10));
    unsigned* dl = (unsigned*)(pl + (r << 10));
    __shared__ float buf[SEQ];
    __shared__ float red[8];
    float mx = -3.0e38f;
    for (int i2 = threadIdx.x; i2 < SEQ/2; i2 += 256){
        int lp = (i2 & ~7) | pinv(i2 & 7);      // logical pair index
        __half2 hv = *(__half2*)&dh[i2];
        __half2 lv = *(__half2*)&dl[i2];
        float v0 = __half2float(hv.x) + __half2float(lv.x);
        float v1 = __half2float(hv.y) + __half2float(lv.y);
        if (mr[2*lp  ] == 0) v0 = -1e9f;
        if (mr[2*lp+1] == 0) v1 = -1e9f;
        buf[2*lp  ] = v0;
        buf[2*lp+1] = v1;
        mx = fmaxf(mx, fmaxf(v0, v1));
    }
    mx = blockMax(mx, red);
    float sum = 0.f;
    for (int i = threadIdx.x; i < SEQ; i += 256){
        float e = expf(buf[i]-mx);
        buf[i] = e; sum += e;
    }
    sum = blockSum(sum, red);
    float inv = 1.f / sum;
    for (int i2 = threadIdx.x; i2 < SEQ/2; i2 += 256){
        int lp = (i2 & ~7) | pinv(i2 & 7);
        unsigned h,l; split2(buf[2*lp]*inv, buf[2*lp+1]*inv, h, l);
        dh[i2] = h; dl[i2] = l;
    }
}

// ---------------- delta branch (2-stage ctx / ksum) ----------------
__global__ __launch_bounds__(256) void ctx1_kernel(const float* __restrict__ kd,
                                                   const float* __restrict__ vd,
                                                   float* __restrict__ ctxp){
    int z = blockIdx.x >> 2;         // 0..63
    int chunk = blockIdx.x & 3;      // 256 seq rows each
    int b = z >> 4, h = z & 15;
    const float* kbase = kd + ((long long)b*SEQ)*DM + h*DK;
    const float* vbase = vd + ((long long)b*SEQ)*DM + h*DK;
    __shared__ float ks[64][65];
    __shared__ float vs[64][65];
    int tid = threadIdx.x;
    int d0 = (tid >> 4) << 2;
    int e0 = (tid & 15) << 2;
    float acc[4][4];
    #pragma unroll
    for (int i=0;i<4;i++)
        #pragma unroll
        for (int j=0;j<4;j++) acc[i][j]=0.f;

    for (int s0 = chunk*256; s0 < chunk*256+256; s0 += 64) {
        for (int t = tid; t < 64*16; t += 256) {
            int rr = t >> 4; int cc = (t & 15) << 2;
            float4 kv = *(const float4*)(kbase + (long long)(s0+rr)*DM + cc);
            float4 vv = *(const float4*)(vbase + (long long)(s0+rr)*DM + cc);
            ks[rr][cc+0]=kv.x; ks[rr][cc+1]=kv.y; ks[rr][cc+2]=kv.z; ks[rr][cc+3]=kv.w;
            vs[rr][cc+0]=vv.x; vs[rr][cc+1]=vv.y; vs[rr][cc+2]=vv.z; vs[rr][cc+3]=vv.w;
        }
        __syncthreads();
        #pragma unroll 4
        for (int ss=0; ss<64; ss++){
            float kr[4], vr[4];
            #pragma unroll
            for (int i=0;i<4;i++) kr[i]=ks[ss][d0+i];
            #pragma unroll
            for (int j=0;j<4;j++) vr[j]=vs[ss][e0+j];
            #pragma unroll
            for (int i=0;i<4;i++)
                #pragma unroll
                for (int j=0;j<4;j++) acc[i][j] += kr[i]*vr[j];
        }
        __syncthreads();
    }
    float* cbase = ctxp + ((long long)z*4 + chunk)*DK*DK;
    #pragma unroll
    for (int i=0;i<4;i++)
        #pragma unroll
        for (int j=0;j<4;j++)
            cbase[(d0+i)*DK + e0+j] = acc[i][j];
}

__global__ void ctx2_kernel(const float* __restrict__ ctxp, float* __restrict__ ctx){
    int z = blockIdx.x;
    const float* p = ctxp + (long long)z*4*DK*DK;
    float* o = ctx + (long long)z*DK*DK;
    for (int i = threadIdx.x; i < DK*DK; i += 256)
        o[i] = p[i] + p[DK*DK + i] + p[2*DK*DK + i] + p[3*DK*DK + i];
}

__global__ void ksum1_kernel(const float* __restrict__ kd, float* __restrict__ ksump){
    int z = blockIdx.x >> 3;
    int c = blockIdx.x & 7;
    int b = z >> 4, h = z & 15;
    int d = threadIdx.x;
    const float* base = kd + ((long long)(b*SEQ + c*128))*DM + h*DK + d;
    float s = 0.f;
    #pragma unroll 4
    for (int ss=0; ss<128; ss++) s += fmaxf(base[(long long)ss*DM], 0.f);
    ksump[(z*8 + c)*DK + d] = s;
}

__global__ void ksum2_kernel(const float* __restrict__ ksump, float* __restrict__ ksum){
    int z = blockIdx.x;
    int d = threadIdx.x;
    float s = 0.f;
    #pragma unroll
    for (int c=0;c<8;c++) s += ksump[(z*8 + c)*DK + d];
    ksum[z*DK + d] = s;
}

__global__ __launch_bounds__(256) void delta_kernel(const float* __restrict__ qd,
                                                    const float* __restrict__ ctx,
                                                    const float* __restrict__ ksum,
                                                    __half* __restrict__ dh,
                                                    __half* __restrict__ dl){
    int z = blockIdx.x >> 2;
    int sc = blockIdx.x & 3;
    int b = z >> 4, h = z & 15;
    __shared__ float cs[DK*DK];
    __shared__ float kss[DK];
    for (int i = threadIdx.x; i < DK*DK; i += 256) cs[i] = ctx[(long long)z*DK*DK + i];
    if (threadIdx.x < DK) kss[threadIdx.x] = ksum[z*DK + threadIdx.x];
    __syncthreads();
    int s = sc*256 + threadIdx.x;
    const float* qrow = qd + ((long long)(b*SEQ + s))*DM + h*DK;
    float q[DK];
    #pragma unroll
    for (int d=0; d<DK; d+=4){
        float4 v = *(const float4*)(qrow + d);
        q[d+0]=fmaxf(v.x,0.f); q[d+1]=fmaxf(v.y,0.f);
        q[d+2]=fmaxf(v.z,0.f); q[d+3]=fmaxf(v.w,0.f);
    }
    float zv = 1e-6f;
    #pragma unroll
    for (int d=0; d<DK; d++) zv += q[d]*kss[d];
    float invz = 1.f / zv;
    long long obase = ((long long)(b*SEQ + s))*DM + h*DK;
    unsigned* ohp = (unsigned*)(dh + obase);
    unsigned* olp = (unsigned*)(dl + obase);
    for (int e=0; e<DK; e+=2){
        float a0 = 0.f, a1 = 0.f;
        #pragma unroll
        for (int d=0; d<DK; d++){
            a0 += q[d]*cs[d*DK + e];
            a1 += q[d]*cs[d*DK + e+1];
        }
        unsigned hh,ll; split2(a0*invz, a1*invz, hh, ll);
        int w = wperm(e>>1);
        ohp[w] = hh; olp[w] = ll;
    }
}

// ---------------- gate ----------------
__global__ __launch_bounds__(256) void gate_kernel(const float* __restrict__ xn,
                                                   const float* __restrict__ wg,
                                                   float* __restrict__ gate){
    int t = blockIdx.x;
    float p0=0.f, p1=0.f;
    for (int k = threadIdx.x; k < DM; k += 256){
        float xv = xn[(long long)t*DM + k];
        p0 += xv*wg[k*2+0];
        p1 += xv*wg[k*2+1];
    }
    __shared__ float red[8];
    p0 = blockSum(p0, red);
    p1 = blockSum(p1, red);
    if (threadIdx.x == 0){
        float m = fmaxf(p0,p1);
        float e0 = expf(p0-m), e1 = expf(p1-m);
        float inv = 1.f/(e0+e1);
        gate[t*2+0] = e0*inv;
        gate[t*2+1] = e1*inv;
    }
}

__global__ void combine1_kernel(const float* __restrict__ x,
                                const float* __restrict__ dense,
                                const float* __restrict__ delta,
                                const float* __restrict__ gate,
                                float* __restrict__ x1){
    long long i = (long long)blockIdx.x*256 + threadIdx.x;
    int t = (int)(i >> 10);
    x1[i] = x[i] + gate[t*2]*dense[i] + gate[t*2+1]*delta[i];
}

// ---------------- router ----------------
__global__ __launch_bounds__(256) void router_kernel(const float* __restrict__ xn2,
                                                     const float* __restrict__ wr,
                                                     int* __restrict__ topk_idx,
                                                     float* __restrict__ topk_w,
                                                     int* __restrict__ counts){
    int t = blockIdx.x;
    float p[NE];
    #pragma unroll
    for (int e=0;e<NE;e++) p[e]=0.f;
    for (int k = threadIdx.x; k < DM; k += 256){
        float xv = xn2[(long long)t*DM + k];
        #pragma unroll
        for (int e=0;e<NE;e++) p[e] += xv*wr[k*NE + e];
    }
    __shared__ float part[NE][8];
    int w = threadIdx.x >> 5;
    #pragma unroll
    for (int e=0;e<NE;e++){
        float v = warpSum(p[e]);
        if ((threadIdx.x & 31)==0) part[e][w] = v;
    }
    __syncthreads();
    if (threadIdx.x == 0){
        float lg[NE];
        for (int e=0;e<NE;e++){
            float s=0.f;
            for (int ww=0; ww<8; ww++) s += part[e][ww];
            lg[e]=s;
        }
        int i0=0; float v0=lg[0];
        for (int e=1;e<NE;e++) if (lg[e]>v0){v0=lg[e];i0=e;}
        int i1=-1; float v1=-3.0e38f;
        for (int e=0;e<NE;e++) if (e!=i0 && lg[e]>v1){v1=lg[e];i1=e;}
        float e1 = expf(v1-v0);
        float inv = 1.f/(1.f+e1);
        topk_idx[t*2+0]=i0; topk_idx[t*2+1]=i1;
        topk_w[t*2+0]=inv;  topk_w[t*2+1]=e1*inv;
        atomicAdd(&counts[i0],1); atomicAdd(&counts[i1],1);
    }
}

__global__ void prep_kernel(int* counts, int* cursor, int* tok){
    int i = blockIdx.x*256 + threadIdx.x;
    if (i < NE){ counts[i]=0; cursor[i]=0; }
    if (i < PAIR_CAP) tok[i]=0;
}

__global__ void scan_kernel(const int* counts, int* off, int* tile_e){
    if (threadIdx.x==0 && blockIdx.x==0){
        int o = 0;
        off[0]=0;
        for (int e=0;e<NE;e++){ o += (counts[e]+127)&~127; off[e+1]=o; }
        for (int t=0;t<NTILE72;t++){
            int row = t*128;
            int ee = NE-1;
            for (int i=0;i<NE;i++){ if (row < off[i+1]) { ee=i; break; } }
            tile_e[t]=ee;
        }
    }
}

__global__ void place_kernel(const int* __restrict__ topk_idx,
                             const int* __restrict__ off,
                             int* cursor, int* tok, int* pair_pos){
    int t = blockIdx.x*256 + threadIdx.x;
    if (t >= NTOK) return;
    for (int k=0;k<2;k++){
        int e = topk_idx[t*2+k];
        int pos = atomicAdd(&cursor[e],1);
        int r = off[e] + pos;
        tok[r] = t;
        pair_pos[t*2+k] = r;
    }
}

__global__ void final_kernel(const float* __restrict__ x1,
                             const float* __restrict__ y2,
                             const float* __restrict__ topk_w,
                             const int* __restrict__ pair_pos,
                             float* __restrict__ out){
    long long i = (long long)blockIdx.x*256 + threadIdx.x;
    int t = (int)(i >> 10);
    int c = (int)(i & 1023);
    int p0 = pair_pos[t*2+0], p1 = pair_pos[t*2+1];
    out[i] = x1[i] + topk_w[t*2+0]*y2[(long long)p0*DM + c]
                   + topk_w[t*2+1]*y2[(long long)p1*DM + c];
}

// ---------------- host side ----------------
static void gemm(const __half* Ahi, const __half* Alo,
                 const __half* Bhi, const __half* Blo,
                 float* Cf, __half* Chi, __half* Clo,
                 int M, int N, int K, int lda, int ldb, int ldc,
                 int batch, int innerN,
                 long long sAo, long long sAi, long long sBo, long long sBi,
                 long long sCo, long long sCi,
                 const int* rowIdx, const int* tileE, long long expSB,
                 float alpha, int act, int cT){
    dim3 grid((N+127)/128, (M+127)/128, batch);
    gemm_hh_kernel<<<grid, 256>>>(Ahi,Alo,Bhi,Blo,Cf,Chi,Clo,
                                  M,N,K,lda,ldb,ldc,innerN,
                                  sAo,sAi,sBo,sBi,sCo,sCi,
                                  rowIdx,tileE,expSB,alpha,act,cT);
}

extern "C" void kernel_launch(void* const* d_in, const int* in_sizes, int n_in,
                              void* d_out, int out_size){
    const float* x        = (const float*)d_in[0];
    const int*   mask     = (const int*)  d_in[1];
    const float* ln1_g    = (const float*)d_in[2];
    const float* ln1_b    = (const float*)d_in[3];
    const float* wq       = (const float*)d_in[4];
    const float* wk       = (const float*)d_in[5];
    const float* wv       = (const float*)d_in[6];
    const float* wo       = (const float*)d_in[7];
    const float* wqd      = (const float*)d_in[8];
    const float* wkd      = (const float*)d_in[9];
    const float* wvd      = (const float*)d_in[10];
    const float* wod      = (const float*)d_in[11];
    const float* w_gate   = (const float*)d_in[12];
    const float* ln2_g    = (const float*)d_in[13];
    const float* ln2_b    = (const float*)d_in[14];
    const float* w_router = (const float*)d_in[15];
    const float* e_w1     = (const float*)d_in[16];
    const float* e_w2     = (const float*)d_in[17];
    float* out = (float*)d_out;

    float *xn1,*qd,*kd,*vd,*dense_o,*delta_o,*gate,*x1,*xn2,*ctx,*ctxp,*ksum,*ksump,*y2,*topk_w;
    int *topk_idx,*counts,*cursor,*off,*tile_e,*tok,*pair_pos;
    __half *xn1h,*xn1l,*qh,*ql,*kh,*kl,*vTh,*vTl,*ph,*pl,*acth,*actl,*dlh,*dll;
    __half *xn2h,*xn2l,*h1h,*h1l;
    __half *wT_hi,*wT_lo,*e1T_hi,*e1T_lo,*e2T_hi,*e2T_lo;

    cudaGetSymbolAddress((void**)&xn1,     g_xn1);
    cudaGetSymbolAddress((void**)&qd,      g_qd);
    cudaGetSymbolAddress((void**)&kd,      g_kd);
    cudaGetSymbolAddress((void**)&vd,      g_vd);
    cudaGetSymbolAddress((void**)&dense_o, g_dense_o);
    cudaGetSymbolAddress((void**)&delta_o, g_delta_o);
    cudaGetSymbolAddress((void**)&gate,    g_gate);
    cudaGetSymbolAddress((void**)&x1,      g_x1);
    cudaGetSymbolAddress((void**)&xn2,     g_xn2);
    cudaGetSymbolAddress((void**)&ctx,     g_ctx);
    cudaGetSymbolAddress((void**)&ctxp,    g_ctxp);
    cudaGetSymbolAddress((void**)&ksum,    g_ksum);
    cudaGetSymbolAddress((void**)&ksump,   g_ksump);
    cudaGetSymbolAddress((void**)&y2,      g_y2);
    cudaGetSymbolAddress((void**)&topk_w,  g_topk_w);
    cudaGetSymbolAddress((void**)&topk_idx,g_topk_idx);
    cudaGetSymbolAddress((void**)&counts,  g_counts);
    cudaGetSymbolAddress((void**)&cursor,  g_cursor);
    cudaGetSymbolAddress((void**)&off,     g_off);
    cudaGetSymbolAddress((void**)&tile_e,  g_tile_e);
    cudaGetSymbolAddress((void**)&tok,     g_tok);
    cudaGetSymbolAddress((void**)&pair_pos,g_pair_pos);
    cudaGetSymbolAddress((void**)&xn1h,    g_xn1h);
    cudaGetSymbolAddress((void**)&xn1l,    g_xn1l);
    cudaGetSymbolAddress((void**)&qh,      g_qh);
    cudaGetSymbolAddress((void**)&ql,      g_ql);
    cudaGetSymbolAddress((void**)&kh,      g_kh);
    cudaGetSymbolAddress((void**)&kl,      g_kl);
    cudaGetSymbolAddress((void**)&vTh,     g_vTh);
    cudaGetSymbolAddress((void**)&vTl,     g_vTl);
    cudaGetSymbolAddress((void**)&ph,      g_ph);
    cudaGetSymbolAddress((void**)&pl,      g_pl);
    cudaGetSymbolAddress((void**)&acth,    g_acth);
    cudaGetSymbolAddress((void**)&actl,    g_actl);
    cudaGetSymbolAddress((void**)&dlh,     g_dlh);
    cudaGetSymbolAddress((void**)&dll,     g_dll);
    cudaGetSymbolAddress((void**)&xn2h,    g_xn2h);
    cudaGetSymbolAddress((void**)&xn2l,    g_xn2l);
    cudaGetSymbolAddress((void**)&h1h,     g_h1h);
    cudaGetSymbolAddress((void**)&h1l,     g_h1l);
    cudaGetSymbolAddress((void**)&wT_hi,   g_wT_hi);
    cudaGetSymbolAddress((void**)&wT_lo,   g_wT_lo);
    cudaGetSymbolAddress((void**)&e1T_hi,  g_e1T_hi);
    cudaGetSymbolAddress((void**)&e1T_lo,  g_e1T_lo);
    cudaGetSymbolAddress((void**)&e2T_hi,  g_e2T_hi);
    cudaGetSymbolAddress((void**)&e2T_lo,  g_e2T_lo);

    const long long TOKD = (long long)SEQ*DM;

    // 0: LN1 (needs only x)
    ln_kernel<<<NTOK,256>>>(x, ln1_g, ln1_b, xn1, xn1h, xn1l);
    // 1: dense weight splits
    WP8 wp;
    wp.p[0]=wq; wp.p[1]=wk; wp.p[2]=wv; wp.p[3]=wo;
    wp.p[4]=wqd; wp.p[5]=wkd; wp.p[6]=wvd; wp.p[7]=wod;
    wsplit8_kernel<<<dim3(32,32,8), dim3(32,8)>>>(wp, wT_hi, wT_lo);
    // 2: expert w1 split
    wsplit_kernel<<<dim3(DFF/32, DM/32, NE), dim3(32,8)>>>(e_w1, e1T_hi, e1T_lo, DM, DFF);

    // 3: q projection GEMM  <-- ncu sample target
    gemm(xn1h,xn1l, wT_hi+0LL*WSZ,wT_lo+0LL*WSZ, 0,qh,ql,   NTOK,DM,DM, DM,DM,DM, 1,1, 0,0,0,0,0,0, 0,0,0, 1.f,0,0);
    gemm(xn1h,xn1l, wT_hi+1LL*WSZ,wT_lo+1LL*WSZ, 0,kh,kl,   NTOK,DM,DM, DM,DM,DM, 1,1, 0,0,0,0,0,0, 0,0,0, 1.f,0,0);
    gemm(xn1h,xn1l, wT_hi+2LL*WSZ,wT_lo+2LL*WSZ, 0,vTh,vTl, NTOK,DM,DM, DM,DM,NTOK, 1,1, 0,0,0,0,0,0, 0,0,0, 1.f,0,1);
    gemm(xn1h,xn1l, wT_hi+4LL*WSZ,wT_lo+4LL*WSZ, qd,0,0,    NTOK,DM,DM, DM,DM,DM, 1,1, 0,0,0,0,0,0, 0,0,0, 1.f,0,0);
    gemm(xn1h,xn1l, wT_hi+5LL*WSZ,wT_lo+5LL*WSZ, kd,0,0,    NTOK,DM,DM, DM,DM,DM, 1,1, 0,0,0,0,0,0, 0,0,0, 1.f,0,0);
    gemm(xn1h,xn1l, wT_hi+6LL*WSZ,wT_lo+6LL*WSZ, vd,0,0,    NTOK,DM,DM, DM,DM,DM, 1,1, 0,0,0,0,0,0, 0,0,0, 1.f,0,0);

    // scores = Q @ K^T / 8 -> permuted hi/lo halves (no fp32 materialization)
    gemm(qh,ql, kh,kl, 0,ph,pl, SEQ,SEQ,DK, DM,DM,SEQ,
         NB*NH, NH,
         TOKD, DK,  TOKD, DK,  (long long)NH*SEQ*SEQ, (long long)SEQ*SEQ,
         0, 0, 0, 0.125f, 0, 0);

    // masked softmax in place on halves
    softmax_kernel<<<NB*NH*SEQ, 256>>>(mask, ph, pl);

    // attnctx = P @ V -> halves
    gemm(ph,pl, vTh,vTl, 0,acth,actl, SEQ,DK,SEQ, SEQ,NTOK,DM,
         NB*NH, NH,
         (long long)NH*SEQ*SEQ, (long long)SEQ*SEQ,  SEQ, (long long)DK*NTOK,
         TOKD, DK,
         0, 0, 0, 1.f, 0, 0);

    // delta branch (2-stage)
    ctx1_kernel<<<NB*NH*4, 256>>>(kd, vd, ctxp);
    ctx2_kernel<<<NB*NH, 256>>>(ctxp, ctx);
    ksum1_kernel<<<NB*NH*8, 64>>>(kd, ksump);
    ksum2_kernel<<<NB*NH, 64>>>(ksump, ksum);
    delta_kernel<<<NB*NH*4, 256>>>(qd, ctx, ksum, dlh, dll);

    // output projections
    gemm(acth,actl, wT_hi+3LL*WSZ,wT_lo+3LL*WSZ, dense_o,0,0, NTOK,DM,DM, DM,DM,DM, 1,1, 0,0,0,0,0,0, 0,0,0, 1.f,0,0);
    gemm(dlh,dll,   wT_hi+7LL*WSZ,wT_lo+7LL*WSZ, delta_o,0,0, NTOK,DM,DM, DM,DM,DM, 1,1, 0,0,0,0,0,0, 0,0,0, 1.f,0,0);

    // gate + combine
    gate_kernel<<<NTOK,256>>>(xn1, w_gate, gate);
    combine1_kernel<<<NTOK*DM/256, 256>>>(x, dense_o, delta_o, gate, x1);

    // LN2
    ln_kernel<<<NTOK,256>>>(x1, ln2_g, ln2_b, xn2, xn2h, xn2l);

    // routing
    prep_kernel<<<(PAIR_CAP+255)/256, 256>>>(counts, cursor, tok);
    router_kernel<<<NTOK, 256>>>(xn2, w_router, topk_idx, topk_w, counts);
    scan_kernel<<<1,32>>>(counts, off, tile_e);
    place_kernel<<<(NTOK+255)/256, 256>>>(topk_idx, off, cursor, tok, pair_pos);

    // expert w2 split (needed only by gemm2)
    wsplit_kernel<<<dim3(DM/32, DFF/32, NE), dim3(32,8)>>>(e_w2, e2T_hi, e2T_lo, DFF, DM);

    // expert GEMM1 (gathered, gelu) -> h1 halves
    gemm(xn2h,xn2l, e1T_hi,e1T_lo, 0,h1h,h1l, PAIR_CAP,DFF,DM, DM,DM,DFF,
         1,1, 0,0,0,0,0,0,
         tok, tile_e, (long long)DM*DFF, 1.f, 1, 0);

    // expert GEMM2 -> y2 fp32
    gemm(h1h,h1l, e2T_hi,e2T_lo, y2,0,0, PAIR_CAP,DM,DFF, DFF,DFF,DM,
         1,1, 0,0,0,0,0,0,
         0, tile_e, (long long)DFF*DM, 1.f, 0, 0);

    // final combine
    final_kernel<<<NTOK*DM/256, 256>>>(x1, y2, topk_w, pair_pos, out);
}

// round 7
// speedup vs baseline: 2.2592x; 1.0640x over previous
#include <cuda_runtime.h>
#include <cuda_fp16.h>
#include <math.h>

// ---------------- problem constants ----------------
#define NTOK 4096              // B*S
#define DM   1024
#define DFF  2048
#define NH   16
#define DK   64
#define NB   4
#define SEQ  1024
#define NE   8
#define PAIR_CAP 9216
#define NTILE72  72
#define WSZ  (1024*1024)

// ---------------- fp32 scratch ----------------
__device__ float g_xn1[NTOK*DM];
__device__ float g_qd [NTOK*DM];
__device__ float g_kd [NTOK*DM];
__device__ float g_vd [NTOK*DM];
__device__ float g_dense_o[NTOK*DM];
__device__ float g_delta_o[NTOK*DM];
__device__ float g_gate[NTOK*2];
__device__ float g_x1 [NTOK*DM];
__device__ float g_xn2[NTOK*DM];
__device__ float g_ctx [NB*NH*DK*DK];
__device__ float g_ctxp[NB*NH*4*DK*DK];
__device__ float g_ksum[NB*NH*DK];
__device__ float g_ksump[NB*NH*8*DK];
__device__ float g_y2[(long long)PAIR_CAP*DM];
__device__ int   g_topk_idx[NTOK*2];
__device__ float g_topk_w [NTOK*2];
__device__ int   g_counts[NE];
__device__ int   g_cursor[NE];
__device__ int   g_off[NE+1];
__device__ int   g_tile_e[NTILE72];
__device__ int   g_tok[PAIR_CAP];
__device__ int   g_pair_pos[NTOK*2];

// ---------------- fp16 hi/lo scratch (k-pair permuted layout) ----------------
__device__ __half g_xn1h[NTOK*DM],  g_xn1l[NTOK*DM];
__device__ __half g_qh  [NTOK*DM],  g_ql  [NTOK*DM];
__device__ __half g_kh  [NTOK*DM],  g_kl  [NTOK*DM];
__device__ __half g_vTh [DM*NTOK],  g_vTl [DM*NTOK];
__device__ __half g_ph  [(long long)NB*NH*SEQ*SEQ], g_pl[(long long)NB*NH*SEQ*SEQ];
__device__ __half g_acth[NTOK*DM],  g_actl[NTOK*DM];
__device__ __half g_dlh [NTOK*DM],  g_dll [NTOK*DM];
__device__ __half g_xn2h[NTOK*DM],  g_xn2l[NTOK*DM];
__device__ __half g_h1h [(long long)PAIR_CAP*DFF], g_h1l[(long long)PAIR_CAP*DFF];

__device__ __half g_wT_hi[8LL*WSZ];
__device__ __half g_wT_lo[8LL*WSZ];
__device__ __half g_e1T_hi[8LL*DM*DFF];
__device__ __half g_e1T_lo[8LL*DM*DFF];
__device__ __half g_e2T_hi[8LL*DFF*DM];
__device__ __half g_e2T_lo[8LL*DFF*DM];

// ---------------- multi-output descriptor (batched projections) ----------------
struct MD {
    const __half* ah[6];
    const __half* al[6];
    float*  f[6];
    __half* h[6];
    __half* l[6];
    int ldc[6];
    int cT[6];
};

// ---------------- permutation helpers ----------------
__device__ __forceinline__ int pperm(int p){ return ((p&3)<<1) | (p>>2); }
__device__ __forceinline__ int pinv(int w){ return (w>>1) | ((w&1)<<2); }
__device__ __forceinline__ int kperm(int k){
    return (k & ~15) | (pperm((k>>1)&7)<<1) | (k&1);
}
__device__ __forceinline__ int wperm(int p){
    return (p & ~7) | pperm(p&7);
}

// ---------------- helpers ----------------
__device__ __forceinline__ void mma_f16(float* d,
        unsigned a0, unsigned a1, unsigned a2, unsigned a3,
        unsigned b0, unsigned b1){
    asm volatile("mma.sync.aligned.m16n8k16.row.col.f32.f16.f16.f32 "
        "{%0,%1,%2,%3}, {%4,%5,%6,%7}, {%8,%9}, {%0,%1,%2,%3};"
        : "+f"(d[0]),"+f"(d[1]),"+f"(d[2]),"+f"(d[3])
        : "r"(a0),"r"(a1),"r"(a2),"r"(a3),"r"(b0),"r"(b1));
}
__device__ __forceinline__ unsigned packh(__half x, __half y){
    return (unsigned)__half_as_ushort(x) | ((unsigned)__half_as_ushort(y) << 16);
}
__device__ __forceinline__ void split2(float x, float y, unsigned& hi, unsigned& lo){
    __half hx = __float2half_rn(x), hy = __float2half_rn(y);
    __half lx = __float2half_rn(x - __half2float(hx));
    __half ly = __float2half_rn(y - __half2float(hy));
    hi = packh(hx, hy);
    lo = packh(lx, ly);
}
__device__ __forceinline__ void cp16(unsigned saddr, const void* g, bool v){
    asm volatile("cp.async.ca.shared.global [%0], [%1], 16, %2;"
        :: "r"(saddr), "l"(g), "r"(v ? 16 : 0));
}

__device__ __forceinline__ float warpSum(float v){
    #pragma unroll
    for (int o=16;o;o>>=1) v += __shfl_xor_sync(0xffffffffu, v, o);
    return v;
}
__device__ __forceinline__ float warpMax(float v){
    #pragma unroll
    for (int o=16;o;o>>=1) v = fmaxf(v, __shfl_xor_sync(0xffffffffu, v, o));
    return v;
}
__device__ __forceinline__ float blockSum(float v, float* red){
    v = warpSum(v);
    if ((threadIdx.x & 31) == 0) red[threadIdx.x>>5] = v;
    __syncthreads();
    if (threadIdx.x < 32) {
        float t = (threadIdx.x < 8) ? red[threadIdx.x] : 0.f;
        t = warpSum(t);
        if (threadIdx.x == 0) red[0] = t;
    }
    __syncthreads();
    float r = red[0];
    __syncthreads();
    return r;
}
__device__ __forceinline__ float blockMax(float v, float* red){
    v = warpMax(v);
    if ((threadIdx.x & 31) == 0) red[threadIdx.x>>5] = v;
    __syncthreads();
    if (threadIdx.x < 32) {
        float t = (threadIdx.x < 8) ? red[threadIdx.x] : -3.0e38f;
        t = warpMax(t);
        if (threadIdx.x == 0) red[0] = t;
    }
    __syncthreads();
    float r = red[0];
    __syncthreads();
    return r;
}

// ---------------- weight transpose + split (permuted k) ----------------
struct WP8 { const float* p[8]; };

__global__ void wsplit8_kernel(WP8 wp, __half* __restrict__ hiB, __half* __restrict__ loB){
    __shared__ float ts[32][33];
    int mat = blockIdx.z;
    const float* W = wp.p[mat];
    __half* hi = hiB + (long long)mat*WSZ;
    __half* lo = loB + (long long)mat*WSZ;
    int k0 = blockIdx.y*32, n0 = blockIdx.x*32;
    int tx = threadIdx.x, ty = threadIdx.y;   // 32 x 8
    #pragma unroll
    for (int i=0;i<4;i++)
        ts[ty+8*i][tx] = W[(long long)(k0+ty+8*i)*DM + n0 + tx];
    __syncthreads();
    #pragma unroll
    for (int i=0;i<4;i++){
        int n = n0 + ty + 8*i, k = k0 + tx;
        float v = ts[tx][ty+8*i];
        __half h = __float2half_rn(v);
        int kp = kperm(k);
        hi[(long long)n*DM + kp] = h;
        lo[(long long)n*DM + kp] = __float2half_rn(v - __half2float(h));
    }
}

__global__ void wsplit_kernel(const float* __restrict__ W,
                              __half* __restrict__ hi, __half* __restrict__ lo,
                              int K, int N){
    __shared__ float ts[32][33];
    long long zoff = (long long)blockIdx.z * K * N;
    W  += zoff; hi += zoff; lo += zoff;
    int k0 = blockIdx.y*32, n0 = blockIdx.x*32;
    int tx = threadIdx.x, ty = threadIdx.y;
    #pragma unroll
    for (int i=0;i<4;i++)
        ts[ty+8*i][tx] = W[(long long)(k0+ty+8*i)*N + n0 + tx];
    __syncthreads();
    #pragma unroll
    for (int i=0;i<4;i++){
        int n = n0 + ty + 8*i, k = k0 + tx;
        float v = ts[tx][ty+8*i];
        __half h = __float2half_rn(v);
        int kp = kperm(k);
        hi[(long long)n*K + kp] = h;
        lo[(long long)n*K + kp] = __float2half_rn(v - __half2float(h));
    }
}

// ---------------- layernorm (fp32 out + permuted split out) ----------------
__global__ __launch_bounds__(256) void ln_kernel(const float* __restrict__ x,
                                                 const float* __restrict__ g,
                                                 const float* __restrict__ b,
                                                 float* __restrict__ y,
                                                 __half* __restrict__ yh,
                                                 __half* __restrict__ yl){
    __shared__ float row[DM];
    __shared__ float red[8];
    long long base = (long long)blockIdx.x * DM;
    float s = 0.f;
    for (int i = threadIdx.x; i < DM; i += 256) { float v = x[base+i]; row[i] = v; s += v; }
    s = blockSum(s, red);
    float mu = s * (1.f/DM);
    float vs = 0.f;
    for (int i = threadIdx.x; i < DM; i += 256) { float d = row[i]-mu; vs += d*d; }
    vs = blockSum(vs, red);
    float rstd = rsqrtf(vs * (1.f/DM) + 1e-5f);
    unsigned* oh = (unsigned*)(yh + base);
    unsigned* ol = (unsigned*)(yl + base);
    for (int i2 = threadIdx.x; i2 < DM/2; i2 += 256){
        int i = i2*2;
        float v0 = (row[i  ]-mu)*rstd*g[i  ] + b[i  ];
        float v1 = (row[i+1]-mu)*rstd*g[i+1] + b[i+1];
        if (y){ y[base+i] = v0; y[base+i+1] = v1; }
        unsigned h,l; split2(v0,v1,h,l);
        int w = wperm(i2);
        oh[w] = h; ol[w] = l;
    }
}

// ---------------- fp16x3 GEMM, 3-stage cp.async, templated N-tile ----------------
// NTILES=8 -> 128x128 CTA tile; NTILES=4 -> 128x64 CTA tile.
template<int NTILES>
__global__ __launch_bounds__(256,2) void gemm_hh_kernel(
    const __half* __restrict__ Ahi, const __half* __restrict__ Alo,
    const __half* __restrict__ Bhi, const __half* __restrict__ Blo,
    float* __restrict__ Cf, __half* __restrict__ Chi, __half* __restrict__ Clo,
    int M, int N, int K, int lda, int ldb, int ldc,
    int innerN,
    long long sAo, long long sAi, long long sBo, long long sBi,
    long long sCo, long long sCi,
    const int* __restrict__ rowIdx, const int* __restrict__ tileExpert,
    long long expStrideB, float alpha, int actMode, int cT,
    MD md, int nMulti)
{
    __shared__ unsigned AsH[3][128][8];
    __shared__ unsigned AsL[3][128][8];
    __shared__ unsigned BsH[3][128][8];
    __shared__ unsigned BsL[3][128][8];

    int z  = blockIdx.z;
    int zo = z / innerN, zi = z - zo*innerN;
    if (nMulti > 0){
        Ahi = md.ah[zi]; Alo = md.al[zi];
        Cf  = md.f[zi];  Chi = md.h[zi]; Clo = md.l[zi];
        ldc = md.ldc[zi]; cT = md.cT[zi];
    }
    Ahi += zo*sAo + zi*sAi;
    Alo += zo*sAo + zi*sAi;
    long long boff = zo*sBo + zi*sBi;
    if (tileExpert) boff += (long long)tileExpert[blockIdx.y] * expStrideB;
    Bhi += boff; Blo += boff;
    long long coff = zo*sCo + zi*sCi;

    const int tm0 = blockIdx.y * 128;
    const int tn0 = blockIdx.x * (NTILES*16);
    const int tid = threadIdx.x;
    const int lane = tid & 31;
    const int warp = tid >> 5;
    const int wm = (warp & 3) * 32;
    const int wn = (warp >> 2) * (NTILES*8);
    const int g = lane >> 2;
    const int q = lane & 3;

    // loaders: 2 threads/row, each copies 8 consecutive (permuted) halves
    const int lrow = tid >> 1;
    const int lsel = tid & 1;
    const int loff = lsel * 8;

    int grow = tm0 + lrow;
    bool aval = grow < M;
    int srcRow = aval ? (rowIdx ? (rowIdx[grow] & (NTOK-1)) : grow) : 0;
    const __half* AhiP = Ahi + (long long)srcRow * lda + loff;
    const __half* AloP = Alo + (long long)srcRow * lda + loff;
    bool bval = (tn0 + lrow) < N;
    int brow = bval ? (tn0 + lrow) : 0;
    const __half* BhiP = Bhi + (long long)brow * ldb + loff;
    const __half* BloP = Blo + (long long)brow * ldb + loff;

    unsigned base_off = (unsigned)((lrow*8 + lsel*4)*4);
    unsigned aH0 = (unsigned)__cvta_generic_to_shared(&AsH[0][0][0]) + base_off;
    unsigned aL0 = (unsigned)__cvta_generic_to_shared(&AsL[0][0][0]) + base_off;
    unsigned bH0 = (unsigned)__cvta_generic_to_shared(&BsH[0][0][0]) + base_off;
    unsigned bL0 = (unsigned)__cvta_generic_to_shared(&BsL[0][0][0]) + base_off;

    float acc[2][NTILES][4];
    #pragma unroll
    for (int mi=0;mi<2;mi++)
        #pragma unroll
        for (int ni=0;ni<NTILES;ni++)
            #pragma unroll
            for (int t=0;t<4;t++) acc[mi][ni][t]=0.f;

    const int nt = K >> 4;

    #define ISSUE(T) do{                                             \
        int _t = (T);                                                 \
        if (_t < nt){                                                 \
            unsigned _bo = (unsigned)((_t % 3) * 4096);               \
            int _kn = _t * 16;                                        \
            cp16(aH0 + _bo, AhiP + _kn, aval);                        \
            cp16(aL0 + _bo, AloP + _kn, aval);                        \
            cp16(bH0 + _bo, BhiP + _kn, bval);                        \
            cp16(bL0 + _bo, BloP + _kn, bval);                        \
        }                                                             \
        asm volatile("cp.async.commit_group;");                       \
    }while(0)

    ISSUE(0);
    ISSUE(1);

    int buf = 0;
    for (int k = 0; k < nt; k++){
        asm volatile("cp.async.wait_group 1;");
        __syncthreads();
        ISSUE(k+2);

        // compute on buf
        {
            uint2 ah[2][2], al[2][2];
            #pragma unroll
            for (int mi = 0; mi < 2; mi++){
                int row = wm + mi*16 + g;
                ah[mi][0] = *(const uint2*)&AsH[buf][row  ][2*q];
                ah[mi][1] = *(const uint2*)&AsH[buf][row+8][2*q];
                al[mi][0] = *(const uint2*)&AsL[buf][row  ][2*q];
                al[mi][1] = *(const uint2*)&AsL[buf][row+8][2*q];
            }
            #pragma unroll
            for (int ni = 0; ni < NTILES; ni++){
                int col = wn + ni*8 + g;
                uint2 bh = *(const uint2*)&BsH[buf][col][2*q];
                uint2 bl = *(const uint2*)&BsL[buf][col][2*q];
                #pragma unroll
                for (int mi = 0; mi < 2; mi++){
                    mma_f16(acc[mi][ni], ah[mi][0].x, ah[mi][1].x, ah[mi][0].y, ah[mi][1].y, bh.x, bh.y);
                    mma_f16(acc[mi][ni], ah[mi][0].x, ah[mi][1].x, ah[mi][0].y, ah[mi][1].y, bl.x, bl.y);
                    mma_f16(acc[mi][ni], al[mi][0].x, al[mi][1].x, al[mi][0].y, al[mi][1].y, bh.x, bh.y);
                }
            }
        }
        buf = (buf == 2) ? 0 : buf + 1;
    }
    #undef ISSUE

    // epilogue
    float* CfP = Cf ? (Cf + coff) : (float*)0;
    __half* ChiP = Chi ? (Chi + coff) : (__half*)0;
    __half* CloP = Clo ? (Clo + coff) : (__half*)0;
    #pragma unroll
    for (int mi = 0; mi < 2; mi++){
        #pragma unroll
        for (int rr = 0; rr < 2; rr++){
            int row = tm0 + wm + mi*16 + g + rr*8;
            if (row >= M) continue;
            #pragma unroll
            for (int ni = 0; ni < NTILES; ni++){
                int col = tn0 + wn + ni*8 + q*2;
                if (col >= N) continue;
                float v0 = acc[mi][ni][rr*2+0] * alpha;
                float v1 = acc[mi][ni][rr*2+1] * alpha;
                if (actMode == 1){
                    v0 = 0.5f * v0 * (1.f + erff(v0 * 0.70710678118654752f));
                    v1 = 0.5f * v1 * (1.f + erff(v1 * 0.70710678118654752f));
                }
                if (!cT){
                    long long prow = (long long)row * ldc;
                    if (CfP) *(float2*)&CfP[prow + col] = make_float2(v0, v1);
                    if (ChiP){
                        unsigned h,l; split2(v0,v1,h,l);
                        int pcol = (col & ~15) | (pperm((col>>1)&7)<<1);
                        *(unsigned*)&ChiP[prow + pcol] = h;
                        *(unsigned*)&CloP[prow + pcol] = l;
                    }
                } else {
                    if (CfP){
                        CfP[(long long)(col  ) * ldc + row] = v0;
                        if (col + 1 < N) CfP[(long long)(col+1) * ldc + row] = v1;
                    }
                    if (ChiP){
                        int rowp = kperm(row);
                        __half h0 = __float2half_rn(v0);
                        ChiP[(long long)(col) * ldc + rowp] = h0;
                        CloP[(long long)(col) * ldc + rowp] = __float2half_rn(v0 - __half2float(h0));
                        if (col + 1 < N){
                            __half h1v = __float2half_rn(v1);
                            ChiP[(long long)(col+1) * ldc + rowp] = h1v;
                            CloP[(long long)(col+1) * ldc + rowp] = __float2half_rn(v1 - __half2float(h1v));
                        }
                    }
                }
            }
        }
    }
}

// ---------------- masked row softmax on permuted hi/lo halves (in place) ----------------
__global__ __launch_bounds__(256) void softmax_kernel(const int* __restrict__ mask,
                                                      __half* __restrict__ ph,
                                                      __half* __restrict__ pl){
    long long r = blockIdx.x;
    int qq = (int)(r & 1023);
    int b = (int)(r >> 14);
    const int* mr = mask + ((long long)b << 20) + ((long long)qq << 10);
    unsigned* dh = (unsigned*)(ph + (r << 10));
    unsigned* dl = (unsigned*)(pl + (r << 10));
    __shared__ float buf[SEQ];
    __shared__ float red[8];
    float mx = -3.0e38f;
    for (int i2 = threadIdx.x; i2 < SEQ/2; i2 += 256){
        int lp = (i2 & ~7) | pinv(i2 & 7);
        __half2 hv = *(__half2*)&dh[i2];
        __half2 lv = *(__half2*)&dl[i2];
        float v0 = __half2float(hv.x) + __half2float(lv.x);
        float v1 = __half2float(hv.y) + __half2float(lv.y);
        if (mr[2*lp  ] == 0) v0 = -1e9f;
        if (mr[2*lp+1] == 0) v1 = -1e9f;
        buf[2*lp  ] = v0;
        buf[2*lp+1] = v1;
        mx = fmaxf(mx, fmaxf(v0, v1));
    }
    mx = blockMax(mx, red);
    float sum = 0.f;
    for (int i = threadIdx.x; i < SEQ; i += 256){
        float e = expf(buf[i]-mx);
        buf[i] = e; sum += e;
    }
    sum = blockSum(sum, red);
    float inv = 1.f / sum;
    for (int i2 = threadIdx.x; i2 < SEQ/2; i2 += 256){
        int lp = (i2 & ~7) | pinv(i2 & 7);
        unsigned h,l; split2(buf[2*lp]*inv, buf[2*lp+1]*inv, h, l);
        dh[i2] = h; dl[i2] = l;
    }
}

// ---------------- delta branch (2-stage ctx / ksum) ----------------
__global__ __launch_bounds__(256) void ctx1_kernel(const float* __restrict__ kd,
                                                   const float* __restrict__ vd,
                                                   float* __restrict__ ctxp){
    int z = blockIdx.x >> 2;
    int chunk = blockIdx.x & 3;
    int b = z >> 4, h = z & 15;
    const float* kbase = kd + ((long long)b*SEQ)*DM + h*DK;
    const float* vbase = vd + ((long long)b*SEQ)*DM + h*DK;
    __shared__ float ks[64][65];
    __shared__ float vs[64][65];
    int tid = threadIdx.x;
    int d0 = (tid >> 4) << 2;
    int e0 = (tid & 15) << 2;
    float acc[4][4];
    #pragma unroll
    for (int i=0;i<4;i++)
        #pragma unroll
        for (int j=0;j<4;j++) acc[i][j]=0.f;

    for (int s0 = chunk*256; s0 < chunk*256+256; s0 += 64) {
        for (int t = tid; t < 64*16; t += 256) {
            int rr = t >> 4; int cc = (t & 15) << 2;
            float4 kv = *(const float4*)(kbase + (long long)(s0+rr)*DM + cc);
            float4 vv = *(const float4*)(vbase + (long long)(s0+rr)*DM + cc);
            ks[rr][cc+0]=kv.x; ks[rr][cc+1]=kv.y; ks[rr][cc+2]=kv.z; ks[rr][cc+3]=kv.w;
            vs[rr][cc+0]=vv.x; vs[rr][cc+1]=vv.y; vs[rr][cc+2]=vv.z; vs[rr][cc+3]=vv.w;
        }
        __syncthreads();
        #pragma unroll 4
        for (int ss=0; ss<64; ss++){
            float kr[4], vr[4];
            #pragma unroll
            for (int i=0;i<4;i++) kr[i]=ks[ss][d0+i];
            #pragma unroll
            for (int j=0;j<4;j++) vr[j]=vs[ss][e0+j];
            #pragma unroll
            for (int i=0;i<4;i++)
                #pragma unroll
                for (int j=0;j<4;j++) acc[i][j] += kr[i]*vr[j];
        }
        __syncthreads();
    }
    float* cbase = ctxp + ((long long)z*4 + chunk)*DK*DK;
    #pragma unroll
    for (int i=0;i<4;i++)
        #pragma unroll
        for (int j=0;j<4;j++)
            cbase[(d0+i)*DK + e0+j] = acc[i][j];
}

__global__ void ctx2_kernel(const float* __restrict__ ctxp, float* __restrict__ ctx){
    int z = blockIdx.x;
    const float* p = ctxp + (long long)z*4*DK*DK;
    float* o = ctx + (long long)z*DK*DK;
    for (int i = threadIdx.x; i < DK*DK; i += 256)
        o[i] = p[i] + p[DK*DK + i] + p[2*DK*DK + i] + p[3*DK*DK + i];
}

__global__ void ksum1_kernel(const float* __restrict__ kd, float* __restrict__ ksump){
    int z = blockIdx.x >> 3;
    int c = blockIdx.x & 7;
    int b = z >> 4, h = z & 15;
    int d = threadIdx.x;
    const float* base = kd + ((long long)(b*SEQ + c*128))*DM + h*DK + d;
    float s = 0.f;
    #pragma unroll 4
    for (int ss=0; ss<128; ss++) s += fmaxf(base[(long long)ss*DM], 0.f);
    ksump[(z*8 + c)*DK + d] = s;
}

__global__ void ksum2_kernel(const float* __restrict__ ksump, float* __restrict__ ksum){
    int z = blockIdx.x;
    int d = threadIdx.x;
    float s = 0.f;
    #pragma unroll
    for (int c=0;c<8;c++) s += ksump[(z*8 + c)*DK + d];
    ksum[z*DK + d] = s;
}

__global__ __launch_bounds__(256) void delta_kernel(const float* __restrict__ qd,
                                                    const float* __restrict__ ctx,
                                                    const float* __restrict__ ksum,
                                                    __half* __restrict__ dh,
                                                    __half* __restrict__ dl){
    int z = blockIdx.x >> 2;
    int sc = blockIdx.x & 3;
    int b = z >> 4, h = z & 15;
    __shared__ float cs[DK*DK];
    __shared__ float kss[DK];
    for (int i = threadIdx.x; i < DK*DK; i += 256) cs[i] = ctx[(long long)z*DK*DK + i];
    if (threadIdx.x < DK) kss[threadIdx.x] = ksum[z*DK + threadIdx.x];
    __syncthreads();
    int s = sc*256 + threadIdx.x;
    const float* qrow = qd + ((long long)(b*SEQ + s))*DM + h*DK;
    float q[DK];
    #pragma unroll
    for (int d=0; d<DK; d+=4){
        float4 v = *(const float4*)(qrow + d);
        q[d+0]=fmaxf(v.x,0.f); q[d+1]=fmaxf(v.y,0.f);
        q[d+2]=fmaxf(v.z,0.f); q[d+3]=fmaxf(v.w,0.f);
    }
    float zv = 1e-6f;
    #pragma unroll
    for (int d=0; d<DK; d++) zv += q[d]*kss[d];
    float invz = 1.f / zv;
    long long obase = ((long long)(b*SEQ + s))*DM + h*DK;
    unsigned* ohp = (unsigned*)(dh + obase);
    unsigned* olp = (unsigned*)(dl + obase);
    for (int e=0; e<DK; e+=2){
        float a0 = 0.f, a1 = 0.f;
        #pragma unroll
        for (int d=0; d<DK; d++){
            a0 += q[d]*cs[d*DK + e];
            a1 += q[d]*cs[d*DK + e+1];
        }
        unsigned hh,ll; split2(a0*invz, a1*invz, hh, ll);
        int w = wperm(e>>1);
        ohp[w] = hh; olp[w] = ll;
    }
}

// ---------------- gate ----------------
__global__ __launch_bounds__(256) void gate_kernel(const float* __restrict__ xn,
                                                   const float* __restrict__ wg,
                                                   float* __restrict__ gate){
    int t = blockIdx.x;
    float p0=0.f, p1=0.f;
    for (int k = threadIdx.x; k < DM; k += 256){
        float xv = xn[(long long)t*DM + k];
        p0 += xv*wg[k*2+0];
        p1 += xv*wg[k*2+1];
    }
    __shared__ float red[8];
    p0 = blockSum(p0, red);
    p1 = blockSum(p1, red);
    if (threadIdx.x == 0){
        float m = fmaxf(p0,p1);
        float e0 = expf(p0-m), e1 = expf(p1-m);
        float inv = 1.f/(e0+e1);
        gate[t*2+0] = e0*inv;
        gate[t*2+1] = e1*inv;
    }
}

__global__ void combine1_kernel(const float* __restrict__ x,
                                const float* __restrict__ dense,
                                const float* __restrict__ delta,
                                const float* __restrict__ gate,
                                float* __restrict__ x1){
    long long i = (long long)blockIdx.x*256 + threadIdx.x;
    int t = (int)(i >> 10);
    x1[i] = x[i] + gate[t*2]*dense[i] + gate[t*2+1]*delta[i];
}

// ---------------- router ----------------
__global__ __launch_bounds__(256) void router_kernel(const float* __restrict__ xn2,
                                                     const float* __restrict__ wr,
                                                     int* __restrict__ topk_idx,
                                                     float* __restrict__ topk_w,
                                                     int* __restrict__ counts){
    int t = blockIdx.x;
    float p[NE];
    #pragma unroll
    for (int e=0;e<NE;e++) p[e]=0.f;
    for (int k = threadIdx.x; k < DM; k += 256){
        float xv = xn2[(long long)t*DM + k];
        #pragma unroll
        for (int e=0;e<NE;e++) p[e] += xv*wr[k*NE + e];
    }
    __shared__ float part[NE][8];
    int w = threadIdx.x >> 5;
    #pragma unroll
    for (int e=0;e<NE;e++){
        float v = warpSum(p[e]);
        if ((threadIdx.x & 31)==0) part[e][w] = v;
    }
    __syncthreads();
    if (threadIdx.x == 0){
        float lg[NE];
        for (int e=0;e<NE;e++){
            float s=0.f;
            for (int ww=0; ww<8; ww++) s += part[e][ww];
            lg[e]=s;
        }
        int i0=0; float v0=lg[0];
        for (int e=1;e<NE;e++) if (lg[e]>v0){v0=lg[e];i0=e;}
        int i1=-1; float v1=-3.0e38f;
        for (int e=0;e<NE;e++) if (e!=i0 && lg[e]>v1){v1=lg[e];i1=e;}
        float e1 = expf(v1-v0);
        float inv = 1.f/(1.f+e1);
        topk_idx[t*2+0]=i0; topk_idx[t*2+1]=i1;
        topk_w[t*2+0]=inv;  topk_w[t*2+1]=e1*inv;
        atomicAdd(&counts[i0],1); atomicAdd(&counts[i1],1);
    }
}

__global__ void prep_kernel(int* counts, int* cursor, int* tok){
    int i = blockIdx.x*256 + threadIdx.x;
    if (i < NE){ counts[i]=0; cursor[i]=0; }
    if (i < PAIR_CAP) tok[i]=0;
}

__global__ void scan_kernel(const int* counts, int* off, int* tile_e){
    if (threadIdx.x==0 && blockIdx.x==0){
        int o = 0;
        off[0]=0;
        for (int e=0;e<NE;e++){ o += (counts[e]+127)&~127; off[e+1]=o; }
        for (int t=0;t<NTILE72;t++){
            int row = t*128;
            int ee = NE-1;
            for (int i=0;i<NE;i++){ if (row < off[i+1]) { ee=i; break; } }
            tile_e[t]=ee;
        }
    }
}

__global__ void place_kernel(const int* __restrict__ topk_idx,
                             const int* __restrict__ off,
                             int* cursor, int* tok, int* pair_pos){
    int t = blockIdx.x*256 + threadIdx.x;
    if (t >= NTOK) return;
    for (int k=0;k<2;k++){
        int e = topk_idx[t*2+k];
        int pos = atomicAdd(&cursor[e],1);
        int r = off[e] + pos;
        tok[r] = t;
        pair_pos[t*2+k] = r;
    }
}

__global__ void final_kernel(const float* __restrict__ x1,
                             const float* __restrict__ y2,
                             const float* __restrict__ topk_w,
                             const int* __restrict__ pair_pos,
                             float* __restrict__ out){
    long long i = (long long)blockIdx.x*256 + threadIdx.x;
    int t = (int)(i >> 10);
    int c = (int)(i & 1023);
    int p0 = pair_pos[t*2+0], p1 = pair_pos[t*2+1];
    out[i] = x1[i] + topk_w[t*2+0]*y2[(long long)p0*DM + c]
                   + topk_w[t*2+1]*y2[(long long)p1*DM + c];
}

// ---------------- host side ----------------
static void gemm(const __half* Ahi, const __half* Alo,
                 const __half* Bhi, const __half* Blo,
                 float* Cf, __half* Chi, __half* Clo,
                 int M, int N, int K, int lda, int ldb, int ldc,
                 int batch, int innerN,
                 long long sAo, long long sAi, long long sBo, long long sBi,
                 long long sCo, long long sCi,
                 const int* rowIdx, const int* tileE, long long expSB,
                 float alpha, int act, int cT,
                 int bn64, const MD& md, int nMulti){
    if (bn64){
        dim3 grid((N+63)/64, (M+127)/128, batch);
        gemm_hh_kernel<4><<<grid, 256>>>(Ahi,Alo,Bhi,Blo,Cf,Chi,Clo,
                                         M,N,K,lda,ldb,ldc,innerN,
                                         sAo,sAi,sBo,sBi,sCo,sCi,
                                         rowIdx,tileE,expSB,alpha,act,cT,md,nMulti);
    } else {
        dim3 grid((N+127)/128, (M+127)/128, batch);
        gemm_hh_kernel<8><<<grid, 256>>>(Ahi,Alo,Bhi,Blo,Cf,Chi,Clo,
                                         M,N,K,lda,ldb,ldc,innerN,
                                         sAo,sAi,sBo,sBi,sCo,sCi,
                                         rowIdx,tileE,expSB,alpha,act,cT,md,nMulti);
    }
}

extern "C" void kernel_launch(void* const* d_in, const int* in_sizes, int n_in,
                              void* d_out, int out_size){
    const float* x        = (const float*)d_in[0];
    const int*   mask     = (const int*)  d_in[1];
    const float* ln1_g    = (const float*)d_in[2];
    const float* ln1_b    = (const float*)d_in[3];
    const float* wq       = (const float*)d_in[4];
    const float* wk       = (const float*)d_in[5];
    const float* wv       = (const float*)d_in[6];
    const float* wo       = (const float*)d_in[7];
    const float* wqd      = (const float*)d_in[8];
    const float* wkd      = (const float*)d_in[9];
    const float* wvd      = (const float*)d_in[10];
    const float* wod      = (const float*)d_in[11];
    const float* w_gate   = (const float*)d_in[12];
    const float* ln2_g    = (const float*)d_in[13];
    const float* ln2_b    = (const float*)d_in[14];
    const float* w_router = (const float*)d_in[15];
    const float* e_w1     = (const float*)d_in[16];
    const float* e_w2     = (const float*)d_in[17];
    float* out = (float*)d_out;

    float *xn1,*qd,*kd,*vd,*dense_o,*delta_o,*gate,*x1,*xn2,*ctx,*ctxp,*ksum,*ksump,*y2,*topk_w;
    int *topk_idx,*counts,*cursor,*off,*tile_e,*tok,*pair_pos;
    __half *xn1h,*xn1l,*qh,*ql,*kh,*kl,*vTh,*vTl,*ph,*pl,*acth,*actl,*dlh,*dll;
    __half *xn2h,*xn2l,*h1h,*h1l;
    __half *wT_hi,*wT_lo,*e1T_hi,*e1T_lo,*e2T_hi,*e2T_lo;

    cudaGetSymbolAddress((void**)&xn1,     g_xn1);
    cudaGetSymbolAddress((void**)&qd,      g_qd);
    cudaGetSymbolAddress((void**)&kd,      g_kd);
    cudaGetSymbolAddress((void**)&vd,      g_vd);
    cudaGetSymbolAddress((void**)&dense_o, g_dense_o);
    cudaGetSymbolAddress((void**)&delta_o, g_delta_o);
    cudaGetSymbolAddress((void**)&gate,    g_gate);
    cudaGetSymbolAddress((void**)&x1,      g_x1);
    cudaGetSymbolAddress((void**)&xn2,     g_xn2);
    cudaGetSymbolAddress((void**)&ctx,     g_ctx);
    cudaGetSymbolAddress((void**)&ctxp,    g_ctxp);
    cudaGetSymbolAddress((void**)&ksum,    g_ksum);
    cudaGetSymbolAddress((void**)&ksump,   g_ksump);
    cudaGetSymbolAddress((void**)&y2,      g_y2);
    cudaGetSymbolAddress((void**)&topk_w,  g_topk_w);
    cudaGetSymbolAddress((void**)&topk_idx,g_topk_idx);
    cudaGetSymbolAddress((void**)&counts,  g_counts);
    cudaGetSymbolAddress((void**)&cursor,  g_cursor);
    cudaGetSymbolAddress((void**)&off,     g_off);
    cudaGetSymbolAddress((void**)&tile_e,  g_tile_e);
    cudaGetSymbolAddress((void**)&tok,     g_tok);
    cudaGetSymbolAddress((void**)&pair_pos,g_pair_pos);
    cudaGetSymbolAddress((void**)&xn1h,    g_xn1h);
    cudaGetSymbolAddress((void**)&xn1l,    g_xn1l);
    cudaGetSymbolAddress((void**)&qh,      g_qh);
    cudaGetSymbolAddress((void**)&ql,      g_ql);
    cudaGetSymbolAddress((void**)&kh,      g_kh);
    cudaGetSymbolAddress((void**)&kl,      g_kl);
    cudaGetSymbolAddress((void**)&vTh,     g_vTh);
    cudaGetSymbolAddress((void**)&vTl,     g_vTl);
    cudaGetSymbolAddress((void**)&ph,      g_ph);
    cudaGetSymbolAddress((void**)&pl,      g_pl);
    cudaGetSymbolAddress((void**)&acth,    g_acth);
    cudaGetSymbolAddress((void**)&actl,    g_actl);
    cudaGetSymbolAddress((void**)&dlh,     g_dlh);
    cudaGetSymbolAddress((void**)&dll,     g_dll);
    cudaGetSymbolAddress((void**)&xn2h,    g_xn2h);
    cudaGetSymbolAddress((void**)&xn2l,    g_xn2l);
    cudaGetSymbolAddress((void**)&h1h,     g_h1h);
    cudaGetSymbolAddress((void**)&h1l,     g_h1l);
    cudaGetSymbolAddress((void**)&wT_hi,   g_wT_hi);
    cudaGetSymbolAddress((void**)&wT_lo,   g_wT_lo);
    cudaGetSymbolAddress((void**)&e1T_hi,  g_e1T_hi);
    cudaGetSymbolAddress((void**)&e1T_lo,  g_e1T_lo);
    cudaGetSymbolAddress((void**)&e2T_hi,  g_e2T_hi);
    cudaGetSymbolAddress((void**)&e2T_lo,  g_e2T_lo);

    const long long TOKD = (long long)SEQ*DM;
    MD md0; memset(&md0, 0, sizeof(md0));

    // 0: LN1
    ln_kernel<<<NTOK,256>>>(x, ln1_g, ln1_b, xn1, xn1h, xn1l);
    // 1: dense weight splits — order: wq wk wv wqd wkd wvd | wo wod
    WP8 wp;
    wp.p[0]=wq; wp.p[1]=wk; wp.p[2]=wv; wp.p[3]=wqd;
    wp.p[4]=wkd; wp.p[5]=wvd; wp.p[6]=wo; wp.p[7]=wod;
    wsplit8_kernel<<<dim3(32,32,8), dim3(32,8)>>>(wp, wT_hi, wT_lo);
    // 2: expert w1 split
    wsplit_kernel<<<dim3(DFF/32, DM/32, NE), dim3(32,8)>>>(e_w1, e1T_hi, e1T_lo, DM, DFF);

    // 3: all 6 projections in ONE batched launch (grid 1536)  <-- ncu target
    {
        MD md; memset(&md, 0, sizeof(md));
        for (int z=0; z<6; z++){ md.ah[z]=xn1h; md.al[z]=xn1l; md.ldc[z]=DM; md.cT[z]=0; }
        md.h[0]=qh;  md.l[0]=ql;
        md.h[1]=kh;  md.l[1]=kl;
        md.h[2]=vTh; md.l[2]=vTl; md.ldc[2]=NTOK; md.cT[2]=1;
        md.f[3]=qd;
        md.f[4]=kd;
        md.f[5]=vd;
        gemm(xn1h,xn1l, wT_hi,wT_lo, 0,0,0,
             NTOK,DM,DM, DM,DM,DM, 6,6,
             0,0, 0,WSZ, 0,0,
             0,0,0, 1.f,0,0, 0, md, 6);
    }

    // scores = Q @ K^T / 8 -> permuted hi/lo halves
    gemm(qh,ql, kh,kl, 0,ph,pl, SEQ,SEQ,DK, DM,DM,SEQ,
         NB*NH, NH,
         TOKD, DK,  TOKD, DK,  (long long)NH*SEQ*SEQ, (long long)SEQ*SEQ,
         0, 0, 0, 0.125f, 0, 0, 0, md0, 0);

    // masked softmax in place
    softmax_kernel<<<NB*NH*SEQ, 256>>>(mask, ph, pl);

    // attnctx = P @ V (BN=64 tile: no wasted columns)
    gemm(ph,pl, vTh,vTl, 0,acth,actl, SEQ,DK,SEQ, SEQ,NTOK,DM,
         NB*NH, NH,
         (long long)NH*SEQ*SEQ, (long long)SEQ*SEQ,  SEQ, (long long)DK*NTOK,
         TOKD, DK,
         0, 0, 0, 1.f, 0, 0, 1, md0, 0);

    // delta branch (2-stage)
    ctx1_kernel<<<NB*NH*4, 256>>>(kd, vd, ctxp);
    ctx2_kernel<<<NB*NH, 256>>>(ctxp, ctx);
    ksum1_kernel<<<NB*NH*8, 64>>>(kd, ksump);
    ksum2_kernel<<<NB*NH, 64>>>(ksump, ksum);
    delta_kernel<<<NB*NH*4, 256>>>(qd, ctx, ksum, dlh, dll);

    // both output projections in ONE batched launch (grid 512)
    {
        MD md; memset(&md, 0, sizeof(md));
        md.ah[0]=acth; md.al[0]=actl; md.f[0]=dense_o; md.ldc[0]=DM; md.cT[0]=0;
        md.ah[1]=dlh;  md.al[1]=dll;  md.f[1]=delta_o; md.ldc[1]=DM; md.cT[1]=0;
        gemm(acth,actl, wT_hi+6LL*WSZ, wT_lo+6LL*WSZ, 0,0,0,
             NTOK,DM,DM, DM,DM,DM, 2,2,
             0,0, 0,WSZ, 0,0,
             0,0,0, 1.f,0,0, 0, md, 2);
    }

    // gate + combine
    gate_kernel<<<NTOK,256>>>(xn1, w_gate, gate);
    combine1_kernel<<<NTOK*DM/256, 256>>>(x, dense_o, delta_o, gate, x1);

    // LN2
    ln_kernel<<<NTOK,256>>>(x1, ln2_g, ln2_b, xn2, xn2h, xn2l);

    // routing
    prep_kernel<<<(PAIR_CAP+255)/256, 256>>>(counts, cursor, tok);
    router_kernel<<<NTOK, 256>>>(xn2, w_router, topk_idx, topk_w, counts);
    scan_kernel<<<1,32>>>(counts, off, tile_e);
    place_kernel<<<(NTOK+255)/256, 256>>>(topk_idx, off, cursor, tok, pair_pos);

    // expert w2 split
    wsplit_kernel<<<dim3(DM/32, DFF/32, NE), dim3(32,8)>>>(e_w2, e2T_hi, e2T_lo, DFF, DM);

    // expert GEMM1 (gathered, gelu) -> h1 halves
    gemm(xn2h,xn2l, e1T_hi,e1T_lo, 0,h1h,h1l, PAIR_CAP,DFF,DM, DM,DM,DFF,
         1,1, 0,0,0,0,0,0,
         tok, tile_e, (long long)DM*DFF, 1.f, 1, 0, 0, md0, 0);

    // expert GEMM2 -> y2 fp32
    gemm(h1h,h1l, e2T_hi,e2T_lo, y2,0,0, PAIR_CAP,DM,DFF, DFF,DFF,DM,
         1,1, 0,0,0,0,0,0,
         0, tile_e, (long long)DFF*DM, 1.f, 0, 0, 0, md0, 0);

    // final combine
    final_kernel<<<NTOK*DM/256, 256>>>(x1, y2, topk_w, pair_pos, out);
}

// round 8
// speedup vs baseline: 2.2672x; 1.0035x over previous
#include <cuda_runtime.h>
#include <cuda_fp16.h>
#include <math.h>

// ---------------- problem constants ----------------
#define NTOK 4096              // B*S
#define DM   1024
#define DFF  2048
#define NH   16
#define DK   64
#define NB   4
#define SEQ  1024
#define NE   8
#define PAIR_CAP 9216
#define NTILE72  72
#define WSZ  (1024*1024)

// ---------------- fp32 scratch ----------------
__device__ float g_xn1[NTOK*DM];
__device__ float g_qd [NTOK*DM];
__device__ float g_kd [NTOK*DM];
__device__ float g_vd [NTOK*DM];
__device__ float g_dense_o[NTOK*DM];
__device__ float g_delta_o[NTOK*DM];
__device__ float g_gate[NTOK*2];
__device__ float g_x1 [NTOK*DM];
__device__ float g_xn2[NTOK*DM];
__device__ float g_ctx [NB*NH*DK*DK];
__device__ float g_ctxp[NB*NH*4*DK*DK];
__device__ float g_ksum[NB*NH*DK];
__device__ float g_ksump[NB*NH*8*DK];
__device__ float g_y2[(long long)PAIR_CAP*DM];
__device__ int   g_topk_idx[NTOK*2];
__device__ float g_topk_w [NTOK*2];
__device__ int   g_counts[NE];
__device__ int   g_cursor[NE];
__device__ int   g_off[NE+1];
__device__ int   g_tile_e[NTILE72];
__device__ int   g_tok[PAIR_CAP];
__device__ int   g_pair_pos[NTOK*2];

// ---------------- fp16 hi/lo scratch (k-pair permuted layout) ----------------
__device__ __half g_xn1h[NTOK*DM],  g_xn1l[NTOK*DM];
__device__ __half g_qh  [NTOK*DM],  g_ql  [NTOK*DM];
__device__ __half g_kh  [NTOK*DM],  g_kl  [NTOK*DM];
__device__ __half g_vTh [DM*NTOK],  g_vTl [DM*NTOK];
__device__ __half g_ph  [(long long)NB*NH*SEQ*SEQ], g_pl[(long long)NB*NH*SEQ*SEQ];
__device__ __half g_acth[NTOK*DM],  g_actl[NTOK*DM];
__device__ __half g_dlh [NTOK*DM],  g_dll [NTOK*DM];
__device__ __half g_xn2h[NTOK*DM],  g_xn2l[NTOK*DM];
__device__ __half g_h1h [(long long)PAIR_CAP*DFF], g_h1l[(long long)PAIR_CAP*DFF];

__device__ __half g_wT_hi[8LL*WSZ];
__device__ __half g_wT_lo[8LL*WSZ];
__device__ __half g_e1T_hi[8LL*DM*DFF];
__device__ __half g_e1T_lo[8LL*DM*DFF];
__device__ __half g_e2T_hi[8LL*DFF*DM];
__device__ __half g_e2T_lo[8LL*DFF*DM];

// ---------------- multi-output descriptor (batched projections) ----------------
struct MD {
    const __half* ah[6];
    const __half* al[6];
    float*  f[6];
    __half* h[6];
    __half* l[6];
    int ldc[6];
    int cT[6];
};

// ---------------- permutation helpers ----------------
__device__ __forceinline__ int pperm(int p){ return ((p&3)<<1) | (p>>2); }
__device__ __forceinline__ int pinv(int w){ return (w>>1) | ((w&1)<<2); }
__device__ __forceinline__ int kperm(int k){
    return (k & ~15) | (pperm((k>>1)&7)<<1) | (k&1);
}
__device__ __forceinline__ int wperm(int p){
    return (p & ~7) | pperm(p&7);
}

// ---------------- helpers ----------------
__device__ __forceinline__ void mma_f16(float* d,
        unsigned a0, unsigned a1, unsigned a2, unsigned a3,
        unsigned b0, unsigned b1){
    asm volatile("mma.sync.aligned.m16n8k16.row.col.f32.f16.f16.f32 "
        "{%0,%1,%2,%3}, {%4,%5,%6,%7}, {%8,%9}, {%0,%1,%2,%3};"
        : "+f"(d[0]),"+f"(d[1]),"+f"(d[2]),"+f"(d[3])
        : "r"(a0),"r"(a1),"r"(a2),"r"(a3),"r"(b0),"r"(b1));
}
__device__ __forceinline__ unsigned packh(__half x, __half y){
    return (unsigned)__half_as_ushort(x) | ((unsigned)__half_as_ushort(y) << 16);
}
__device__ __forceinline__ void split2(float x, float y, unsigned& hi, unsigned& lo){
    __half hx = __float2half_rn(x), hy = __float2half_rn(y);
    __half lx = __float2half_rn(x - __half2float(hx));
    __half ly = __float2half_rn(y - __half2float(hy));
    hi = packh(hx, hy);
    lo = packh(lx, ly);
}
__device__ __forceinline__ void cp16(unsigned saddr, const void* g, bool v){
    asm volatile("cp.async.ca.shared.global [%0], [%1], 16, %2;"
        :: "r"(saddr), "l"(g), "r"(v ? 16 : 0));
}

__device__ __forceinline__ float warpSum(float v){
    #pragma unroll
    for (int o=16;o;o>>=1) v += __shfl_xor_sync(0xffffffffu, v, o);
    return v;
}
__device__ __forceinline__ float warpMax(float v){
    #pragma unroll
    for (int o=16;o;o>>=1) v = fmaxf(v, __shfl_xor_sync(0xffffffffu, v, o));
    return v;
}
__device__ __forceinline__ float blockSum(float v, float* red){
    v = warpSum(v);
    if ((threadIdx.x & 31) == 0) red[threadIdx.x>>5] = v;
    __syncthreads();
    if (threadIdx.x < 32) {
        float t = (threadIdx.x < 8) ? red[threadIdx.x] : 0.f;
        t = warpSum(t);
        if (threadIdx.x == 0) red[0] = t;
    }
    __syncthreads();
    float r = red[0];
    __syncthreads();
    return r;
}
__device__ __forceinline__ float blockMax(float v, float* red){
    v = warpMax(v);
    if ((threadIdx.x & 31) == 0) red[threadIdx.x>>5] = v;
    __syncthreads();
    if (threadIdx.x < 32) {
        float t = (threadIdx.x < 8) ? red[threadIdx.x] : -3.0e38f;
        t = warpMax(t);
        if (threadIdx.x == 0) red[0] = t;
    }
    __syncthreads();
    float r = red[0];
    __syncthreads();
    return r;
}

// ---------------- weight transpose + split (permuted k) ----------------
struct WP8 { const float* p[8]; };

__global__ void wsplit8_kernel(WP8 wp, __half* __restrict__ hiB, __half* __restrict__ loB){
    __shared__ float ts[32][33];
    int mat = blockIdx.z;
    const float* W = wp.p[mat];
    __half* hi = hiB + (long long)mat*WSZ;
    __half* lo = loB + (long long)mat*WSZ;
    int k0 = blockIdx.y*32, n0 = blockIdx.x*32;
    int tx = threadIdx.x, ty = threadIdx.y;   // 32 x 8
    #pragma unroll
    for (int i=0;i<4;i++)
        ts[ty+8*i][tx] = W[(long long)(k0+ty+8*i)*DM + n0 + tx];
    __syncthreads();
    #pragma unroll
    for (int i=0;i<4;i++){
        int n = n0 + ty + 8*i, k = k0 + tx;
        float v = ts[tx][ty+8*i];
        __half h = __float2half_rn(v);
        int kp = kperm(k);
        hi[(long long)n*DM + kp] = h;
        lo[(long long)n*DM + kp] = __float2half_rn(v - __half2float(h));
    }
}

__global__ void wsplit_kernel(const float* __restrict__ W,
                              __half* __restrict__ hi, __half* __restrict__ lo,
                              int K, int N){
    __shared__ float ts[32][33];
    long long zoff = (long long)blockIdx.z * K * N;
    W  += zoff; hi += zoff; lo += zoff;
    int k0 = blockIdx.y*32, n0 = blockIdx.x*32;
    int tx = threadIdx.x, ty = threadIdx.y;
    #pragma unroll
    for (int i=0;i<4;i++)
        ts[ty+8*i][tx] = W[(long long)(k0+ty+8*i)*N + n0 + tx];
    __syncthreads();
    #pragma unroll
    for (int i=0;i<4;i++){
        int n = n0 + ty + 8*i, k = k0 + tx;
        float v = ts[tx][ty+8*i];
        __half h = __float2half_rn(v);
        int kp = kperm(k);
        hi[(long long)n*K + kp] = h;
        lo[(long long)n*K + kp] = __float2half_rn(v - __half2float(h));
    }
}

// ---------------- layernorm (fp32 out + permuted split out) ----------------
__global__ __launch_bounds__(256) void ln_kernel(const float* __restrict__ x,
                                                 const float* __restrict__ g,
                                                 const float* __restrict__ b,
                                                 float* __restrict__ y,
                                                 __half* __restrict__ yh,
                                                 __half* __restrict__ yl){
    __shared__ float row[DM];
    __shared__ float red[8];
    long long base = (long long)blockIdx.x * DM;
    float s = 0.f;
    for (int i = threadIdx.x; i < DM; i += 256) { float v = x[base+i]; row[i] = v; s += v; }
    s = blockSum(s, red);
    float mu = s * (1.f/DM);
    float vs = 0.f;
    for (int i = threadIdx.x; i < DM; i += 256) { float d = row[i]-mu; vs += d*d; }
    vs = blockSum(vs, red);
    float rstd = rsqrtf(vs * (1.f/DM) + 1e-5f);
    unsigned* oh = (unsigned*)(yh + base);
    unsigned* ol = (unsigned*)(yl + base);
    for (int i2 = threadIdx.x; i2 < DM/2; i2 += 256){
        int i = i2*2;
        float v0 = (row[i  ]-mu)*rstd*g[i  ] + b[i  ];
        float v1 = (row[i+1]-mu)*rstd*g[i+1] + b[i+1];
        if (y){ y[base+i] = v0; y[base+i+1] = v1; }
        unsigned h,l; split2(v0,v1,h,l);
        int w = wperm(i2);
        oh[w] = h; ol[w] = l;
    }
}

// ---------------- fp16x3 GEMM, 3-stage cp.async, templated N-tile ----------------
// NTILES=8 -> 128x128 CTA tile; NTILES=4 -> 128x64 CTA tile.
template<int NTILES>
__global__ __launch_bounds__(256,2) void gemm_hh_kernel(
    const __half* __restrict__ Ahi, const __half* __restrict__ Alo,
    const __half* __restrict__ Bhi, const __half* __restrict__ Blo,
    float* __restrict__ Cf, __half* __restrict__ Chi, __half* __restrict__ Clo,
    int M, int N, int K, int lda, int ldb, int ldc,
    int innerN,
    long long sAo, long long sAi, long long sBo, long long sBi,
    long long sCo, long long sCi,
    const int* __restrict__ rowIdx, const int* __restrict__ tileExpert,
    long long expStrideB, float alpha, int actMode, int cT,
    MD md, int nMulti)
{
    __shared__ unsigned AsH[3][128][8];
    __shared__ unsigned AsL[3][128][8];
    __shared__ unsigned BsH[3][128][8];
    __shared__ unsigned BsL[3][128][8];

    int z  = blockIdx.z;
    int zo = z / innerN, zi = z - zo*innerN;
    if (nMulti > 0){
        Ahi = md.ah[zi]; Alo = md.al[zi];
        Cf  = md.f[zi];  Chi = md.h[zi]; Clo = md.l[zi];
        ldc = md.ldc[zi]; cT = md.cT[zi];
    }
    Ahi += zo*sAo + zi*sAi;
    Alo += zo*sAo + zi*sAi;
    long long boff = zo*sBo + zi*sBi;
    if (tileExpert) boff += (long long)tileExpert[blockIdx.y] * expStrideB;
    Bhi += boff; Blo += boff;
    long long coff = zo*sCo + zi*sCi;

    const int tm0 = blockIdx.y * 128;
    const int tn0 = blockIdx.x * (NTILES*16);
    const int tid = threadIdx.x;
    const int lane = tid & 31;
    const int warp = tid >> 5;
    const int wm = (warp & 3) * 32;
    const int wn = (warp >> 2) * (NTILES*8);
    const int g = lane >> 2;
    const int q = lane & 3;

    // loaders: 2 threads/row, each copies 8 consecutive (permuted) halves
    const int lrow = tid >> 1;
    const int lsel = tid & 1;
    const int loff = lsel * 8;

    int grow = tm0 + lrow;
    bool aval = grow < M;
    int srcRow = aval ? (rowIdx ? (rowIdx[grow] & (NTOK-1)) : grow) : 0;
    const __half* AhiP = Ahi + (long long)srcRow * lda + loff;
    const __half* AloP = Alo + (long long)srcRow * lda + loff;
    bool bval = (tn0 + lrow) < N;
    int brow = bval ? (tn0 + lrow) : 0;
    const __half* BhiP = Bhi + (long long)brow * ldb + loff;
    const __half* BloP = Blo + (long long)brow * ldb + loff;

    unsigned base_off = (unsigned)((lrow*8 + lsel*4)*4);
    unsigned aH0 = (unsigned)__cvta_generic_to_shared(&AsH[0][0][0]) + base_off;
    unsigned aL0 = (unsigned)__cvta_generic_to_shared(&AsL[0][0][0]) + base_off;
    unsigned bH0 = (unsigned)__cvta_generic_to_shared(&BsH[0][0][0]) + base_off;
    unsigned bL0 = (unsigned)__cvta_generic_to_shared(&BsL[0][0][0]) + base_off;

    float acc[2][NTILES][4];
    #pragma unroll
    for (int mi=0;mi<2;mi++)
        #pragma unroll
        for (int ni=0;ni<NTILES;ni++)
            #pragma unroll
            for (int t=0;t<4;t++) acc[mi][ni][t]=0.f;

    const int nt = K >> 4;

    #define ISSUE(T) do{                                             \
        int _t = (T);                                                 \
        if (_t < nt){                                                 \
            unsigned _bo = (unsigned)((_t % 3) * 4096);               \
            int _kn = _t * 16;                                        \
            cp16(aH0 + _bo, AhiP + _kn, aval);                        \
            cp16(aL0 + _bo, AloP + _kn, aval);                        \
            cp16(bH0 + _bo, BhiP + _kn, bval);                        \
            cp16(bL0 + _bo, BloP + _kn, bval);                        \
        }                                                             \
        asm volatile("cp.async.commit_group;");                       \
    }while(0)

    ISSUE(0);
    ISSUE(1);

    int buf = 0;
    for (int k = 0; k < nt; k++){
        asm volatile("cp.async.wait_group 1;");
        __syncthreads();
        ISSUE(k+2);

        // compute on buf
        {
            uint2 ah[2][2], al[2][2];
            #pragma unroll
            for (int mi = 0; mi < 2; mi++){
                int row = wm + mi*16 + g;
                ah[mi][0] = *(const uint2*)&AsH[buf][row  ][2*q];
                ah[mi][1] = *(const uint2*)&AsH[buf][row+8][2*q];
                al[mi][0] = *(const uint2*)&AsL[buf][row  ][2*q];
                al[mi][1] = *(const uint2*)&AsL[buf][row+8][2*q];
            }
            #pragma unroll
            for (int ni = 0; ni < NTILES; ni++){
                int col = wn + ni*8 + g;
                uint2 bh = *(const uint2*)&BsH[buf][col][2*q];
                uint2 bl = *(const uint2*)&BsL[buf][col][2*q];
                #pragma unroll
                for (int mi = 0; mi < 2; mi++){
                    mma_f16(acc[mi][ni], ah[mi][0].x, ah[mi][1].x, ah[mi][0].y, ah[mi][1].y, bh.x, bh.y);
                    mma_f16(acc[mi][ni], ah[mi][0].x, ah[mi][1].x, ah[mi][0].y, ah[mi][1].y, bl.x, bl.y);
                    mma_f16(acc[mi][ni], al[mi][0].x, al[mi][1].x, al[mi][0].y, al[mi][1].y, bh.x, bh.y);
                }
            }
        }
        buf = (buf == 2) ? 0 : buf + 1;
    }
    #undef ISSUE

    // epilogue
    float* CfP = Cf ? (Cf + coff) : (float*)0;
    __half* ChiP = Chi ? (Chi + coff) : (__half*)0;
    __half* CloP = Clo ? (Clo + coff) : (__half*)0;
    #pragma unroll
    for (int mi = 0; mi < 2; mi++){
        #pragma unroll
        for (int rr = 0; rr < 2; rr++){
            int row = tm0 + wm + mi*16 + g + rr*8;
            if (row >= M) continue;
            #pragma unroll
            for (int ni = 0; ni < NTILES; ni++){
                int col = tn0 + wn + ni*8 + q*2;
                if (col >= N) continue;
                float v0 = acc[mi][ni][rr*2+0] * alpha;
                float v1 = acc[mi][ni][rr*2+1] * alpha;
                if (actMode == 1){
                    v0 = 0.5f * v0 * (1.f + erff(v0 * 0.70710678118654752f));
                    v1 = 0.5f * v1 * (1.f + erff(v1 * 0.70710678118654752f));
                }
                if (!cT){
                    long long prow = (long long)row * ldc;
                    if (CfP) *(float2*)&CfP[prow + col] = make_float2(v0, v1);
                    if (ChiP){
                        unsigned h,l; split2(v0,v1,h,l);
                        int pcol = (col & ~15) | (pperm((col>>1)&7)<<1);
                        *(unsigned*)&ChiP[prow + pcol] = h;
                        *(unsigned*)&CloP[prow + pcol] = l;
                    }
                } else {
                    if (CfP){
                        CfP[(long long)(col  ) * ldc + row] = v0;
                        if (col + 1 < N) CfP[(long long)(col+1) * ldc + row] = v1;
                    }
                    if (ChiP){
                        int rowp = kperm(row);
                        __half h0 = __float2half_rn(v0);
                        ChiP[(long long)(col) * ldc + rowp] = h0;
                        CloP[(long long)(col) * ldc + rowp] = __float2half_rn(v0 - __half2float(h0));
                        if (col + 1 < N){
                            __half h1v = __float2half_rn(v1);
                            ChiP[(long long)(col+1) * ldc + rowp] = h1v;
                            CloP[(long long)(col+1) * ldc + rowp] = __float2half_rn(v1 - __half2float(h1v));
                        }
                    }
                }
            }
        }
    }
}

// ---------------- masked row softmax on permuted hi/lo halves (in place) ----------------
__global__ __launch_bounds__(256) void softmax_kernel(const int* __restrict__ mask,
                                                      __half* __restrict__ ph,
                                                      __half* __restrict__ pl){
    long long r = blockIdx.x;
    int qq = (int)(r & 1023);
    int b = (int)(r >> 14);
    const int* mr = mask + ((long long)b << 20) + ((long long)qq << 10);
    unsigned* dh = (unsigned*)(ph + (r << 10));
    unsigned* dl = (unsigned*)(pl + (r << 10));
    __shared__ float buf[SEQ];
    __shared__ float red[8];
    float mx = -3.0e38f;
    for (int i2 = threadIdx.x; i2 < SEQ/2; i2 += 256){
        int lp = (i2 & ~7) | pinv(i2 & 7);
        __half2 hv = *(__half2*)&dh[i2];
        __half2 lv = *(__half2*)&dl[i2];
        float v0 = __half2float(hv.x) + __half2float(lv.x);
        float v1 = __half2float(hv.y) + __half2float(lv.y);
        if (mr[2*lp  ] == 0) v0 = -1e9f;
        if (mr[2*lp+1] == 0) v1 = -1e9f;
        buf[2*lp  ] = v0;
        buf[2*lp+1] = v1;
        mx = fmaxf(mx, fmaxf(v0, v1));
    }
    mx = blockMax(mx, red);
    float sum = 0.f;
    for (int i = threadIdx.x; i < SEQ; i += 256){
        float e = expf(buf[i]-mx);
        buf[i] = e; sum += e;
    }
    sum = blockSum(sum, red);
    float inv = 1.f / sum;
    for (int i2 = threadIdx.x; i2 < SEQ/2; i2 += 256){
        int lp = (i2 & ~7) | pinv(i2 & 7);
        unsigned h,l; split2(buf[2*lp]*inv, buf[2*lp+1]*inv, h, l);
        dh[i2] = h; dl[i2] = l;
    }
}

// ---------------- delta branch (2-stage ctx / ksum) ----------------
__global__ __launch_bounds__(256) void ctx1_kernel(const float* __restrict__ kd,
                                                   const float* __restrict__ vd,
                                                   float* __restrict__ ctxp){
    int z = blockIdx.x >> 2;
    int chunk = blockIdx.x & 3;
    int b = z >> 4, h = z & 15;
    const float* kbase = kd + ((long long)b*SEQ)*DM + h*DK;
    const float* vbase = vd + ((long long)b*SEQ)*DM + h*DK;
    __shared__ float ks[64][65];
    __shared__ float vs[64][65];
    int tid = threadIdx.x;
    int d0 = (tid >> 4) << 2;
    int e0 = (tid & 15) << 2;
    float acc[4][4];
    #pragma unroll
    for (int i=0;i<4;i++)
        #pragma unroll
        for (int j=0;j<4;j++) acc[i][j]=0.f;

    for (int s0 = chunk*256; s0 < chunk*256+256; s0 += 64) {
        for (int t = tid; t < 64*16; t += 256) {
            int rr = t >> 4; int cc = (t & 15) << 2;
            float4 kv = *(const float4*)(kbase + (long long)(s0+rr)*DM + cc);
            float4 vv = *(const float4*)(vbase + (long long)(s0+rr)*DM + cc);
            ks[rr][cc+0]=kv.x; ks[rr][cc+1]=kv.y; ks[rr][cc+2]=kv.z; ks[rr][cc+3]=kv.w;
            vs[rr][cc+0]=vv.x; vs[rr][cc+1]=vv.y; vs[rr][cc+2]=vv.z; vs[rr][cc+3]=vv.w;
        }
        __syncthreads();
        #pragma unroll 4
        for (int ss=0; ss<64; ss++){
            float kr[4], vr[4];
            #pragma unroll
            for (int i=0;i<4;i++) kr[i]=ks[ss][d0+i];
            #pragma unroll
            for (int j=0;j<4;j++) vr[j]=vs[ss][e0+j];
            #pragma unroll
            for (int i=0;i<4;i++)
                #pragma unroll
                for (int j=0;j<4;j++) acc[i][j] += kr[i]*vr[j];
        }
        __syncthreads();
    }
    float* cbase = ctxp + ((long long)z*4 + chunk)*DK*DK;
    #pragma unroll
    for (int i=0;i<4;i++)
        #pragma unroll
        for (int j=0;j<4;j++)
            cbase[(d0+i)*DK + e0+j] = acc[i][j];
}

__global__ void ctx2_kernel(const float* __restrict__ ctxp, float* __restrict__ ctx){
    int z = blockIdx.x;
    const float* p = ctxp + (long long)z*4*DK*DK;
    float* o = ctx + (long long)z*DK*DK;
    for (int i = threadIdx.x; i < DK*DK; i += 256)
        o[i] = p[i] + p[DK*DK + i] + p[2*DK*DK + i] + p[3*DK*DK + i];
}

__global__ void ksum1_kernel(const float* __restrict__ kd, float* __restrict__ ksump){
    int z = blockIdx.x >> 3;
    int c = blockIdx.x & 7;
    int b = z >> 4, h = z & 15;
    int d = threadIdx.x;
    const float* base = kd + ((long long)(b*SEQ + c*128))*DM + h*DK + d;
    float s = 0.f;
    #pragma unroll 4
    for (int ss=0; ss<128; ss++) s += fmaxf(base[(long long)ss*DM], 0.f);
    ksump[(z*8 + c)*DK + d] = s;
}

__global__ void ksum2_kernel(const float* __restrict__ ksump, float* __restrict__ ksum){
    int z = blockIdx.x;
    int d = threadIdx.x;
    float s = 0.f;
    #pragma unroll
    for (int c=0;c<8;c++) s += ksump[(z*8 + c)*DK + d];
    ksum[z*DK + d] = s;
}

__global__ __launch_bounds__(256) void delta_kernel(const float* __restrict__ qd,
                                                    const float* __restrict__ ctx,
                                                    const float* __restrict__ ksum,
                                                    __half* __restrict__ dh,
                                                    __half* __restrict__ dl){
    int z = blockIdx.x >> 2;
    int sc = blockIdx.x & 3;
    int b = z >> 4, h = z & 15;
    __shared__ float cs[DK*DK];
    __shared__ float kss[DK];
    for (int i = threadIdx.x; i < DK*DK; i += 256) cs[i] = ctx[(long long)z*DK*DK + i];
    if (threadIdx.x < DK) kss[threadIdx.x] = ksum[z*DK + threadIdx.x];
    __syncthreads();
    int s = sc*256 + threadIdx.x;
    const float* qrow = qd + ((long long)(b*SEQ + s))*DM + h*DK;
    float q[DK];
    #pragma unroll
    for (int d=0; d<DK; d+=4){
        float4 v = *(const float4*)(qrow + d);
        q[d+0]=fmaxf(v.x,0.f); q[d+1]=fmaxf(v.y,0.f);
        q[d+2]=fmaxf(v.z,0.f); q[d+3]=fmaxf(v.w,0.f);
    }
    float zv = 1e-6f;
    #pragma unroll
    for (int d=0; d<DK; d++) zv += q[d]*kss[d];
    float invz = 1.f / zv;
    long long obase = ((long long)(b*SEQ + s))*DM + h*DK;
    unsigned* ohp = (unsigned*)(dh + obase);
    unsigned* olp = (unsigned*)(dl + obase);
    for (int e=0; e<DK; e+=2){
        float a0 = 0.f, a1 = 0.f;
        #pragma unroll
        for (int d=0; d<DK; d++){
            a0 += q[d]*cs[d*DK + e];
            a1 += q[d]*cs[d*DK + e+1];
        }
        unsigned hh,ll; split2(a0*invz, a1*invz, hh, ll);
        int w = wperm(e>>1);
        ohp[w] = hh; olp[w] = ll;
    }
}

// ---------------- gate ----------------
__global__ __launch_bounds__(256) void gate_kernel(const float* __restrict__ xn,
                                                   const float* __restrict__ wg,
                                                   float* __restrict__ gate){
    int t = blockIdx.x;
    float p0=0.f, p1=0.f;
    for (int k = threadIdx.x; k < DM; k += 256){
        float xv = xn[(long long)t*DM + k];
        p0 += xv*wg[k*2+0];
        p1 += xv*wg[k*2+1];
    }
    __shared__ float red[8];
    p0 = blockSum(p0, red);
    p1 = blockSum(p1, red);
    if (threadIdx.x == 0){
        float m = fmaxf(p0,p1);
        float e0 = expf(p0-m), e1 = expf(p1-m);
        float inv = 1.f/(e0+e1);
        gate[t*2+0] = e0*inv;
        gate[t*2+1] = e1*inv;
    }
}

__global__ void combine1_kernel(const float* __restrict__ x,
                                const float* __restrict__ dense,
                                const float* __restrict__ delta,
                                const float* __restrict__ gate,
                                float* __restrict__ x1){
    long long i = (long long)blockIdx.x*256 + threadIdx.x;
    int t = (int)(i >> 10);
    x1[i] = x[i] + gate[t*2]*dense[i] + gate[t*2+1]*delta[i];
}

// ---------------- router ----------------
__global__ __launch_bounds__(256) void router_kernel(const float* __restrict__ xn2,
                                                     const float* __restrict__ wr,
                                                     int* __restrict__ topk_idx,
                                                     float* __restrict__ topk_w,
                                                     int* __restrict__ counts){
    int t = blockIdx.x;
    float p[NE];
    #pragma unroll
    for (int e=0;e<NE;e++) p[e]=0.f;
    for (int k = threadIdx.x; k < DM; k += 256){
        float xv = xn2[(long long)t*DM + k];
        #pragma unroll
        for (int e=0;e<NE;e++) p[e] += xv*wr[k*NE + e];
    }
    __shared__ float part[NE][8];
    int w = threadIdx.x >> 5;
    #pragma unroll
    for (int e=0;e<NE;e++){
        float v = warpSum(p[e]);
        if ((threadIdx.x & 31)==0) part[e][w] = v;
    }
    __syncthreads();
    if (threadIdx.x == 0){
        float lg[NE];
        for (int e=0;e<NE;e++){
            float s=0.f;
            for (int ww=0; ww<8; ww++) s += part[e][ww];
            lg[e]=s;
        }
        int i0=0; float v0=lg[0];
        for (int e=1;e<NE;e++) if (lg[e]>v0){v0=lg[e];i0=e;}
        int i1=-1; float v1=-3.0e38f;
        for (int e=0;e<NE;e++) if (e!=i0 && lg[e]>v1){v1=lg[e];i1=e;}
        float e1 = expf(v1-v0);
        float inv = 1.f/(1.f+e1);
        topk_idx[t*2+0]=i0; topk_idx[t*2+1]=i1;
        topk_w[t*2+0]=inv;  topk_w[t*2+1]=e1*inv;
        atomicAdd(&counts[i0],1); atomicAdd(&counts[i1],1);
    }
}

__global__ void prep_kernel(int* counts, int* cursor, int* tok){
    int i = blockIdx.x*256 + threadIdx.x;
    if (i < NE){ counts[i]=0; cursor[i]=0; }
    if (i < PAIR_CAP) tok[i]=0;
}

__global__ void scan_kernel(const int* counts, int* off, int* tile_e){
    if (threadIdx.x==0 && blockIdx.x==0){
        int o = 0;
        off[0]=0;
        for (int e=0;e<NE;e++){ o += (counts[e]+127)&~127; off[e+1]=o; }
        for (int t=0;t<NTILE72;t++){
            int row = t*128;
            int ee = NE-1;
            for (int i=0;i<NE;i++){ if (row < off[i+1]) { ee=i; break; } }
            tile_e[t]=ee;
        }
    }
}

__global__ void place_kernel(const int* __restrict__ topk_idx,
                             const int* __restrict__ off,
                             int* cursor, int* tok, int* pair_pos){
    int t = blockIdx.x*256 + threadIdx.x;
    if (t >= NTOK) return;
    for (int k=0;k<2;k++){
        int e = topk_idx[t*2+k];
        int pos = atomicAdd(&cursor[e],1);
        int r = off[e] + pos;
        tok[r] = t;
        pair_pos[t*2+k] = r;
    }
}

__global__ void final_kernel(const float* __restrict__ x1,
                             const float* __restrict__ y2,
                             const float* __restrict__ topk_w,
                             const int* __restrict__ pair_pos,
                             float* __restrict__ out){
    long long i = (long long)blockIdx.x*256 + threadIdx.x;
    int t = (int)(i >> 10);
    int c = (int)(i & 1023);
    int p0 = pair_pos[t*2+0], p1 = pair_pos[t*2+1];
    out[i] = x1[i] + topk_w[t*2+0]*y2[(long long)p0*DM + c]
                   + topk_w[t*2+1]*y2[(long long)p1*DM + c];
}

// ---------------- host side ----------------
static void gemm(const __half* Ahi, const __half* Alo,
                 const __half* Bhi, const __half* Blo,
                 float* Cf, __half* Chi, __half* Clo,
                 int M, int N, int K, int lda, int ldb, int ldc,
                 int batch, int innerN,
                 long long sAo, long long sAi, long long sBo, long long sBi,
                 long long sCo, long long sCi,
                 const int* rowIdx, const int* tileE, long long expSB,
                 float alpha, int act, int cT,
                 int bn64, const MD& md, int nMulti){
    if (bn64){
        dim3 grid((N+63)/64, (M+127)/128, batch);
        gemm_hh_kernel<4><<<grid, 256>>>(Ahi,Alo,Bhi,Blo,Cf,Chi,Clo,
                                         M,N,K,lda,ldb,ldc,innerN,
                                         sAo,sAi,sBo,sBi,sCo,sCi,
                                         rowIdx,tileE,expSB,alpha,act,cT,md,nMulti);
    } else {
        dim3 grid((N+127)/128, (M+127)/128, batch);
        gemm_hh_kernel<8><<<grid, 256>>>(Ahi,Alo,Bhi,Blo,Cf,Chi,Clo,
                                         M,N,K,lda,ldb,ldc,innerN,
                                         sAo,sAi,sBo,sBi,sCo,sCi,
                                         rowIdx,tileE,expSB,alpha,act,cT,md,nMulti);
    }
}

extern "C" void kernel_launch(void* const* d_in, const int* in_sizes, int n_in,
                              void* d_out, int out_size){
    const float* x        = (const float*)d_in[0];
    const int*   mask     = (const int*)  d_in[1];
    const float* ln1_g    = (const float*)d_in[2];
    const float* ln1_b    = (const float*)d_in[3];
    const float* wq       = (const float*)d_in[4];
    const float* wk       = (const float*)d_in[5];
    const float* wv       = (const float*)d_in[6];
    const float* wo       = (const float*)d_in[7];
    const float* wqd      = (const float*)d_in[8];
    const float* wkd      = (const float*)d_in[9];
    const float* wvd      = (const float*)d_in[10];
    const float* wod      = (const float*)d_in[11];
    const float* w_gate   = (const float*)d_in[12];
    const float* ln2_g    = (const float*)d_in[13];
    const float* ln2_b    = (const float*)d_in[14];
    const float* w_router = (const float*)d_in[15];
    const float* e_w1     = (const float*)d_in[16];
    const float* e_w2     = (const float*)d_in[17];
    float* out = (float*)d_out;

    float *xn1,*qd,*kd,*vd,*dense_o,*delta_o,*gate,*x1,*xn2,*ctx,*ctxp,*ksum,*ksump,*y2,*topk_w;
    int *topk_idx,*counts,*cursor,*off,*tile_e,*tok,*pair_pos;
    __half *xn1h,*xn1l,*qh,*ql,*kh,*kl,*vTh,*vTl,*ph,*pl,*acth,*actl,*dlh,*dll;
    __half *xn2h,*xn2l,*h1h,*h1l;
    __half *wT_hi,*wT_lo,*e1T_hi,*e1T_lo,*e2T_hi,*e2T_lo;

    cudaGetSymbolAddress((void**)&xn1,     g_xn1);
    cudaGetSymbolAddress((void**)&qd,      g_qd);
    cudaGetSymbolAddress((void**)&kd,      g_kd);
    cudaGetSymbolAddress((void**)&vd,      g_vd);
    cudaGetSymbolAddress((void**)&dense_o, g_dense_o);
    cudaGetSymbolAddress((void**)&delta_o, g_delta_o);
    cudaGetSymbolAddress((void**)&gate,    g_gate);
    cudaGetSymbolAddress((void**)&x1,      g_x1);
    cudaGetSymbolAddress((void**)&xn2,     g_xn2);
    cudaGetSymbolAddress((void**)&ctx,     g_ctx);
    cudaGetSymbolAddress((void**)&ctxp,    g_ctxp);
    cudaGetSymbolAddress((void**)&ksum,    g_ksum);
    cudaGetSymbolAddress((void**)&ksump,   g_ksump);
    cudaGetSymbolAddress((void**)&y2,      g_y2);
    cudaGetSymbolAddress((void**)&topk_w,  g_topk_w);
    cudaGetSymbolAddress((void**)&topk_idx,g_topk_idx);
    cudaGetSymbolAddress((void**)&counts,  g_counts);
    cudaGetSymbolAddress((void**)&cursor,  g_cursor);
    cudaGetSymbolAddress((void**)&off,     g_off);
    cudaGetSymbolAddress((void**)&tile_e,  g_tile_e);
    cudaGetSymbolAddress((void**)&tok,     g_tok);
    cudaGetSymbolAddress((void**)&pair_pos,g_pair_pos);
    cudaGetSymbolAddress((void**)&xn1h,    g_xn1h);
    cudaGetSymbolAddress((void**)&xn1l,    g_xn1l);
    cudaGetSymbolAddress((void**)&qh,      g_qh);
    cudaGetSymbolAddress((void**)&ql,      g_ql);
    cudaGetSymbolAddress((void**)&kh,      g_kh);
    cudaGetSymbolAddress((void**)&kl,      g_kl);
    cudaGetSymbolAddress((void**)&vTh,     g_vTh);
    cudaGetSymbolAddress((void**)&vTl,     g_vTl);
    cudaGetSymbolAddress((void**)&ph,      g_ph);
    cudaGetSymbolAddress((void**)&pl,      g_pl);
    cudaGetSymbolAddress((void**)&acth,    g_acth);
    cudaGetSymbolAddress((void**)&actl,    g_actl);
    cudaGetSymbolAddress((void**)&dlh,     g_dlh);
    cudaGetSymbolAddress((void**)&dll,     g_dll);
    cudaGetSymbolAddress((void**)&xn2h,    g_xn2h);
    cudaGetSymbolAddress((void**)&xn2l,    g_xn2l);
    cudaGetSymbolAddress((void**)&h1h,     g_h1h);
    cudaGetSymbolAddress((void**)&h1l,     g_h1l);
    cudaGetSymbolAddress((void**)&wT_hi,   g_wT_hi);
    cudaGetSymbolAddress((void**)&wT_lo,   g_wT_lo);
    cudaGetSymbolAddress((void**)&e1T_hi,  g_e1T_hi);
    cudaGetSymbolAddress((void**)&e1T_lo,  g_e1T_lo);
    cudaGetSymbolAddress((void**)&e2T_hi,  g_e2T_hi);
    cudaGetSymbolAddress((void**)&e2T_lo,  g_e2T_lo);

    const long long TOKD = (long long)SEQ*DM;
    MD md0; memset(&md0, 0, sizeof(md0));

    // 0: LN1
    ln_kernel<<<NTOK,256>>>(x, ln1_g, ln1_b, xn1, xn1h, xn1l);
    // 1: dense weight splits — order: wq wk wv wqd wkd wvd | wo wod
    WP8 wp;
    wp.p[0]=wq; wp.p[1]=wk; wp.p[2]=wv; wp.p[3]=wqd;
    wp.p[4]=wkd; wp.p[5]=wvd; wp.p[6]=wo; wp.p[7]=wod;
    wsplit8_kernel<<<dim3(32,32,8), dim3(32,8)>>>(wp, wT_hi, wT_lo);
    // 2: expert w1 split
    wsplit_kernel<<<dim3(DFF/32, DM/32, NE), dim3(32,8)>>>(e_w1, e1T_hi, e1T_lo, DM, DFF);

    // 3: all 6 projections in ONE batched launch (grid 1536)  <-- ncu target
    {
        MD md; memset(&md, 0, sizeof(md));
        for (int z=0; z<6; z++){ md.ah[z]=xn1h; md.al[z]=xn1l; md.ldc[z]=DM; md.cT[z]=0; }
        md.h[0]=qh;  md.l[0]=ql;
        md.h[1]=kh;  md.l[1]=kl;
        md.h[2]=vTh; md.l[2]=vTl; md.ldc[2]=NTOK; md.cT[2]=1;
        md.f[3]=qd;
        md.f[4]=kd;
        md.f[5]=vd;
        gemm(xn1h,xn1l, wT_hi,wT_lo, 0,0,0,
             NTOK,DM,DM, DM,DM,DM, 6,6,
             0,0, 0,WSZ, 0,0,
             0,0,0, 1.f,0,0, 0, md, 6);
    }

    // scores = Q @ K^T / 8 -> permuted hi/lo halves
    gemm(qh,ql, kh,kl, 0,ph,pl, SEQ,SEQ,DK, DM,DM,SEQ,
         NB*NH, NH,
         TOKD, DK,  TOKD, DK,  (long long)NH*SEQ*SEQ, (long long)SEQ*SEQ,
         0, 0, 0, 0.125f, 0, 0, 0, md0, 0);

    // masked softmax in place
    softmax_kernel<<<NB*NH*SEQ, 256>>>(mask, ph, pl);

    // attnctx = P @ V (BN=64 tile: no wasted columns)
    gemm(ph,pl, vTh,vTl, 0,acth,actl, SEQ,DK,SEQ, SEQ,NTOK,DM,
         NB*NH, NH,
         (long long)NH*SEQ*SEQ, (long long)SEQ*SEQ,  SEQ, (long long)DK*NTOK,
         TOKD, DK,
         0, 0, 0, 1.f, 0, 0, 1, md0, 0);

    // delta branch (2-stage)
    ctx1_kernel<<<NB*NH*4, 256>>>(kd, vd, ctxp);
    ctx2_kernel<<<NB*NH, 256>>>(ctxp, ctx);
    ksum1_kernel<<<NB*NH*8, 64>>>(kd, ksump);
    ksum2_kernel<<<NB*NH, 64>>>(ksump, ksum);
    delta_kernel<<<NB*NH*4, 256>>>(qd, ctx, ksum, dlh, dll);

    // both output projections in ONE batched launch (grid 512)
    {
        MD md; memset(&md, 0, sizeof(md));
        md.ah[0]=acth; md.al[0]=actl; md.f[0]=dense_o; md.ldc[0]=DM; md.cT[0]=0;
        md.ah[1]=dlh;  md.al[1]=dll;  md.f[1]=delta_o; md.ldc[1]=DM; md.cT[1]=0;
        gemm(acth,actl, wT_hi+6LL*WSZ, wT_lo+6LL*WSZ, 0,0,0,
             NTOK,DM,DM, DM,DM,DM, 2,2,
             0,0, 0,WSZ, 0,0,
             0,0,0, 1.f,0,0, 0, md, 2);
    }

    // gate + combine
    gate_kernel<<<NTOK,256>>>(xn1, w_gate, gate);
    combine1_kernel<<<NTOK*DM/256, 256>>>(x, dense_o, delta_o, gate, x1);

    // LN2
    ln_kernel<<<NTOK,256>>>(x1, ln2_g, ln2_b, xn2, xn2h, xn2l);

    // routing
    prep_kernel<<<(PAIR_CAP+255)/256, 256>>>(counts, cursor, tok);
    router_kernel<<<NTOK, 256>>>(xn2, w_router, topk_idx, topk_w, counts);
    scan_kernel<<<1,32>>>(counts, off, tile_e);
    place_kernel<<<(NTOK+255)/256, 256>>>(topk_idx, off, cursor, tok, pair_pos);

    // expert w2 split
    wsplit_kernel<<<dim3(DM/32, DFF/32, NE), dim3(32,8)>>>(e_w2, e2T_hi, e2T_lo, DFF, DM);

    // expert GEMM1 (gathered, gelu) -> h1 halves
    gemm(xn2h,xn2l, e1T_hi,e1T_lo, 0,h1h,h1l, PAIR_CAP,DFF,DM, DM,DM,DFF,
         1,1, 0,0,0,0,0,0,
         tok, tile_e, (long long)DM*DFF, 1.f, 1, 0, 0, md0, 0);

    // expert GEMM2 -> y2 fp32
    gemm(h1h,h1l, e2T_hi,e2T_lo, y2,0,0, PAIR_CAP,DM,DFF, DFF,DFF,DM,
         1,1, 0,0,0,0,0,0,
         0, tile_e, (long long)DFF*DM, 1.f, 0, 0, 0, md0, 0);

    // final combine
    final_kernel<<<NTOK*DM/256, 256>>>(x1, y2, topk_w, pair_pos, out);
}

// round 10
// speedup vs baseline: 2.5040x; 1.1044x over previous
#include <cuda_runtime.h>
#include <cuda_fp16.h>
#include <math.h>

#define NTOK 4096
#define DM   1024
#define DFF  2048
#define NH   16
#define DK   64
#define NB   4
#define SEQ  1024
#define NE   8
#define PAIR_CAP 9216
#define NTILE72  72
#define WSZ  (1024*1024)   // words per DMxDM weight (DM*DM)

// ---------------- fp32 scratch ----------------
__device__ float g_qd [NTOK*DM];
__device__ float g_kd [NTOK*DM];
__device__ float g_vd [NTOK*DM];
__device__ float g_dense_o[NTOK*DM];
__device__ float g_delta_o[NTOK*DM];
__device__ float g_gate[NTOK*2];
__device__ float g_x1 [NTOK*DM];
__device__ float g_xn1[NTOK*DM];
__device__ float g_xn2[NTOK*DM];
__device__ float g_ctx [NB*NH*DK*DK];
__device__ float g_ctxp[NB*NH*4*DK*DK];
__device__ float g_ksum[NB*NH*DK];
__device__ float g_ksump[NB*NH*8*DK];
__device__ float g_y2[(long long)PAIR_CAP*DM];
__device__ int   g_topk_idx[NTOK*2];
__device__ float g_topk_w [NTOK*2];
__device__ int   g_counts[NE];
__device__ int   g_cursor[NE];
__device__ int   g_off[NE+1];
__device__ int   g_tile_e[NTILE72];
__device__ int   g_tok[PAIR_CAP];
__device__ int   g_pair_pos[NTOK*2];

// ---------------- HL (interleaved hi/lo fp16) scratch, word units ----------------
// row of K elements = K words: per 8-pair group, stored word 2*pperm(p)+s (s=0 hi,1 lo)
__device__ unsigned g_xn1u[NTOK*DM];
__device__ unsigned g_qu  [NTOK*DM];
__device__ unsigned g_ku  [NTOK*DM];
__device__ unsigned g_vTu [DM*NTOK];
__device__ unsigned g_pu  [(long long)NB*NH*SEQ*SEQ];
__device__ unsigned g_actu[NTOK*DM];
__device__ unsigned g_dlu [NTOK*DM];
__device__ unsigned g_xn2u[NTOK*DM];
__device__ unsigned g_h1u [(long long)PAIR_CAP*DFF];
__device__ unsigned g_wu  [8LL*WSZ];
__device__ unsigned g_e1u [8LL*DM*DFF];
__device__ unsigned g_e2u [8LL*DFF*DM];

struct MD {
    const unsigned* a[6];
    float* f[6]; unsigned* h[6];
    int ldc[6]; int cT[6];
};

// ---------------- perm helpers ----------------
__device__ __forceinline__ int pperm(int p){ return ((p&3)<<1) | (p>>2); }
__device__ __forceinline__ int pinv(int w){ return (w>>1) | ((w&1)<<2); }
// word index (within row) of hi word for logical pair p
__device__ __forceinline__ int hlw(int p){ return 2*(p & ~7) + 2*pperm(p & 7); }

// ---------------- low-level ----------------
__device__ __forceinline__ void mma_f16(float* d,
        unsigned a0, unsigned a1, unsigned a2, unsigned a3,
        unsigned b0, unsigned b1){
    asm volatile("mma.sync.aligned.m16n8k16.row.col.f32.f16.f16.f32 "
        "{%0,%1,%2,%3}, {%4,%5,%6,%7}, {%8,%9}, {%0,%1,%2,%3};"
        : "+f"(d[0]),"+f"(d[1]),"+f"(d[2]),"+f"(d[3])
        : "r"(a0),"r"(a1),"r"(a2),"r"(a3),"r"(b0),"r"(b1));
}
__device__ __forceinline__ unsigned packh(__half x, __half y){
    return (unsigned)__half_as_ushort(x) | ((unsigned)__half_as_ushort(y) << 16);
}
__device__ __forceinline__ void split2(float x, float y, unsigned& hi, unsigned& lo){
    __half hx = __float2half_rn(x), hy = __float2half_rn(y);
    __half lx = __float2half_rn(x - __half2float(hx));
    __half ly = __float2half_rn(y - __half2float(hy));
    hi = packh(hx, hy);
    lo = packh(lx, ly);
}
__device__ __forceinline__ void cp16(unsigned saddr, const void* g, bool v){
    asm volatile("cp.async.ca.shared.global [%0], [%1], 16, %2;"
        :: "r"(saddr), "l"(g), "r"(v ? 16 : 0));
}

__device__ __forceinline__ float warpSum(float v){
    #pragma unroll
    for (int o=16;o;o>>=1) v += __shfl_xor_sync(0xffffffffu, v, o);
    return v;
}
__device__ __forceinline__ float warpMax(float v){
    #pragma unroll
    for (int o=16;o;o>>=1) v = fmaxf(v, __shfl_xor_sync(0xffffffffu, v, o));
    return v;
}
__device__ __forceinline__ float blockSum(float v, float* red){
    v = warpSum(v);
    if ((threadIdx.x & 31) == 0) red[threadIdx.x>>5] = v;
    __syncthreads();
    if (threadIdx.x < 32) {
        float t = (threadIdx.x < 8) ? red[threadIdx.x] : 0.f;
        t = warpSum(t);
        if (threadIdx.x == 0) red[0] = t;
    }
    __syncthreads();
    float r = red[0];
    __syncthreads();
    return r;
}
__device__ __forceinline__ float blockMax(float v, float* red){
    v = warpMax(v);
    if ((threadIdx.x & 31) == 0) red[threadIdx.x>>5] = v;
    __syncthreads();
    if (threadIdx.x < 32) {
        float t = (threadIdx.x < 8) ? red[threadIdx.x] : -3.0e38f;
        t = warpMax(t);
        if (threadIdx.x == 0) red[0] = t;
    }
    __syncthreads();
    float r = red[0];
    __syncthreads();
    return r;
}

// ---------------- weight transpose + split -> HL ----------------
struct WP8 { const float* p[8]; };

__device__ __forceinline__ void hl_store1(unsigned* rowbuf, int k, float v){
    __half h = __float2half_rn(v);
    __half l = __float2half_rn(v - __half2float(h));
    int W = hlw(k >> 1);
    ((__half*)(rowbuf + W    ))[k & 1] = h;
    ((__half*)(rowbuf + W + 1))[k & 1] = l;
}

__global__ void wsplit8_kernel(WP8 wp, unsigned* __restrict__ oB){
    __shared__ float ts[32][33];
    int mat = blockIdx.z;
    const float* W = wp.p[mat];
    unsigned* o = oB + (long long)mat*WSZ;
    int k0 = blockIdx.y*32, n0 = blockIdx.x*32;
    int tx = threadIdx.x, ty = threadIdx.y;
    #pragma unroll
    for (int i=0;i<4;i++)
        ts[ty+8*i][tx] = W[(long long)(k0+ty+8*i)*DM + n0 + tx];
    __syncthreads();
    #pragma unroll
    for (int i=0;i<4;i++){
        int n = n0 + ty + 8*i, k = k0 + tx;
        hl_store1(o + (long long)n*DM, k, ts[tx][ty+8*i]);
    }
}

__global__ void wsplit_kernel(const float* __restrict__ W,
                              unsigned* __restrict__ o, int K, int N){
    __shared__ float ts[32][33];
    W += (long long)blockIdx.z * K * N;
    o += (long long)blockIdx.z * K * N;
    int k0 = blockIdx.y*32, n0 = blockIdx.x*32;
    int tx = threadIdx.x, ty = threadIdx.y;
    #pragma unroll
    for (int i=0;i<4;i++)
        ts[ty+8*i][tx] = W[(long long)(k0+ty+8*i)*N + n0 + tx];
    __syncthreads();
    #pragma unroll
    for (int i=0;i<4;i++){
        int n = n0 + ty + 8*i, k = k0 + tx;
        hl_store1(o + (long long)n*K, k, ts[tx][ty+8*i]);
    }
}

// ---------------- layernorm (fp32 + HL out) ----------------
__global__ __launch_bounds__(256) void ln_kernel(const float* __restrict__ x,
                                                 const float* __restrict__ g,
                                                 const float* __restrict__ b,
                                                 float* __restrict__ y,
                                                 unsigned* __restrict__ yu){
    __shared__ float row[DM];
    __shared__ float red[8];
    long long base = (long long)blockIdx.x * DM;
    float s = 0.f;
    for (int i = threadIdx.x; i < DM; i += 256) { float v = x[base+i]; row[i] = v; s += v; }
    s = blockSum(s, red);
    float mu = s * (1.f/DM);
    float vs = 0.f;
    for (int i = threadIdx.x; i < DM; i += 256) { float d = row[i]-mu; vs += d*d; }
    vs = blockSum(vs, red);
    float rstd = rsqrtf(vs * (1.f/DM) + 1e-5f);
    unsigned* ob = yu + base;
    for (int i2 = threadIdx.x; i2 < DM/2; i2 += 256){
        int i = i2*2;
        float v0 = (row[i  ]-mu)*rstd*g[i  ] + b[i  ];
        float v1 = (row[i+1]-mu)*rstd*g[i+1] + b[i+1];
        if (y){ y[base+i] = v0; y[base+i+1] = v1; }
        unsigned h,l; split2(v0,v1,h,l);
        *(uint2*)&ob[hlw(i2)] = make_uint2(h,l);
    }
}

// ---------------- fp16x3 GEMM on HL operands, LDS.128 fragments ----------------
template<int NTILES>
__global__ __launch_bounds__(256,2) void gemm_hh_kernel(
    const unsigned* __restrict__ A, const unsigned* __restrict__ B,
    float* __restrict__ Cf, unsigned* __restrict__ Ch,
    int M, int N, int K, int ldaw, int ldbw, int ldc,
    int innerN,
    long long sAo, long long sAi, long long sBo, long long sBi,
    long long sCo, long long sCi,
    const int* __restrict__ rowIdx, const int* __restrict__ tileExpert,
    long long expSB, float alpha, int actMode, int cT,
    MD md, int nMulti,
    const int* __restrict__ moeOff, const int* __restrict__ moeCnt)
{
    __shared__ unsigned As[3][128][16];
    __shared__ unsigned Bs[3][128][16];

    int z  = blockIdx.z;
    int zo = z / innerN, zi = z - zo*innerN;
    if (nMulti > 0){
        A = md.a[zi];
        Cf = md.f[zi]; Ch = md.h[zi];
        ldc = md.ldc[zi]; cT = md.cT[zi];
    }
    const int tm0 = blockIdx.y * 128;
    const int tn0 = blockIdx.x * (NTILES*16);
    // MoE pad-tile skip
    if (moeCnt){
        int e = tileExpert[blockIdx.y];
        if (tm0 >= moeOff[e] + moeCnt[e]) return;
    }
    A += zo*sAo + zi*sAi;
    long long boff = zo*sBo + zi*sBi;
    if (tileExpert) boff += (long long)tileExpert[blockIdx.y] * expSB;
    B += boff;
    long long coff = zo*sCo + zi*sCi;

    const int tid = threadIdx.x;
    const int lane = tid & 31;
    const int warp = tid >> 5;
    const int wm = (warp & 3) * 32;
    const int wn = (warp >> 2) * (NTILES*8);
    const int g = lane >> 2;
    const int q = lane & 3;

    const int lrow = tid >> 1;
    const int lsel = tid & 1;

    int grow = tm0 + lrow;
    bool aval = grow < M;
    int srcRow = aval ? (rowIdx ? (rowIdx[grow] & (NTOK-1)) : grow) : 0;
    const unsigned* Ap = A + (long long)srcRow * ldaw + lsel*8;
    bool bval = (tn0 + lrow) < N;
    int brow = bval ? (tn0 + lrow) : 0;
    const unsigned* Bp = B + (long long)brow * ldbw + lsel*8;

    unsigned base_off = (unsigned)((lrow*16 + lsel*8)*4);
    unsigned aS = (unsigned)__cvta_generic_to_shared(&As[0][0][0]) + base_off;
    unsigned bS = (unsigned)__cvta_generic_to_shared(&Bs[0][0][0]) + base_off;

    float acc[2][NTILES][4];
    #pragma unroll
    for (int mi=0;mi<2;mi++)
        #pragma unroll
        for (int ni=0;ni<NTILES;ni++)
            #pragma unroll
            for (int t=0;t<4;t++) acc[mi][ni][t]=0.f;

    const int nt = K >> 4;

    #define ISSUE(T) do{                                     \
        int _t = (T);                                         \
        if (_t < nt){                                         \
            unsigned _bo = (unsigned)((_t % 3) * 8192);       \
            int _kn = _t * 16;                                \
            cp16(aS + _bo,      Ap + _kn,     aval);          \
            cp16(aS + _bo + 16, Ap + _kn + 4, aval);          \
            cp16(bS + _bo,      Bp + _kn,     bval);          \
            cp16(bS + _bo + 16, Bp + _kn + 4, bval);          \
        }                                                     \
        asm volatile("cp.async.commit_group;");               \
    }while(0)

    ISSUE(0);
    ISSUE(1);

    int buf = 0;
    for (int k = 0; k < nt; k++){
        asm volatile("cp.async.wait_group 1;");
        __syncthreads();
        ISSUE(k+2);
        {
            uint4 a1[2], a2[2];
            #pragma unroll
            for (int mi = 0; mi < 2; mi++){
                int row = wm + mi*16 + g;
                a1[mi] = *(const uint4*)&As[buf][row  ][4*q];
                a2[mi] = *(const uint4*)&As[buf][row+8][4*q];
            }
            #pragma unroll
            for (int ni = 0; ni < NTILES; ni++){
                int col = wn + ni*8 + g;
                uint4 bb = *(const uint4*)&Bs[buf][col][4*q];
                #pragma unroll
                for (int mi = 0; mi < 2; mi++){
                    mma_f16(acc[mi][ni], a1[mi].x, a2[mi].x, a1[mi].z, a2[mi].z, bb.x, bb.z);
                    mma_f16(acc[mi][ni], a1[mi].x, a2[mi].x, a1[mi].z, a2[mi].z, bb.y, bb.w);
                    mma_f16(acc[mi][ni], a1[mi].y, a2[mi].y, a1[mi].w, a2[mi].w, bb.x, bb.z);
                }
            }
        }
        buf = (buf == 2) ? 0 : buf + 1;
    }
    #undef ISSUE

    float* CfP = Cf ? (Cf + coff) : (float*)0;
    unsigned* ChP = Ch ? (Ch + coff) : (unsigned*)0;
    #pragma unroll
    for (int mi = 0; mi < 2; mi++){
        #pragma unroll
        for (int rr = 0; rr < 2; rr++){
            int row = tm0 + wm + mi*16 + g + rr*8;
            if (row >= M) continue;
            #pragma unroll
            for (int ni = 0; ni < NTILES; ni++){
                int col = tn0 + wn + ni*8 + q*2;
                if (col >= N) continue;
                float v0 = acc[mi][ni][rr*2+0] * alpha;
                float v1 = acc[mi][ni][rr*2+1] * alpha;
                if (actMode == 1){
                    v0 = 0.5f * v0 * (1.f + erff(v0 * 0.70710678118654752f));
                    v1 = 0.5f * v1 * (1.f + erff(v1 * 0.70710678118654752f));
                }
                if (!cT){
                    if (CfP) *(float2*)&CfP[(long long)row*ldc + col] = make_float2(v0, v1);
                    if (ChP){
                        unsigned h,l; split2(v0,v1,h,l);
                        *(uint2*)&ChP[(long long)row*ldc + hlw(col>>1)] = make_uint2(h,l);
                    }
                } else {
                    // transposed half out: out row = col, k element = row
                    int W = hlw(row >> 1);
                    int hs = row & 1;
                    {
                        __half h0 = __float2half_rn(v0);
                        unsigned* p = ChP + (long long)col*ldc;
                        ((__half*)(p + W    ))[hs] = h0;
                        ((__half*)(p + W + 1))[hs] = __float2half_rn(v0 - __half2float(h0));
                    }
                    if (col + 1 < N){
                        __half h1 = __float2half_rn(v1);
                        unsigned* p = ChP + (long long)(col+1)*ldc;
                        ((__half*)(p + W    ))[hs] = h1;
                        ((__half*)(p + W + 1))[hs] = __float2half_rn(v1 - __half2float(h1));
                    }
                }
            }
        }
    }
}

// ---------------- masked row softmax on HL rows (in place) ----------------
__global__ __launch_bounds__(256) void softmax_kernel(const int* __restrict__ mask,
                                                      unsigned* __restrict__ P){
    long long r = blockIdx.x;
    int qq = (int)(r & 1023);
    int b = (int)(r >> 14);
    const int* mr = mask + ((long long)b << 20) + ((long long)qq << 10);
    unsigned* row32 = P + (r << 10);
    __shared__ float buf[SEQ];
    __shared__ float red[8];
    float mx = -3.0e38f;
    for (int j = threadIdx.x; j < SEQ/2; j += 256){
        int lp = (j & ~7) | pinv(j & 7);
        uint2 u = *(uint2*)&row32[2*j];
        __half2 hv = *(__half2*)&u.x;
        __half2 lv = *(__half2*)&u.y;
        float v0 = __half2float(hv.x) + __half2float(lv.x);
        float v1 = __half2float(hv.y) + __half2float(lv.y);
        if (mr[2*lp  ] == 0) v0 = -1e9f;
        if (mr[2*lp+1] == 0) v1 = -1e9f;
        buf[2*lp  ] = v0;
        buf[2*lp+1] = v1;
        mx = fmaxf(mx, fmaxf(v0, v1));
    }
    mx = blockMax(mx, red);
    float sum = 0.f;
    for (int i = threadIdx.x; i < SEQ; i += 256){
        float e = expf(buf[i]-mx);
        buf[i] = e; sum += e;
    }
    sum = blockSum(sum, red);
    float inv = 1.f / sum;
    for (int j = threadIdx.x; j < SEQ/2; j += 256){
        int lp = (j & ~7) | pinv(j & 7);
        unsigned h,l; split2(buf[2*lp]*inv, buf[2*lp+1]*inv, h, l);
        *(uint2*)&row32[2*j] = make_uint2(h,l);
    }
}

// ---------------- delta branch ----------------
__global__ __launch_bounds__(256) void ctx1_kernel(const float* __restrict__ kd,
                                                   const float* __restrict__ vd,
                                                   float* __restrict__ ctxp){
    int z = blockIdx.x >> 2;
    int chunk = blockIdx.x & 3;
    int b = z >> 4, h = z & 15;
    const float* kbase = kd + ((long long)b*SEQ)*DM + h*DK;
    const float* vbase = vd + ((long long)b*SEQ)*DM + h*DK;
    __shared__ float ks[64][65];
    __shared__ float vs[64][65];
    int tid = threadIdx.x;
    int d0 = (tid >> 4) << 2;
    int e0 = (tid & 15) << 2;
    float acc[4][4];
    #pragma unroll
    for (int i=0;i<4;i++)
        #pragma unroll
        for (int j=0;j<4;j++) acc[i][j]=0.f;

    for (int s0 = chunk*256; s0 < chunk*256+256; s0 += 64) {
        for (int t = tid; t < 64*16; t += 256) {
            int rr = t >> 4; int cc = (t & 15) << 2;
            float4 kv = *(const float4*)(kbase + (long long)(s0+rr)*DM + cc);
            float4 vv = *(const float4*)(vbase + (long long)(s0+rr)*DM + cc);
            ks[rr][cc+0]=kv.x; ks[rr][cc+1]=kv.y; ks[rr][cc+2]=kv.z; ks[rr][cc+3]=kv.w;
            vs[rr][cc+0]=vv.x; vs[rr][cc+1]=vv.y; vs[rr][cc+2]=vv.z; vs[rr][cc+3]=vv.w;
        }
        __syncthreads();
        #pragma unroll 4
        for (int ss=0; ss<64; ss++){
            float kr[4], vr[4];
            #pragma unroll
            for (int i=0;i<4;i++) kr[i]=ks[ss][d0+i];
            #pragma unroll
            for (int j=0;j<4;j++) vr[j]=vs[ss][e0+j];
            #pragma unroll
            for (int i=0;i<4;i++)
                #pragma unroll
                for (int j=0;j<4;j++) acc[i][j] += kr[i]*vr[j];
        }
        __syncthreads();
    }
    float* cbase = ctxp + ((long long)z*4 + chunk)*DK*DK;
    #pragma unroll
    for (int i=0;i<4;i++)
        #pragma unroll
        for (int j=0;j<4;j++)
            cbase[(d0+i)*DK + e0+j] = acc[i][j];
}

__global__ void ctx2_kernel(const float* __restrict__ ctxp, float* __restrict__ ctx){
    int z = blockIdx.x;
    const float* p = ctxp + (long long)z*4*DK*DK;
    float* o = ctx + (long long)z*DK*DK;
    for (int i = threadIdx.x; i < DK*DK; i += 256)
        o[i] = p[i] + p[DK*DK + i] + p[2*DK*DK + i] + p[3*DK*DK + i];
}

__global__ void ksum1_kernel(const float* __restrict__ kd, float* __restrict__ ksump){
    int z = blockIdx.x >> 3;
    int c = blockIdx.x & 7;
    int b = z >> 4, h = z & 15;
    int d = threadIdx.x;
    const float* base = kd + ((long long)(b*SEQ + c*128))*DM + h*DK + d;
    float s = 0.f;
    #pragma unroll 4
    for (int ss=0; ss<128; ss++) s += fmaxf(base[(long long)ss*DM], 0.f);
    ksump[(z*8 + c)*DK + d] = s;
}

__global__ void ksum2_kernel(const float* __restrict__ ksump, float* __restrict__ ksum){
    int z = blockIdx.x;
    int d = threadIdx.x;
    float s = 0.f;
    #pragma unroll
    for (int c=0;c<8;c++) s += ksump[(z*8 + c)*DK + d];
    ksum[z*DK + d] = s;
}

__global__ __launch_bounds__(256) void delta_kernel(const float* __restrict__ qd,
                                                    const float* __restrict__ ctx,
                                                    const float* __restrict__ ksum,
                                                    unsigned* __restrict__ du){
    int z = blockIdx.x >> 2;
    int sc = blockIdx.x & 3;
    int b = z >> 4, h = z & 15;
    __shared__ float cs[DK*DK];
    __shared__ float kss[DK];
    for (int i = threadIdx.x; i < DK*DK; i += 256) cs[i] = ctx[(long long)z*DK*DK + i];
    if (threadIdx.x < DK) kss[threadIdx.x] = ksum[z*DK + threadIdx.x];
    __syncthreads();
    int s = sc*256 + threadIdx.x;
    const float* qrow = qd + ((long long)(b*SEQ + s))*DM + h*DK;
    float q[DK];
    #pragma unroll
    for (int d=0; d<DK; d+=4){
        float4 v = *(const float4*)(qrow + d);
        q[d+0]=fmaxf(v.x,0.f); q[d+1]=fmaxf(v.y,0.f);
        q[d+2]=fmaxf(v.z,0.f); q[d+3]=fmaxf(v.w,0.f);
    }
    float zv = 1e-6f;
    #pragma unroll
    for (int d=0; d<DK; d++) zv += q[d]*kss[d];
    float invz = 1.f / zv;
    unsigned* ob = du + ((long long)(b*SEQ + s))*DM + h*DK;
    for (int e=0; e<DK; e+=2){
        float a0 = 0.f, a1 = 0.f;
        #pragma unroll
        for (int d=0; d<DK; d++){
            a0 += q[d]*cs[d*DK + e];
            a1 += q[d]*cs[d*DK + e+1];
        }
        unsigned hh,ll; split2(a0*invz, a1*invz, hh, ll);
        *(uint2*)&ob[hlw(e>>1)] = make_uint2(hh,ll);
    }
}

// ---------------- gate / combine / router / final ----------------
__global__ __launch_bounds__(256) void gate_kernel(const float* __restrict__ xn,
                                                   const float* __restrict__ wg,
                                                   float* __restrict__ gate){
    int t = blockIdx.x;
    float p0=0.f, p1=0.f;
    for (int k = threadIdx.x; k < DM; k += 256){
        float xv = xn[(long long)t*DM + k];
        p0 += xv*wg[k*2+0];
        p1 += xv*wg[k*2+1];
    }
    __shared__ float red[8];
    p0 = blockSum(p0, red);
    p1 = blockSum(p1, red);
    if (threadIdx.x == 0){
        float m = fmaxf(p0,p1);
        float e0 = expf(p0-m), e1 = expf(p1-m);
        float inv = 1.f/(e0+e1);
        gate[t*2+0] = e0*inv;
        gate[t*2+1] = e1*inv;
    }
}

__global__ void combine1_kernel(const float* __restrict__ x,
                                const float* __restrict__ dense,
                                const float* __restrict__ delta,
                                const float* __restrict__ gate,
                                float* __restrict__ x1){
    long long i = (long long)blockIdx.x*256 + threadIdx.x;
    int t = (int)(i >> 10);
    x1[i] = x[i] + gate[t*2]*dense[i] + gate[t*2+1]*delta[i];
}

__global__ __launch_bounds__(256) void router_kernel(const float* __restrict__ xn2,
                                                     const float* __restrict__ wr,
                                                     int* __restrict__ topk_idx,
                                                     float* __restrict__ topk_w,
                                                     int* __restrict__ counts){
    int t = blockIdx.x;
    float p[NE];
    #pragma unroll
    for (int e=0;e<NE;e++) p[e]=0.f;
    for (int k = threadIdx.x; k < DM; k += 256){
        float xv = xn2[(long long)t*DM + k];
        #pragma unroll
        for (int e=0;e<NE;e++) p[e] += xv*wr[k*NE + e];
    }
    __shared__ float part[NE][8];
    int w = threadIdx.x >> 5;
    #pragma unroll
    for (int e=0;e<NE;e++){
        float v = warpSum(p[e]);
        if ((threadIdx.x & 31)==0) part[e][w] = v;
    }
    __syncthreads();
    if (threadIdx.x == 0){
        float lg[NE];
        for (int e=0;e<NE;e++){
            float s=0.f;
            for (int ww=0; ww<8; ww++) s += part[e][ww];
            lg[e]=s;
        }
        int i0=0; float v0=lg[0];
        for (int e=1;e<NE;e++) if (lg[e]>v0){v0=lg[e];i0=e;}
        int i1=-1; float v1=-3.0e38f;
        for (int e=0;e<NE;e++) if (e!=i0 && lg[e]>v1){v1=lg[e];i1=e;}
        float e1 = expf(v1-v0);
        float inv = 1.f/(1.f+e1);
        topk_idx[t*2+0]=i0; topk_idx[t*2+1]=i1;
        topk_w[t*2+0]=inv;  topk_w[t*2+1]=e1*inv;
        atomicAdd(&counts[i0],1); atomicAdd(&counts[i1],1);
    }
}

__global__ void prep_kernel(int* counts, int* cursor, int* tok){
    int i = blockIdx.x*256 + threadIdx.x;
    if (i < NE){ counts[i]=0; cursor[i]=0; }
    if (i < PAIR_CAP) tok[i]=0;
}

__global__ void scan_kernel(const int* counts, int* off, int* tile_e){
    if (threadIdx.x==0 && blockIdx.x==0){
        int o = 0;
        off[0]=0;
        for (int e=0;e<NE;e++){ o += (counts[e]+127)&~127; off[e+1]=o; }
        for (int t=0;t<NTILE72;t++){
            int row = t*128;
            int ee = NE-1;
            for (int i=0;i<NE;i++){ if (row < off[i+1]) { ee=i; break; } }
            tile_e[t]=ee;
        }
    }
}

__global__ void place_kernel(const int* __restrict__ topk_idx,
                             const int* __restrict__ off,
                             int* cursor, int* tok, int* pair_pos){
    int t = blockIdx.x*256 + threadIdx.x;
    if (t >= NTOK) return;
    for (int k=0;k<2;k++){
        int e = topk_idx[t*2+k];
        int pos = atomicAdd(&cursor[e],1);
        int r = off[e] + pos;
        tok[r] = t;
        pair_pos[t*2+k] = r;
    }
}

__global__ void final_kernel(const float* __restrict__ x1,
                             const float* __restrict__ y2,
                             const float* __restrict__ topk_w,
                             const int* __restrict__ pair_pos,
                             float* __restrict__ out){
    long long i = (long long)blockIdx.x*256 + threadIdx.x;
    int t = (int)(i >> 10);
    int c = (int)(i & 1023);
    int p0 = pair_pos[t*2+0], p1 = pair_pos[t*2+1];
    out[i] = x1[i] + topk_w[t*2+0]*y2[(long long)p0*DM + c]
                   + topk_w[t*2+1]*y2[(long long)p1*DM + c];
}

// ---------------- host side ----------------
static void gemm(const unsigned* A, const unsigned* B,
                 float* Cf, unsigned* Ch,
                 int M, int N, int K, int ldaw, int ldbw, int ldc,
                 int batch, int innerN,
                 long long sAo, long long sAi, long long sBo, long long sBi,
                 long long sCo, long long sCi,
                 const int* rowIdx, const int* tileE, long long expSB,
                 float alpha, int act, int cT,
                 int bn64, const MD& md, int nMulti,
                 const int* moeOff, const int* moeCnt){
    if (bn64){
        dim3 grid((N+63)/64, (M+127)/128, batch);
        gemm_hh_kernel<4><<<grid, 256>>>(A,B,Cf,Ch,M,N,K,ldaw,ldbw,ldc,innerN,
                                         sAo,sAi,sBo,sBi,sCo,sCi,
                                         rowIdx,tileE,expSB,alpha,act,cT,md,nMulti,
                                         moeOff,moeCnt);
    } else {
        dim3 grid((N+127)/128, (M+127)/128, batch);
        gemm_hh_kernel<8><<<grid, 256>>>(A,B,Cf,Ch,M,N,K,ldaw,ldbw,ldc,innerN,
                                         sAo,sAi,sBo,sBi,sCo,sCi,
                                         rowIdx,tileE,expSB,alpha,act,cT,md,nMulti,
                                         moeOff,moeCnt);
    }
}

extern "C" void kernel_launch(void* const* d_in, const int* in_sizes, int n_in,
                              void* d_out, int out_size){
    const float* x        = (const float*)d_in[0];
    const int*   mask     = (const int*)  d_in[1];
    const float* ln1_g    = (const float*)d_in[2];
    const float* ln1_b    = (const float*)d_in[3];
    const float* wq       = (const float*)d_in[4];
    const float* wk       = (const float*)d_in[5];
    const float* wv       = (const float*)d_in[6];
    const float* wo       = (const float*)d_in[7];
    const float* wqd      = (const float*)d_in[8];
    const float* wkd      = (const float*)d_in[9];
    const float* wvd      = (const float*)d_in[10];
    const float* wod      = (const float*)d_in[11];
    const float* w_gate   = (const float*)d_in[12];
    const float* ln2_g    = (const float*)d_in[13];
    const float* ln2_b    = (const float*)d_in[14];
    const float* w_router = (const float*)d_in[15];
    const float* e_w1     = (const float*)d_in[16];
    const float* e_w2     = (const float*)d_in[17];
    float* out = (float*)d_out;

    float *xn1,*qd,*kd,*vd,*dense_o,*delta_o,*gate,*x1,*xn2,*ctx,*ctxp,*ksum,*ksump,*y2,*topk_w;
    int *topk_idx,*counts,*cursor,*off,*tile_e,*tok,*pair_pos;
    unsigned *xn1u,*qu,*ku,*vTu,*pu,*actu,*dlu,*xn2u,*h1u,*wu,*e1u,*e2u;

    cudaGetSymbolAddress((void**)&xn1,     g_xn1);
    cudaGetSymbolAddress((void**)&qd,      g_qd);
    cudaGetSymbolAddress((void**)&kd,      g_kd);
    cudaGetSymbolAddress((void**)&vd,      g_vd);
    cudaGetSymbolAddress((void**)&dense_o, g_dense_o);
    cudaGetSymbolAddress((void**)&delta_o, g_delta_o);
    cudaGetSymbolAddress((void**)&gate,    g_gate);
    cudaGetSymbolAddress((void**)&x1,      g_x1);
    cudaGetSymbolAddress((void**)&xn2,     g_xn2);
    cudaGetSymbolAddress((void**)&ctx,     g_ctx);
    cudaGetSymbolAddress((void**)&ctxp,    g_ctxp);
    cudaGetSymbolAddress((void**)&ksum,    g_ksum);
    cudaGetSymbolAddress((void**)&ksump,   g_ksump);
    cudaGetSymbolAddress((void**)&y2,      g_y2);
    cudaGetSymbolAddress((void**)&topk_w,  g_topk_w);
    cudaGetSymbolAddress((void**)&topk_idx,g_topk_idx);
    cudaGetSymbolAddress((void**)&counts,  g_counts);
    cudaGetSymbolAddress((void**)&cursor,  g_cursor);
    cudaGetSymbolAddress((void**)&off,     g_off);
    cudaGetSymbolAddress((void**)&tile_e,  g_tile_e);
    cudaGetSymbolAddress((void**)&tok,     g_tok);
    cudaGetSymbolAddress((void**)&pair_pos,g_pair_pos);
    cudaGetSymbolAddress((void**)&xn1u,    g_xn1u);
    cudaGetSymbolAddress((void**)&qu,      g_qu);
    cudaGetSymbolAddress((void**)&ku,      g_ku);
    cudaGetSymbolAddress((void**)&vTu,     g_vTu);
    cudaGetSymbolAddress((void**)&pu,      g_pu);
    cudaGetSymbolAddress((void**)&actu,    g_actu);
    cudaGetSymbolAddress((void**)&dlu,     g_dlu);
    cudaGetSymbolAddress((void**)&xn2u,    g_xn2u);
    cudaGetSymbolAddress((void**)&h1u,     g_h1u);
    cudaGetSymbolAddress((void**)&wu,      g_wu);
    cudaGetSymbolAddress((void**)&e1u,     g_e1u);
    cudaGetSymbolAddress((void**)&e2u,     g_e2u);

    const long long TOKD = (long long)SEQ*DM;
    MD md0; memset(&md0, 0, sizeof(md0));

    // 0: LN1
    ln_kernel<<<NTOK,256>>>(x, ln1_g, ln1_b, xn1, xn1u);
    // 1: dense weight splits — wq wk wv wqd wkd wvd | wo wod
    WP8 wp;
    wp.p[0]=wq; wp.p[1]=wk; wp.p[2]=wv; wp.p[3]=wqd;
    wp.p[4]=wkd; wp.p[5]=wvd; wp.p[6]=wo; wp.p[7]=wod;
    wsplit8_kernel<<<dim3(32,32,8), dim3(32,8)>>>(wp, wu);
    // 2: expert w1 split
    wsplit_kernel<<<dim3(DFF/32, DM/32, NE), dim3(32,8)>>>(e_w1, e1u, DM, DFF);

    // 3: all 6 projections, one batched launch  <-- ncu target
    {
        MD md; memset(&md, 0, sizeof(md));
        for (int z=0; z<6; z++){ md.a[z]=xn1u; md.ldc[z]=DM; md.cT[z]=0; }
        md.h[0]=qu;
        md.h[1]=ku;
        md.h[2]=vTu; md.ldc[2]=NTOK; md.cT[2]=1;
        md.f[3]=qd;
        md.f[4]=kd;
        md.f[5]=vd;
        gemm(xn1u, wu, 0,0,
             NTOK,DM,DM, DM,DM,DM, 6,6,
             0,0, 0,WSZ, 0,0,
             0,0,0, 1.f,0,0, 0, md, 6, 0,0);
    }

    // scores = Q @ K^T / 8 -> HL
    gemm(qu, ku, 0,pu, SEQ,SEQ,DK, DM,DM,SEQ,
         NB*NH, NH,
         TOKD, DK,  TOKD, DK,  (long long)NH*SEQ*SEQ, (long long)SEQ*SEQ,
         0,0,0, 0.125f,0,0, 0, md0, 0, 0,0);

    // masked softmax in place
    softmax_kernel<<<NB*NH*SEQ, 256>>>(mask, pu);

    // attnctx = P @ V (BN=64) -> HL natural
    gemm(pu, vTu, 0,actu, SEQ,DK,SEQ, SEQ,NTOK,DM,
         NB*NH, NH,
         (long long)NH*SEQ*SEQ, (long long)SEQ*SEQ,  SEQ, (long long)DK*NTOK,
         TOKD, DK,
         0,0,0, 1.f,0,0, 1, md0, 0, 0,0);

    // delta branch
    ctx1_kernel<<<NB*NH*4, 256>>>(kd, vd, ctxp);
    ctx2_kernel<<<NB*NH, 256>>>(ctxp, ctx);
    ksum1_kernel<<<NB*NH*8, 64>>>(kd, ksump);
    ksum2_kernel<<<NB*NH, 64>>>(ksump, ksum);
    delta_kernel<<<NB*NH*4, 256>>>(qd, ctx, ksum, dlu);

    // output projections, batched 2
    {
        MD md; memset(&md, 0, sizeof(md));
        md.a[0]=actu; md.f[0]=dense_o; md.ldc[0]=DM; md.cT[0]=0;
        md.a[1]=dlu;  md.f[1]=delta_o; md.ldc[1]=DM; md.cT[1]=0;
        gemm(actu, wu+6LL*WSZ, 0,0,
             NTOK,DM,DM, DM,DM,DM, 2,2,
             0,0, 0,WSZ, 0,0,
             0,0,0, 1.f,0,0, 0, md, 2, 0,0);
    }

    // gate + combine
    gate_kernel<<<NTOK,256>>>(xn1, w_gate, gate);
    combine1_kernel<<<NTOK*DM/256, 256>>>(x, dense_o, delta_o, gate, x1);

    // LN2
    ln_kernel<<<NTOK,256>>>(x1, ln2_g, ln2_b, xn2, xn2u);

    // routing
    prep_kernel<<<(PAIR_CAP+255)/256, 256>>>(counts, cursor, tok);
    router_kernel<<<NTOK, 256>>>(xn2, w_router, topk_idx, topk_w, counts);
    scan_kernel<<<1,32>>>(counts, off, tile_e);
    place_kernel<<<(NTOK+255)/256, 256>>>(topk_idx, off, cursor, tok, pair_pos);

    // expert w2 split
    wsplit_kernel<<<dim3(DM/32, DFF/32, NE), dim3(32,8)>>>(e_w2, e2u, DFF, DM);

    // expert GEMM1 (gathered, gelu) -> h1 HL ; pad tiles skipped
    gemm(xn2u, e1u, 0,h1u, PAIR_CAP,DFF,DM, DM,DM,DFF,
         1,1, 0,0,0,0,0,0,
         tok, tile_e, (long long)DM*DFF, 1.f,1,0, 0, md0, 0, off, counts);

    // expert GEMM2 -> y2 fp32 ; pad tiles skipped
    gemm(h1u, e2u, y2,0, PAIR_CAP,DM,DFF, DFF,DFF,DM,
         1,1, 0,0,0,0,0,0,
         0, tile_e, (long long)DFF*DM, 1.f,0,0, 0, md0, 0, off, counts);

    // final combine
    final_kernel<<<NTOK*DM/256, 256>>>(x1, y2, topk_w, pair_pos, out);
}

// round 11
// speedup vs baseline: 2.5362x; 1.0128x over previous
#include <cuda_runtime.h>
#include <cuda_fp16.h>
#include <math.h>

#define NTOK 4096
#define DM   1024
#define DFF  2048
#define NH   16
#define DK   64
#define NB   4
#define SEQ  1024
#define NE   8
#define PAIR_CAP 9216
#define NTILE72  72
#define WSZ  (1024*1024)   // words per DMxDM weight

// ---------------- fp32 scratch ----------------
__device__ float g_qd [NTOK*DM];
__device__ float g_kd [NTOK*DM];
__device__ float g_vd [NTOK*DM];
__device__ float g_dense_o[NTOK*DM];
__device__ float g_delta_o[NTOK*DM];
__device__ float g_x1 [NTOK*DM];
__device__ float g_xn1[NTOK*DM];
__device__ float g_xn2[NTOK*DM];
__device__ float g_ctx [NB*NH*DK*DK];
__device__ float g_ctxp[NB*NH*4*DK*DK];
__device__ float g_ksum[NB*NH*DK];
__device__ float g_ksump[NB*NH*4*DK];
__device__ float g_y2[(long long)PAIR_CAP*DM];
__device__ int   g_topk_idx[NTOK*2];
__device__ float g_topk_w [NTOK*2];
__device__ int   g_counts[NE];
__device__ int   g_cursor[NE];
__device__ int   g_off[NE+1];
__device__ int   g_tile_e[NTILE72];
__device__ int   g_tok[PAIR_CAP];
__device__ int   g_pair_pos[NTOK*2];

// ---------------- HL (interleaved hi/lo fp16) scratch, word units ----------------
__device__ unsigned g_xn1u[NTOK*DM];
__device__ unsigned g_qu  [NTOK*DM];
__device__ unsigned g_ku  [NTOK*DM];
__device__ unsigned g_vTu [DM*NTOK];
__device__ unsigned g_pu  [(long long)NB*NH*SEQ*SEQ];
__device__ unsigned g_actu[NTOK*DM];
__device__ unsigned g_dlu [NTOK*DM];
__device__ unsigned g_xn2u[NTOK*DM];
__device__ unsigned g_h1u [(long long)PAIR_CAP*DFF];
__device__ unsigned g_wu  [8LL*WSZ];
__device__ unsigned g_e1u [8LL*DM*DFF];
__device__ unsigned g_e2u [8LL*DFF*DM];

struct MD {
    const unsigned* a[6];
    float* f[6]; unsigned* h[6];
    int ldc[6]; int cT[6];
};

// ---------------- perm helpers ----------------
__device__ __forceinline__ int pperm(int p){ return ((p&3)<<1) | (p>>2); }
__device__ __forceinline__ int pinv(int w){ return (w>>1) | ((w&1)<<2); }
// word index (within row) of hi word for logical pair p
__device__ __forceinline__ int hlw(int p){ return 2*(p & ~7) + 2*pperm(p & 7); }

// ---------------- low-level ----------------
__device__ __forceinline__ void mma_f16(float* d,
        unsigned a0, unsigned a1, unsigned a2, unsigned a3,
        unsigned b0, unsigned b1){
    asm volatile("mma.sync.aligned.m16n8k16.row.col.f32.f16.f16.f32 "
        "{%0,%1,%2,%3}, {%4,%5,%6,%7}, {%8,%9}, {%0,%1,%2,%3};"
        : "+f"(d[0]),"+f"(d[1]),"+f"(d[2]),"+f"(d[3])
        : "r"(a0),"r"(a1),"r"(a2),"r"(a3),"r"(b0),"r"(b1));
}
__device__ __forceinline__ unsigned packh(__half x, __half y){
    return (unsigned)__half_as_ushort(x) | ((unsigned)__half_as_ushort(y) << 16);
}
__device__ __forceinline__ void split2(float x, float y, unsigned& hi, unsigned& lo){
    __half hx = __float2half_rn(x), hy = __float2half_rn(y);
    __half lx = __float2half_rn(x - __half2float(hx));
    __half ly = __float2half_rn(y - __half2float(hy));
    hi = packh(hx, hy);
    lo = packh(lx, ly);
}
__device__ __forceinline__ void cp16(unsigned saddr, const void* g, bool v){
    asm volatile("cp.async.ca.shared.global [%0], [%1], 16, %2;"
        :: "r"(saddr), "l"(g), "r"(v ? 16 : 0));
}

__device__ __forceinline__ float warpSum(float v){
    #pragma unroll
    for (int o=16;o;o>>=1) v += __shfl_xor_sync(0xffffffffu, v, o);
    return v;
}
__device__ __forceinline__ float warpMax(float v){
    #pragma unroll
    for (int o=16;o;o>>=1) v = fmaxf(v, __shfl_xor_sync(0xffffffffu, v, o));
    return v;
}
__device__ __forceinline__ float blockSum(float v, float* red){
    v = warpSum(v);
    if ((threadIdx.x & 31) == 0) red[threadIdx.x>>5] = v;
    __syncthreads();
    if (threadIdx.x < 32) {
        float t = (threadIdx.x < 8) ? red[threadIdx.x] : 0.f;
        t = warpSum(t);
        if (threadIdx.x == 0) red[0] = t;
    }
    __syncthreads();
    float r = red[0];
    __syncthreads();
    return r;
}
__device__ __forceinline__ float blockMax(float v, float* red){
    v = warpMax(v);
    if ((threadIdx.x & 31) == 0) red[threadIdx.x>>5] = v;
    __syncthreads();
    if (threadIdx.x < 32) {
        float t = (threadIdx.x < 8) ? red[threadIdx.x] : -3.0e38f;
        t = warpMax(t);
        if (threadIdx.x == 0) red[0] = t;
    }
    __syncthreads();
    float r = red[0];
    __syncthreads();
    return r;
}

// ---------------- weight transpose + split -> HL (uint2 stores) ----------------
struct WP8 { const float* p[8]; };

__global__ void wsplit8_kernel(WP8 wp, unsigned* __restrict__ oB){
    __shared__ float ts[32][33];
    int mat = blockIdx.z;
    const float* W = wp.p[mat];
    unsigned* o = oB + (long long)mat*WSZ;
    int k0 = blockIdx.y*32, n0 = blockIdx.x*32;
    int tx = threadIdx.x, ty = threadIdx.y;   // 32 x 8
    #pragma unroll
    for (int i=0;i<4;i++)
        ts[ty+8*i][tx] = W[(long long)(k0+ty+8*i)*DM + n0 + tx];
    __syncthreads();
    int tid = ty*32 + tx;
    #pragma unroll
    for (int it=0; it<2; it++){
        int item = it*256 + tid;          // 0..511
        int n = item >> 4;                // 0..31
        int pr = item & 15;               // local k-pair 0..15
        unsigned h,l; split2(ts[2*pr][n], ts[2*pr+1][n], h, l);
        *(uint2*)&o[(long long)(n0+n)*DM + hlw((k0>>1)+pr)] = make_uint2(h,l);
    }
}

__global__ void wsplit_kernel(const float* __restrict__ W,
                              unsigned* __restrict__ o, int K, int N){
    __shared__ float ts[32][33];
    W += (long long)blockIdx.z * K * N;
    o += (long long)blockIdx.z * K * N;
    int k0 = blockIdx.y*32, n0 = blockIdx.x*32;
    int tx = threadIdx.x, ty = threadIdx.y;
    #pragma unroll
    for (int i=0;i<4;i++)
        ts[ty+8*i][tx] = W[(long long)(k0+ty+8*i)*N + n0 + tx];
    __syncthreads();
    int tid = ty*32 + tx;
    #pragma unroll
    for (int it=0; it<2; it++){
        int item = it*256 + tid;
        int n = item >> 4;
        int pr = item & 15;
        unsigned h,l; split2(ts[2*pr][n], ts[2*pr+1][n], h, l);
        *(uint2*)&o[(long long)(n0+n)*K + hlw((k0>>1)+pr)] = make_uint2(h,l);
    }
}

// ---------------- layernorm (fp32 + HL out) ----------------
__global__ __launch_bounds__(256) void ln_kernel(const float* __restrict__ x,
                                                 const float* __restrict__ g,
                                                 const float* __restrict__ b,
                                                 float* __restrict__ y,
                                                 unsigned* __restrict__ yu){
    __shared__ float row[DM];
    __shared__ float red[8];
    long long base = (long long)blockIdx.x * DM;
    float s = 0.f;
    for (int i = threadIdx.x; i < DM; i += 256) { float v = x[base+i]; row[i] = v; s += v; }
    s = blockSum(s, red);
    float mu = s * (1.f/DM);
    float vs = 0.f;
    for (int i = threadIdx.x; i < DM; i += 256) { float d = row[i]-mu; vs += d*d; }
    vs = blockSum(vs, red);
    float rstd = rsqrtf(vs * (1.f/DM) + 1e-5f);
    unsigned* ob = yu + base;
    for (int i2 = threadIdx.x; i2 < DM/2; i2 += 256){
        int i = i2*2;
        float v0 = (row[i  ]-mu)*rstd*g[i  ] + b[i  ];
        float v1 = (row[i+1]-mu)*rstd*g[i+1] + b[i+1];
        if (y){ y[base+i] = v0; y[base+i+1] = v1; }
        unsigned h,l; split2(v0,v1,h,l);
        *(uint2*)&ob[hlw(i2)] = make_uint2(h,l);
    }
}

// ---------------- fused gate + combine + LN2 ----------------
__global__ __launch_bounds__(256) void combine_ln_kernel(
    const float* __restrict__ x, const float* __restrict__ dense,
    const float* __restrict__ delta, const float* __restrict__ xn1,
    const float* __restrict__ wg,
    const float* __restrict__ g, const float* __restrict__ b,
    float* __restrict__ x1, float* __restrict__ y, unsigned* __restrict__ yu)
{
    __shared__ float row[DM];
    __shared__ float red[8];
    long long base = (long long)blockIdx.x * DM;
    // gate = softmax(xn1 @ w_gate)
    float p0=0.f, p1=0.f;
    for (int i = threadIdx.x; i < DM; i += 256){
        float xv = xn1[base+i];
        p0 += xv*wg[i*2+0];
        p1 += xv*wg[i*2+1];
    }
    p0 = blockSum(p0, red);
    p1 = blockSum(p1, red);
    float m = fmaxf(p0,p1);
    float e0 = expf(p0-m), e1 = expf(p1-m);
    float inv = 1.f/(e0+e1);
    float g0 = e0*inv, g1 = e1*inv;
    // combine -> x1
    float s = 0.f;
    for (int i = threadIdx.x; i < DM; i += 256){
        float v = x[base+i] + g0*dense[base+i] + g1*delta[base+i];
        row[i] = v; x1[base+i] = v; s += v;
    }
    s = blockSum(s, red);
    float mu = s * (1.f/DM);
    float vs = 0.f;
    for (int i = threadIdx.x; i < DM; i += 256){ float d2 = row[i]-mu; vs += d2*d2; }
    vs = blockSum(vs, red);
    float rstd = rsqrtf(vs * (1.f/DM) + 1e-5f);
    unsigned* ob = yu + base;
    for (int i2 = threadIdx.x; i2 < DM/2; i2 += 256){
        int i = i2*2;
        float v0 = (row[i  ]-mu)*rstd*g[i  ] + b[i  ];
        float v1 = (row[i+1]-mu)*rstd*g[i+1] + b[i+1];
        y[base+i] = v0; y[base+i+1] = v1;
        unsigned h,l; split2(v0,v1,h,l);
        *(uint2*)&ob[hlw(i2)] = make_uint2(h,l);
    }
}

// ---------------- fp16x3 GEMM on HL operands, LDS.128 fragments ----------------
template<int NTILES>
__global__ __launch_bounds__(256,2) void gemm_hh_kernel(
    const unsigned* __restrict__ A, const unsigned* __restrict__ B,
    float* __restrict__ Cf, unsigned* __restrict__ Ch,
    int M, int N, int K, int ldaw, int ldbw, int ldc,
    int innerN,
    long long sAo, long long sAi, long long sBo, long long sBi,
    long long sCo, long long sCi,
    const int* __restrict__ rowIdx, const int* __restrict__ tileExpert,
    long long expSB, float alpha, int actMode, int cT,
    MD md, int nMulti,
    const int* __restrict__ moeOff, const int* __restrict__ moeCnt)
{
    __shared__ unsigned As[3][128][16];
    __shared__ unsigned Bs[3][128][16];

    int z  = blockIdx.z;
    int zo = z / innerN, zi = z - zo*innerN;
    if (nMulti > 0){
        A = md.a[zi];
        Cf = md.f[zi]; Ch = md.h[zi];
        ldc = md.ldc[zi]; cT = md.cT[zi];
    }
    const int tm0 = blockIdx.y * 128;
    const int tn0 = blockIdx.x * (NTILES*16);
    // MoE pad-tile skip
    if (moeCnt){
        int e = tileExpert[blockIdx.y];
        if (tm0 >= moeOff[e] + moeCnt[e]) return;
    }
    A += zo*sAo + zi*sAi;
    long long boff = zo*sBo + zi*sBi;
    if (tileExpert) boff += (long long)tileExpert[blockIdx.y] * expSB;
    B += boff;
    long long coff = zo*sCo + zi*sCi;

    const int tid = threadIdx.x;
    const int lane = tid & 31;
    const int warp = tid >> 5;
    const int wm = (warp & 3) * 32;
    const int wn = (warp >> 2) * (NTILES*8);
    const int g = lane >> 2;
    const int q = lane & 3;

    const int lrow = tid >> 1;
    const int lsel = tid & 1;

    int grow = tm0 + lrow;
    bool aval = grow < M;
    int srcRow = aval ? (rowIdx ? (rowIdx[grow] & (NTOK-1)) : grow) : 0;
    const unsigned* Ap = A + (long long)srcRow * ldaw + lsel*8;
    bool bval = (tn0 + lrow) < N;
    int brow = bval ? (tn0 + lrow) : 0;
    const unsigned* Bp = B + (long long)brow * ldbw + lsel*8;

    unsigned base_off = (unsigned)((lrow*16 + lsel*8)*4);
    unsigned aS = (unsigned)__cvta_generic_to_shared(&As[0][0][0]) + base_off;
    unsigned bS = (unsigned)__cvta_generic_to_shared(&Bs[0][0][0]) + base_off;

    float acc[2][NTILES][4];
    #pragma unroll
    for (int mi=0;mi<2;mi++)
        #pragma unroll
        for (int ni=0;ni<NTILES;ni++)
            #pragma unroll
            for (int t=0;t<4;t++) acc[mi][ni][t]=0.f;

    const int nt = K >> 4;

    #define ISSUE(T) do{                                     \
        int _t = (T);                                         \
        if (_t < nt){                                         \
            unsigned _bo = (unsigned)((_t % 3) * 8192);       \
            int _kn = _t * 16;                                \
            cp16(aS + _bo,      Ap + _kn,     aval);          \
            cp16(aS + _bo + 16, Ap + _kn + 4, aval);          \
            cp16(bS + _bo,      Bp + _kn,     bval);          \
            cp16(bS + _bo + 16, Bp + _kn + 4, bval);          \
        }                                                     \
        asm volatile("cp.async.commit_group;");               \
    }while(0)

    ISSUE(0);
    ISSUE(1);

    int buf = 0;
    for (int k = 0; k < nt; k++){
        asm volatile("cp.async.wait_group 1;");
        __syncthreads();
        ISSUE(k+2);
        {
            uint4 a1[2], a2[2];
            #pragma unroll
            for (int mi = 0; mi < 2; mi++){
                int row = wm + mi*16 + g;
                a1[mi] = *(const uint4*)&As[buf][row  ][4*q];
                a2[mi] = *(const uint4*)&As[buf][row+8][4*q];
            }
            #pragma unroll
            for (int ni = 0; ni < NTILES; ni++){
                int col = wn + ni*8 + g;
                uint4 bb = *(const uint4*)&Bs[buf][col][4*q];
                #pragma unroll
                for (int mi = 0; mi < 2; mi++){
                    mma_f16(acc[mi][ni], a1[mi].x, a2[mi].x, a1[mi].z, a2[mi].z, bb.x, bb.z);
                    mma_f16(acc[mi][ni], a1[mi].x, a2[mi].x, a1[mi].z, a2[mi].z, bb.y, bb.w);
                    mma_f16(acc[mi][ni], a1[mi].y, a2[mi].y, a1[mi].w, a2[mi].w, bb.x, bb.z);
                }
            }
        }
        buf = (buf == 2) ? 0 : buf + 1;
    }
    #undef ISSUE

    float* CfP = Cf ? (Cf + coff) : (float*)0;
    unsigned* ChP = Ch ? (Ch + coff) : (unsigned*)0;
    #pragma unroll
    for (int mi = 0; mi < 2; mi++){
        #pragma unroll
        for (int rr = 0; rr < 2; rr++){
            int row = tm0 + wm + mi*16 + g + rr*8;
            if (row >= M) continue;
            #pragma unroll
            for (int ni = 0; ni < NTILES; ni++){
                int col = tn0 + wn + ni*8 + q*2;
                if (col >= N) continue;
                float v0 = acc[mi][ni][rr*2+0] * alpha;
                float v1 = acc[mi][ni][rr*2+1] * alpha;
                if (actMode == 1){
                    v0 = 0.5f * v0 * (1.f + erff(v0 * 0.70710678118654752f));
                    v1 = 0.5f * v1 * (1.f + erff(v1 * 0.70710678118654752f));
                }
                if (!cT){
                    if (CfP) *(float2*)&CfP[(long long)row*ldc + col] = make_float2(v0, v1);
                    if (ChP){
                        unsigned h,l; split2(v0,v1,h,l);
                        *(uint2*)&ChP[(long long)row*ldc + hlw(col>>1)] = make_uint2(h,l);
                    }
                } else {
                    int W = hlw(row >> 1);
                    int hs = row & 1;
                    {
                        __half h0 = __float2half_rn(v0);
                        unsigned* p = ChP + (long long)col*ldc;
                        ((__half*)(p + W    ))[hs] = h0;
                        ((__half*)(p + W + 1))[hs] = __float2half_rn(v0 - __half2float(h0));
                    }
                    if (col + 1 < N){
                        __half h1 = __float2half_rn(v1);
                        unsigned* p = ChP + (long long)(col+1)*ldc;
                        ((__half*)(p + W    ))[hs] = h1;
                        ((__half*)(p + W + 1))[hs] = __float2half_rn(v1 - __half2float(h1));
                    }
                }
            }
        }
    }
}

// ---------------- masked row softmax on HL rows (in place) ----------------
__global__ __launch_bounds__(256) void softmax_kernel(const int* __restrict__ mask,
                                                      unsigned* __restrict__ P){
    long long r = blockIdx.x;
    int qq = (int)(r & 1023);
    int b = (int)(r >> 14);
    const int* mr = mask + ((long long)b << 20) + ((long long)qq << 10);
    unsigned* row32 = P + (r << 10);
    __shared__ float buf[SEQ];
    __shared__ float red[8];
    float mx = -3.0e38f;
    for (int j = threadIdx.x; j < SEQ/2; j += 256){
        int lp = (j & ~7) | pinv(j & 7);
        uint2 u = *(uint2*)&row32[2*j];
        __half2 hv = *(__half2*)&u.x;
        __half2 lv = *(__half2*)&u.y;
        float v0 = __half2float(hv.x) + __half2float(lv.x);
        float v1 = __half2float(hv.y) + __half2float(lv.y);
        if (mr[2*lp  ] == 0) v0 = -1e9f;
        if (mr[2*lp+1] == 0) v1 = -1e9f;
        buf[2*lp  ] = v0;
        buf[2*lp+1] = v1;
        mx = fmaxf(mx, fmaxf(v0, v1));
    }
    mx = blockMax(mx, red);
    float sum = 0.f;
    for (int i = threadIdx.x; i < SEQ; i += 256){
        float e = expf(buf[i]-mx);
        buf[i] = e; sum += e;
    }
    sum = blockSum(sum, red);
    float inv = 1.f / sum;
    for (int j = threadIdx.x; j < SEQ/2; j += 256){
        int lp = (j & ~7) | pinv(j & 7);
        unsigned h,l; split2(buf[2*lp]*inv, buf[2*lp+1]*inv, h, l);
        *(uint2*)&row32[2*j] = make_uint2(h,l);
    }
}

// ---------------- delta branch (ksum folded into ctx1/ctx2) ----------------
__global__ __launch_bounds__(256) void ctx1_kernel(const float* __restrict__ kd,
                                                   const float* __restrict__ vd,
                                                   float* __restrict__ ctxp,
                                                   float* __restrict__ ksump){
    int z = blockIdx.x >> 2;
    int chunk = blockIdx.x & 3;
    int b = z >> 4, h = z & 15;
    const float* kbase = kd + ((long long)b*SEQ)*DM + h*DK;
    const float* vbase = vd + ((long long)b*SEQ)*DM + h*DK;
    __shared__ float ks[64][65];
    __shared__ float vs[64][65];
    int tid = threadIdx.x;
    int d0 = (tid >> 4) << 2;
    int e0 = (tid & 15) << 2;
    float acc[4][4];
    #pragma unroll
    for (int i=0;i<4;i++)
        #pragma unroll
        for (int j=0;j<4;j++) acc[i][j]=0.f;
    float ksacc = 0.f;

    for (int s0 = chunk*256; s0 < chunk*256+256; s0 += 64) {
        for (int t = tid; t < 64*16; t += 256) {
            int rr = t >> 4; int cc = (t & 15) << 2;
            float4 kv = *(const float4*)(kbase + (long long)(s0+rr)*DM + cc);
            float4 vv = *(const float4*)(vbase + (long long)(s0+rr)*DM + cc);
            ks[rr][cc+0]=kv.x; ks[rr][cc+1]=kv.y; ks[rr][cc+2]=kv.z; ks[rr][cc+3]=kv.w;
            vs[rr][cc+0]=vv.x; vs[rr][cc+1]=vv.y; vs[rr][cc+2]=vv.z; vs[rr][cc+3]=vv.w;
        }
        __syncthreads();
        if (tid < DK){
            #pragma unroll 8
            for (int rr=0; rr<64; rr++) ksacc += fmaxf(ks[rr][tid], 0.f);
        }
        #pragma unroll 4
        for (int ss=0; ss<64; ss++){
            float kr[4], vr[4];
            #pragma unroll
            for (int i=0;i<4;i++) kr[i]=ks[ss][d0+i];
            #pragma unroll
            for (int j=0;j<4;j++) vr[j]=vs[ss][e0+j];
            #pragma unroll
            for (int i=0;i<4;i++)
                #pragma unroll
                for (int j=0;j<4;j++) acc[i][j] += kr[i]*vr[j];
        }
        __syncthreads();
    }
    float* cbase = ctxp + ((long long)z*4 + chunk)*DK*DK;
    #pragma unroll
    for (int i=0;i<4;i++)
        #pragma unroll
        for (int j=0;j<4;j++)
            cbase[(d0+i)*DK + e0+j] = acc[i][j];
    if (tid < DK) ksump[((long long)z*4 + chunk)*DK + tid] = ksacc;
}

__global__ void ctx2_kernel(const float* __restrict__ ctxp, float* __restrict__ ctx,
                            const float* __restrict__ ksump, float* __restrict__ ksum){
    int z = blockIdx.x;
    const float* p = ctxp + (long long)z*4*DK*DK;
    float* o = ctx + (long long)z*DK*DK;
    for (int i = threadIdx.x; i < DK*DK; i += 256)
        o[i] = p[i] + p[DK*DK + i] + p[2*DK*DK + i] + p[3*DK*DK + i];
    if (threadIdx.x < DK){
        int d = threadIdx.x;
        float s = 0.f;
        #pragma unroll
        for (int c=0;c<4;c++) s += ksump[((long long)z*4 + c)*DK + d];
        ksum[z*DK + d] = s;
    }
}

__global__ __launch_bounds__(256) void delta_kernel(const float* __restrict__ qd,
                                                    const float* __restrict__ ctx,
                                                    const float* __restrict__ ksum,
                                                    unsigned* __restrict__ du){
    int z = blockIdx.x >> 2;
    int sc = blockIdx.x & 3;
    int b = z >> 4, h = z & 15;
    __shared__ float cs[DK*DK];
    __shared__ float kss[DK];
    for (int i = threadIdx.x; i < DK*DK; i += 256) cs[i] = ctx[(long long)z*DK*DK + i];
    if (threadIdx.x < DK) kss[threadIdx.x] = ksum[z*DK + threadIdx.x];
    __syncthreads();
    int s = sc*256 + threadIdx.x;
    const float* qrow = qd + ((long long)(b*SEQ + s))*DM + h*DK;
    float q[DK];
    #pragma unroll
    for (int d=0; d<DK; d+=4){
        float4 v = *(const float4*)(qrow + d);
        q[d+0]=fmaxf(v.x,0.f); q[d+1]=fmaxf(v.y,0.f);
        q[d+2]=fmaxf(v.z,0.f); q[d+3]=fmaxf(v.w,0.f);
    }
    float zv = 1e-6f;
    #pragma unroll
    for (int d=0; d<DK; d++) zv += q[d]*kss[d];
    float invz = 1.f / zv;
    unsigned* ob = du + ((long long)(b*SEQ + s))*DM + h*DK;
    for (int e=0; e<DK; e+=2){
        float a0 = 0.f, a1 = 0.f;
        #pragma unroll
        for (int d=0; d<DK; d++){
            a0 += q[d]*cs[d*DK + e];
            a1 += q[d]*cs[d*DK + e+1];
        }
        unsigned hh,ll; split2(a0*invz, a1*invz, hh, ll);
        *(uint2*)&ob[hlw(e>>1)] = make_uint2(hh,ll);
    }
}

// ---------------- router / moe plumbing / final ----------------
__global__ __launch_bounds__(256) void router_kernel(const float* __restrict__ xn2,
                                                     const float* __restrict__ wr,
                                                     int* __restrict__ topk_idx,
                                                     float* __restrict__ topk_w,
                                                     int* __restrict__ counts){
    int t = blockIdx.x;
    float p[NE];
    #pragma unroll
    for (int e=0;e<NE;e++) p[e]=0.f;
    for (int k = threadIdx.x; k < DM; k += 256){
        float xv = xn2[(long long)t*DM + k];
        #pragma unroll
        for (int e=0;e<NE;e++) p[e] += xv*wr[k*NE + e];
    }
    __shared__ float part[NE][8];
    int w = threadIdx.x >> 5;
    #pragma unroll
    for (int e=0;e<NE;e++){
        float v = warpSum(p[e]);
        if ((threadIdx.x & 31)==0) part[e][w] = v;
    }
    __syncthreads();
    if (threadIdx.x == 0){
        float lg[NE];
        for (int e=0;e<NE;e++){
            float s=0.f;
            for (int ww=0; ww<8; ww++) s += part[e][ww];
            lg[e]=s;
        }
        int i0=0; float v0=lg[0];
        for (int e=1;e<NE;e++) if (lg[e]>v0){v0=lg[e];i0=e;}
        int i1=-1; float v1=-3.0e38f;
        for (int e=0;e<NE;e++) if (e!=i0 && lg[e]>v1){v1=lg[e];i1=e;}
        float e1 = expf(v1-v0);
        float inv = 1.f/(1.f+e1);
        topk_idx[t*2+0]=i0; topk_idx[t*2+1]=i1;
        topk_w[t*2+0]=inv;  topk_w[t*2+1]=e1*inv;
        atomicAdd(&counts[i0],1); atomicAdd(&counts[i1],1);
    }
}

__global__ void prep_kernel(int* counts, int* cursor, int* tok){
    int i = blockIdx.x*256 + threadIdx.x;
    if (i < NE){ counts[i]=0; cursor[i]=0; }
    if (i < PAIR_CAP) tok[i]=0;
}

__global__ void scan_kernel(const int* counts, int* off, int* tile_e){
    if (threadIdx.x==0 && blockIdx.x==0){
        int o = 0;
        off[0]=0;
        for (int e=0;e<NE;e++){ o += (counts[e]+127)&~127; off[e+1]=o; }
        for (int t=0;t<NTILE72;t++){
            int row = t*128;
            int ee = NE-1;
            for (int i=0;i<NE;i++){ if (row < off[i+1]) { ee=i; break; } }
            tile_e[t]=ee;
        }
    }
}

__global__ void place_kernel(const int* __restrict__ topk_idx,
                             const int* __restrict__ off,
                             int* cursor, int* tok, int* pair_pos){
    int t = blockIdx.x*256 + threadIdx.x;
    if (t >= NTOK) return;
    for (int k=0;k<2;k++){
        int e = topk_idx[t*2+k];
        int pos = atomicAdd(&cursor[e],1);
        int r = off[e] + pos;
        tok[r] = t;
        pair_pos[t*2+k] = r;
    }
}

__global__ void final_kernel(const float* __restrict__ x1,
                             const float* __restrict__ y2,
                             const float* __restrict__ topk_w,
                             const int* __restrict__ pair_pos,
                             float* __restrict__ out){
    long long i = (long long)blockIdx.x*256 + threadIdx.x;
    int t = (int)(i >> 10);
    int c = (int)(i & 1023);
    int p0 = pair_pos[t*2+0], p1 = pair_pos[t*2+1];
    out[i] = x1[i] + topk_w[t*2+0]*y2[(long long)p0*DM + c]
                   + topk_w[t*2+1]*y2[(long long)p1*DM + c];
}

// ---------------- host side ----------------
static void gemm(const unsigned* A, const unsigned* B,
                 float* Cf, unsigned* Ch,
                 int M, int N, int K, int ldaw, int ldbw, int ldc,
                 int batch, int innerN,
                 long long sAo, long long sAi, long long sBo, long long sBi,
                 long long sCo, long long sCi,
                 const int* rowIdx, const int* tileE, long long expSB,
                 float alpha, int act, int cT,
                 int bn64, const MD& md, int nMulti,
                 const int* moeOff, const int* moeCnt){
    if (bn64){
        dim3 grid((N+63)/64, (M+127)/128, batch);
        gemm_hh_kernel<4><<<grid, 256>>>(A,B,Cf,Ch,M,N,K,ldaw,ldbw,ldc,innerN,
                                         sAo,sAi,sBo,sBi,sCo,sCi,
                                         rowIdx,tileE,expSB,alpha,act,cT,md,nMulti,
                                         moeOff,moeCnt);
    } else {
        dim3 grid((N+127)/128, (M+127)/128, batch);
        gemm_hh_kernel<8><<<grid, 256>>>(A,B,Cf,Ch,M,N,K,ldaw,ldbw,ldc,innerN,
                                         sAo,sAi,sBo,sBi,sCo,sCi,
                                         rowIdx,tileE,expSB,alpha,act,cT,md,nMulti,
                                         moeOff,moeCnt);
    }
}

extern "C" void kernel_launch(void* const* d_in, const int* in_sizes, int n_in,
                              void* d_out, int out_size){
    const float* x        = (const float*)d_in[0];
    const int*   mask     = (const int*)  d_in[1];
    const float* ln1_g    = (const float*)d_in[2];
    const float* ln1_b    = (const float*)d_in[3];
    const float* wq       = (const float*)d_in[4];
    const float* wk       = (const float*)d_in[5];
    const float* wv       = (const float*)d_in[6];
    const float* wo       = (const float*)d_in[7];
    const float* wqd      = (const float*)d_in[8];
    const float* wkd      = (const float*)d_in[9];
    const float* wvd      = (const float*)d_in[10];
    const float* wod      = (const float*)d_in[11];
    const float* w_gate   = (const float*)d_in[12];
    const float* ln2_g    = (const float*)d_in[13];
    const float* ln2_b    = (const float*)d_in[14];
    const float* w_router = (const float*)d_in[15];
    const float* e_w1     = (const float*)d_in[16];
    const float* e_w2     = (const float*)d_in[17];
    float* out = (float*)d_out;

    float *xn1,*qd,*kd,*vd,*dense_o,*delta_o,*x1,*xn2,*ctx,*ctxp,*ksum,*ksump,*y2,*topk_w;
    int *topk_idx,*counts,*cursor,*off,*tile_e,*tok,*pair_pos;
    unsigned *xn1u,*qu,*ku,*vTu,*pu,*actu,*dlu,*xn2u,*h1u,*wu,*e1u,*e2u;

    cudaGetSymbolAddress((void**)&xn1,     g_xn1);
    cudaGetSymbolAddress((void**)&qd,      g_qd);
    cudaGetSymbolAddress((void**)&kd,      g_kd);
    cudaGetSymbolAddress((void**)&vd,      g_vd);
    cudaGetSymbolAddress((void**)&dense_o, g_dense_o);
    cudaGetSymbolAddress((void**)&delta_o, g_delta_o);
    cudaGetSymbolAddress((void**)&x1,      g_x1);
    cudaGetSymbolAddress((void**)&xn2,     g_xn2);
    cudaGetSymbolAddress((void**)&ctx,     g_ctx);
    cudaGetSymbolAddress((void**)&ctxp,    g_ctxp);
    cudaGetSymbolAddress((void**)&ksum,    g_ksum);
    cudaGetSymbolAddress((void**)&ksump,   g_ksump);
    cudaGetSymbolAddress((void**)&y2,      g_y2);
    cudaGetSymbolAddress((void**)&topk_w,  g_topk_w);
    cudaGetSymbolAddress((void**)&topk_idx,g_topk_idx);
    cudaGetSymbolAddress((void**)&counts,  g_counts);
    cudaGetSymbolAddress((void**)&cursor,  g_cursor);
    cudaGetSymbolAddress((void**)&off,     g_off);
    cudaGetSymbolAddress((void**)&tile_e,  g_tile_e);
    cudaGetSymbolAddress((void**)&tok,     g_tok);
    cudaGetSymbolAddress((void**)&pair_pos,g_pair_pos);
    cudaGetSymbolAddress((void**)&xn1u,    g_xn1u);
    cudaGetSymbolAddress((void**)&qu,      g_qu);
    cudaGetSymbolAddress((void**)&ku,      g_ku);
    cudaGetSymbolAddress((void**)&vTu,     g_vTu);
    cudaGetSymbolAddress((void**)&pu,      g_pu);
    cudaGetSymbolAddress((void**)&actu,    g_actu);
    cudaGetSymbolAddress((void**)&dlu,     g_dlu);
    cudaGetSymbolAddress((void**)&xn2u,    g_xn2u);
    cudaGetSymbolAddress((void**)&h1u,     g_h1u);
    cudaGetSymbolAddress((void**)&wu,      g_wu);
    cudaGetSymbolAddress((void**)&e1u,     g_e1u);
    cudaGetSymbolAddress((void**)&e2u,     g_e2u);

    const long long TOKD = (long long)SEQ*DM;
    MD md0; memset(&md0, 0, sizeof(md0));

    // 0: LN1
    ln_kernel<<<NTOK,256>>>(x, ln1_g, ln1_b, xn1, xn1u);
    // 1: dense weight splits — wq wk wv wqd wkd wvd | wo wod
    WP8 wp;
    wp.p[0]=wq; wp.p[1]=wk; wp.p[2]=wv; wp.p[3]=wqd;
    wp.p[4]=wkd; wp.p[5]=wvd; wp.p[6]=wo; wp.p[7]=wod;
    wsplit8_kernel<<<dim3(32,32,8), dim3(32,8)>>>(wp, wu);
    // 2: expert w1 split
    wsplit_kernel<<<dim3(DFF/32, DM/32, NE), dim3(32,8)>>>(e_w1, e1u, DM, DFF);

    // 3: all 6 projections, one batched launch  <-- ncu target
    {
        MD md; memset(&md, 0, sizeof(md));
        for (int z=0; z<6; z++){ md.a[z]=xn1u; md.ldc[z]=DM; md.cT[z]=0; }
        md.h[0]=qu;
        md.h[1]=ku;
        md.h[2]=vTu; md.ldc[2]=NTOK; md.cT[2]=1;
        md.f[3]=qd;
        md.f[4]=kd;
        md.f[5]=vd;
        gemm(xn1u, wu, 0,0,
             NTOK,DM,DM, DM,DM,DM, 6,6,
             0,0, 0,WSZ, 0,0,
             0,0,0, 1.f,0,0, 0, md, 6, 0,0);
    }

    // scores = Q @ K^T / 8 -> HL
    gemm(qu, ku, 0,pu, SEQ,SEQ,DK, DM,DM,SEQ,
         NB*NH, NH,
         TOKD, DK,  TOKD, DK,  (long long)NH*SEQ*SEQ, (long long)SEQ*SEQ,
         0,0,0, 0.125f,0,0, 0, md0, 0, 0,0);

    // masked softmax in place
    softmax_kernel<<<NB*NH*SEQ, 256>>>(mask, pu);

    // attnctx = P @ V (BN=64) -> HL natural
    gemm(pu, vTu, 0,actu, SEQ,DK,SEQ, SEQ,NTOK,DM,
         NB*NH, NH,
         (long long)NH*SEQ*SEQ, (long long)SEQ*SEQ,  SEQ, (long long)DK*NTOK,
         TOKD, DK,
         0,0,0, 1.f,0,0, 1, md0, 0, 0,0);

    // delta branch (ksum fused)
    ctx1_kernel<<<NB*NH*4, 256>>>(kd, vd, ctxp, ksump);
    ctx2_kernel<<<NB*NH, 256>>>(ctxp, ctx, ksump, ksum);
    delta_kernel<<<NB*NH*4, 256>>>(qd, ctx, ksum, dlu);

    // output projections, batched 2
    {
        MD md; memset(&md, 0, sizeof(md));
        md.a[0]=actu; md.f[0]=dense_o; md.ldc[0]=DM; md.cT[0]=0;
        md.a[1]=dlu;  md.f[1]=delta_o; md.ldc[1]=DM; md.cT[1]=0;
        gemm(actu, wu+6LL*WSZ, 0,0,
             NTOK,DM,DM, DM,DM,DM, 2,2,
             0,0, 0,WSZ, 0,0,
             0,0,0, 1.f,0,0, 0, md, 2, 0,0);
    }

    // fused gate + combine + LN2
    combine_ln_kernel<<<NTOK,256>>>(x, dense_o, delta_o, xn1, w_gate,
                                    ln2_g, ln2_b, x1, xn2, xn2u);

    // routing
    prep_kernel<<<(PAIR_CAP+255)/256, 256>>>(counts, cursor, tok);
    router_kernel<<<NTOK, 256>>>(xn2, w_router, topk_idx, topk_w, counts);
    scan_kernel<<<1,32>>>(counts, off, tile_e);
    place_kernel<<<(NTOK+255)/256, 256>>>(topk_idx, off, cursor, tok, pair_pos);

    // expert w2 split
    wsplit_kernel<<<dim3(DM/32, DFF/32, NE), dim3(32,8)>>>(e_w2, e2u, DFF, DM);

    // expert GEMM1 (gathered, gelu) -> h1 HL ; pad tiles skipped
    gemm(xn2u, e1u, 0,h1u, PAIR_CAP,DFF,DM, DM,DM,DFF,
         1,1, 0,0,0,0,0,0,
         tok, tile_e, (long long)DM*DFF, 1.f,1,0, 0, md0, 0, off, counts);

    // expert GEMM2 -> y2 fp32 ; pad tiles skipped
    gemm(h1u, e2u, y2,0, PAIR_CAP,DM,DFF, DFF,DFF,DM,
         1,1, 0,0,0,0,0,0,
         0, tile_e, (long long)DFF*DM, 1.f,0,0, 0, md0, 0, off, counts);

    // final combine
    final_kernel<<<NTOK*DM/256, 256>>>(x1, y2, topk_w, pair_pos, out);
}